// round 1
// baseline (speedup 1.0000x reference)
#include <cuda_runtime.h>
#include <math.h>

// Problem constants
#define BB 2
#define TT 2048
#define EE 1024
#define HH 16
#define DH 64
#define FF 4096
#define MM (BB*TT)   // 4096 rows

// Scratch (device globals: no allocation allowed)
__device__ float g_ln [MM*EE];
__device__ float g_qkv[MM*3*EE];
__device__ float g_att[MM*EE];
__device__ float g_x2 [MM*EE];
__device__ float g_act[(size_t)MM*FF];

// ---------------------------------------------------------------------------
// LayerNorm: one block per row of 1024, 256 threads, float4 per thread
// ---------------------------------------------------------------------------
__global__ void ln_kernel(const float* __restrict__ x,
                          const float* __restrict__ g,
                          const float* __restrict__ b,
                          float* __restrict__ out) {
    int row = blockIdx.x;
    int tid = threadIdx.x;
    const float4* xr = reinterpret_cast<const float4*>(x + (size_t)row * EE);
    float4 v = xr[tid];
    float s  = v.x + v.y + v.z + v.w;
    float sq = v.x*v.x + v.y*v.y + v.z*v.z + v.w*v.w;
    #pragma unroll
    for (int o = 16; o > 0; o >>= 1) {
        s  += __shfl_xor_sync(0xffffffff, s,  o);
        sq += __shfl_xor_sync(0xffffffff, sq, o);
    }
    __shared__ float rs[8], rq[8], mu_s, rstd_s;
    int warp = tid >> 5, lane = tid & 31;
    if (lane == 0) { rs[warp] = s; rq[warp] = sq; }
    __syncthreads();
    if (tid == 0) {
        float ts = 0.f, tq = 0.f;
        #pragma unroll
        for (int i = 0; i < 8; i++) { ts += rs[i]; tq += rq[i]; }
        float mu  = ts * (1.0f / EE);
        float var = tq * (1.0f / EE) - mu * mu;
        mu_s = mu;
        rstd_s = rsqrtf(var + 1e-5f);
    }
    __syncthreads();
    float mu = mu_s, rstd = rstd_s;
    float4 gv = reinterpret_cast<const float4*>(g)[tid];
    float4 bv = reinterpret_cast<const float4*>(b)[tid];
    float4 o;
    o.x = (v.x - mu) * rstd * gv.x + bv.x;
    o.y = (v.y - mu) * rstd * gv.y + bv.y;
    o.z = (v.z - mu) * rstd * gv.z + bv.z;
    o.w = (v.w - mu) * rstd * gv.w + bv.w;
    reinterpret_cast<float4*>(out + (size_t)row * EE)[tid] = o;
}

// ---------------------------------------------------------------------------
// GELU (tanh approximation, matching reference)
// ---------------------------------------------------------------------------
__device__ __forceinline__ float gelu_f(float x) {
    const float c = 0.7978845608028654f;
    float x3 = x * x * x;
    return 0.5f * x * (1.0f + tanhf(c * (x + 0.044715f * x3)));
}

// ---------------------------------------------------------------------------
// SGEMM: C[M,N] = A[M,K] @ W[K,N] + bias (+ optional GELU, + optional residual)
// 128x128 block tile, BK=8, 8x8 microtile, 256 threads, split 64/64 layout
// for conflict-free float4 smem reads.
// ---------------------------------------------------------------------------
template<bool GELU, bool RES>
__global__ void __launch_bounds__(256)
sgemm_kernel(const float* __restrict__ A, const float* __restrict__ W,
             const float* __restrict__ bias, const float* __restrict__ res,
             float* __restrict__ C, int M, int N, int K) {
    __shared__ float As[8][132];   // padded: conflict-free transposed stores
    __shared__ float Bs[8][128];

    int tid = threadIdx.x;
    int bm = blockIdx.y, bn = blockIdx.x;
    const float* Ab = A + (size_t)bm * 128 * K;
    const float* Wb = W + (size_t)bn * 128;

    int aRow = tid >> 1;            // 0..127
    int aCol = (tid & 1) << 2;      // 0 or 4
    int bRow = tid >> 5;            // 0..7
    int bCol = (tid & 31) << 2;     // 0..124

    int tx = tid & 15, ty = tid >> 4;

    float acc[8][8];
    #pragma unroll
    for (int i = 0; i < 8; i++)
        #pragma unroll
        for (int j = 0; j < 8; j++) acc[i][j] = 0.f;

    for (int k0 = 0; k0 < K; k0 += 8) {
        float4 a4 = *reinterpret_cast<const float4*>(Ab + (size_t)aRow * K + k0 + aCol);
        As[aCol + 0][aRow] = a4.x;
        As[aCol + 1][aRow] = a4.y;
        As[aCol + 2][aRow] = a4.z;
        As[aCol + 3][aRow] = a4.w;
        float4 b4 = *reinterpret_cast<const float4*>(Wb + (size_t)(k0 + bRow) * N + bCol);
        *reinterpret_cast<float4*>(&Bs[bRow][bCol]) = b4;
        __syncthreads();

        #pragma unroll
        for (int k = 0; k < 8; k++) {
            float ra[8], rb[8];
            *reinterpret_cast<float4*>(&ra[0]) = *reinterpret_cast<float4*>(&As[k][ty * 4]);
            *reinterpret_cast<float4*>(&ra[4]) = *reinterpret_cast<float4*>(&As[k][64 + ty * 4]);
            *reinterpret_cast<float4*>(&rb[0]) = *reinterpret_cast<float4*>(&Bs[k][tx * 4]);
            *reinterpret_cast<float4*>(&rb[4]) = *reinterpret_cast<float4*>(&Bs[k][64 + tx * 4]);
            #pragma unroll
            for (int i = 0; i < 8; i++)
                #pragma unroll
                for (int j = 0; j < 8; j++)
                    acc[i][j] = fmaf(ra[i], rb[j], acc[i][j]);
        }
        __syncthreads();
    }

    int rowBase = bm * 128;
    int colBase = bn * 128;
    #pragma unroll
    for (int mi = 0; mi < 2; mi++) {
        #pragma unroll
        for (int ii = 0; ii < 4; ii++) {
            int row = rowBase + mi * 64 + ty * 4 + ii;
            #pragma unroll
            for (int nj = 0; nj < 2; nj++) {
                int col = colBase + nj * 64 + tx * 4;
                float4 bb = *reinterpret_cast<const float4*>(bias + col);
                float4 v;
                v.x = acc[mi * 4 + ii][nj * 4 + 0] + bb.x;
                v.y = acc[mi * 4 + ii][nj * 4 + 1] + bb.y;
                v.z = acc[mi * 4 + ii][nj * 4 + 2] + bb.z;
                v.w = acc[mi * 4 + ii][nj * 4 + 3] + bb.w;
                if (GELU) {
                    v.x = gelu_f(v.x); v.y = gelu_f(v.y);
                    v.z = gelu_f(v.z); v.w = gelu_f(v.w);
                }
                if (RES) {
                    float4 rr = *reinterpret_cast<const float4*>(res + (size_t)row * N + col);
                    v.x += rr.x; v.y += rr.y; v.z += rr.z; v.w += rr.w;
                }
                *reinterpret_cast<float4*>(C + (size_t)row * N + col) = v;
            }
        }
    }
}

// ---------------------------------------------------------------------------
// Flash-style causal attention, fp32.
// Grid (T/32, H, B), 256 threads = 8 warps. Each warp owns 4 query rows.
// K tile of 64 keys held transposed in smem (conflict-free score reads);
// V tile natural layout. Online softmax per row; output dims split 2/lane.
// ---------------------------------------------------------------------------
#define QTILE 32
#define KTILE 64

__global__ void __launch_bounds__(256)
attn_kernel(const float* __restrict__ qkv, float* __restrict__ out) {
    int qt0 = blockIdx.x * QTILE;
    int h   = blockIdx.y;
    int b   = blockIdx.z;
    int tid = threadIdx.x, lane = tid & 31, warp = tid >> 5;

    __shared__ float Qs[QTILE][DH];        // 8 KB
    __shared__ float Kt[DH][KTILE + 1];    // transposed, padded: 16.25 KB
    __shared__ float Vs[KTILE][DH];        // 16 KB

    const float* base = qkv + (size_t)b * TT * (3 * EE);

    // Load Q tile (rows qt0..qt0+31, dims h*64..h*64+63)
    #pragma unroll
    for (int it = 0; it < 2; it++) {
        int i = tid + it * 256;            // 0..511 float4s
        int r  = i >> 4;
        int d4 = (i & 15) << 2;
        *reinterpret_cast<float4*>(&Qs[r][d4]) =
            *reinterpret_cast<const float4*>(base + (size_t)(qt0 + r) * 3072 + h * 64 + d4);
    }

    float m[4], l[4], o0[4], o1[4];
    #pragma unroll
    for (int ri = 0; ri < 4; ri++) { m[ri] = -1e30f; l[ri] = 0.f; o0[ri] = 0.f; o1[ri] = 0.f; }

    int rmax = qt0 + QTILE - 1;
    for (int kt0 = 0; kt0 <= rmax; kt0 += KTILE) {
        __syncthreads();
        // Load K (transposed) and V tiles
        #pragma unroll
        for (int it = 0; it < 4; it++) {
            int i = tid + it * 256;        // 0..1023 float4s
            int kk = i >> 4;
            int d4 = (i & 15) << 2;
            const float* kp = base + (size_t)(kt0 + kk) * 3072 + EE + h * 64 + d4;
            float4 k4 = *reinterpret_cast<const float4*>(kp);
            Kt[d4 + 0][kk] = k4.x;
            Kt[d4 + 1][kk] = k4.y;
            Kt[d4 + 2][kk] = k4.z;
            Kt[d4 + 3][kk] = k4.w;
            float4 v4 = *reinterpret_cast<const float4*>(kp + EE);
            *reinterpret_cast<float4*>(&Vs[kk][d4]) = v4;
        }
        __syncthreads();

        #pragma unroll
        for (int ri = 0; ri < 4; ri++) {
            int r = warp * 4 + ri;
            int qrow = qt0 + r;
            float s0 = 0.f, s1 = 0.f;
            #pragma unroll
            for (int d = 0; d < DH; d++) {
                float qd = Qs[r][d];
                s0 = fmaf(qd, Kt[d][lane],      s0);
                s1 = fmaf(qd, Kt[d][lane + 32], s1);
            }
            s0 *= 0.125f; s1 *= 0.125f;
            if (kt0 + lane      > qrow) s0 = -1e30f;
            if (kt0 + lane + 32 > qrow) s1 = -1e30f;

            float tm = fmaxf(s0, s1);
            #pragma unroll
            for (int o = 16; o > 0; o >>= 1)
                tm = fmaxf(tm, __shfl_xor_sync(0xffffffff, tm, o));
            float mn = fmaxf(m[ri], tm);

            float p0 = __expf(s0 - mn);
            float p1 = __expf(s1 - mn);
            float ps = p0 + p1;
            #pragma unroll
            for (int o = 16; o > 0; o >>= 1)
                ps += __shfl_xor_sync(0xffffffff, ps, o);

            float scale = __expf(m[ri] - mn);
            l[ri] = l[ri] * scale + ps;
            m[ri] = mn;
            o0[ri] *= scale;
            o1[ri] *= scale;

            #pragma unroll
            for (int j = 0; j < 32; j++) {
                float pj0 = __shfl_sync(0xffffffff, p0, j);
                float pj1 = __shfl_sync(0xffffffff, p1, j);
                o0[ri] = fmaf(pj0, Vs[j][lane],           o0[ri]);
                o0[ri] = fmaf(pj1, Vs[j + 32][lane],      o0[ri]);
                o1[ri] = fmaf(pj0, Vs[j][lane + 32],      o1[ri]);
                o1[ri] = fmaf(pj1, Vs[j + 32][lane + 32], o1[ri]);
            }
        }
    }

    #pragma unroll
    for (int ri = 0; ri < 4; ri++) {
        int qrow = qt0 + warp * 4 + ri;
        float inv = 1.0f / l[ri];
        size_t o = ((size_t)b * TT + qrow) * EE + h * 64 + lane;
        out[o]      = o0[ri] * inv;
        out[o + 32] = o1[ri] * inv;
    }
}

// ---------------------------------------------------------------------------
// Launch
// ---------------------------------------------------------------------------
extern "C" void kernel_launch(void* const* d_in, const int* in_sizes, int n_in,
                              void* d_out, int out_size) {
    const float* x        = (const float*)d_in[0];
    const float* c_attn_w = (const float*)d_in[1];
    const float* c_attn_b = (const float*)d_in[2];
    const float* c_proj_w = (const float*)d_in[3];
    const float* c_proj_b = (const float*)d_in[4];
    const float* mlp_w1   = (const float*)d_in[5];
    const float* mlp_b1   = (const float*)d_in[6];
    const float* mlp_w2   = (const float*)d_in[7];
    const float* mlp_b2   = (const float*)d_in[8];
    const float* ln1_g    = (const float*)d_in[9];
    const float* ln1_b    = (const float*)d_in[10];
    const float* ln2_g    = (const float*)d_in[11];
    const float* ln2_b    = (const float*)d_in[12];
    float* out = (float*)d_out;

    float *ln, *qkv, *att, *x2, *act;
    cudaGetSymbolAddress((void**)&ln,  g_ln);
    cudaGetSymbolAddress((void**)&qkv, g_qkv);
    cudaGetSymbolAddress((void**)&att, g_att);
    cudaGetSymbolAddress((void**)&x2,  g_x2);
    cudaGetSymbolAddress((void**)&act, g_act);

    // 1. LN1
    ln_kernel<<<MM, 256>>>(x, ln1_g, ln1_b, ln);
    // 2. QKV = ln @ c_attn_w + b           [4096, 3072]
    sgemm_kernel<false, false><<<dim3(3 * EE / 128, MM / 128), 256>>>(
        ln, c_attn_w, c_attn_b, nullptr, qkv, MM, 3 * EE, EE);
    // 3. Attention
    attn_kernel<<<dim3(TT / QTILE, HH, BB), 256>>>(qkv, att);
    // 4. x2 = x + att @ c_proj_w + b       [4096, 1024]
    sgemm_kernel<false, true><<<dim3(EE / 128, MM / 128), 256>>>(
        att, c_proj_w, c_proj_b, x, x2, MM, EE, EE);
    // 5. LN2
    ln_kernel<<<MM, 256>>>(x2, ln2_g, ln2_b, ln);
    // 6. act = gelu(h @ mlp_w1 + b1)       [4096, 4096]
    sgemm_kernel<true, false><<<dim3(FF / 128, MM / 128), 256>>>(
        ln, mlp_w1, mlp_b1, nullptr, act, MM, FF, EE);
    // 7. out = x2 + act @ mlp_w2 + b2      [4096, 1024]
    sgemm_kernel<false, true><<<dim3(EE / 128, MM / 128), 256>>>(
        act, mlp_w2, mlp_b2, x2, out, MM, EE, FF);
}

// round 2
// speedup vs baseline: 1.8327x; 1.8327x over previous
#include <cuda_runtime.h>
#include <math.h>
#include <stdint.h>

// Problem constants
#define BB 2
#define TT 2048
#define EE 1024
#define HH 16
#define DH 64
#define FF 4096
#define MM (BB*TT)   // 4096 rows

// Scratch (device globals: no allocation allowed)
__device__ float g_ln [MM*EE];
__device__ float g_qkv[MM*3*EE];
__device__ float g_att[MM*EE];
__device__ float g_x2 [MM*EE];
__device__ float g_act[(size_t)MM*FF];
__device__ float g_w  [12*1024*1024];   // tf32-rounded weights

#define W_ATTN_OFF 0
#define W_PROJ_OFF (3*EE*EE)            // 3145728
#define W_MLP1_OFF (W_PROJ_OFF + EE*EE) // 4194304
#define W_MLP2_OFF (W_MLP1_OFF + EE*FF) // 8388608

// ---------------------------------------------------------------------------
// tf32 round helper (round-to-nearest into tf32 bit pattern, kept in fp32 reg)
// ---------------------------------------------------------------------------
__device__ __forceinline__ float rtf32(float x) {
    uint32_t u;
    asm("cvt.rna.tf32.f32 %0, %1;" : "=r"(u) : "f"(x));
    return __uint_as_float(u);
}

__device__ __forceinline__ void cp16(uint32_t dst, const void* src) {
    asm volatile("cp.async.cg.shared.global [%0], [%1], 16;\n" :: "r"(dst), "l"(src));
}

// ---------------------------------------------------------------------------
// Weight pre-rounding to tf32 (grid-stride, float4)
// ---------------------------------------------------------------------------
__global__ void round_w_kernel(const float* __restrict__ in, float* __restrict__ out, int n4) {
    int i = blockIdx.x * blockDim.x + threadIdx.x;
    for (; i < n4; i += gridDim.x * blockDim.x) {
        float4 v = reinterpret_cast<const float4*>(in)[i];
        v.x = rtf32(v.x); v.y = rtf32(v.y); v.z = rtf32(v.z); v.w = rtf32(v.w);
        reinterpret_cast<float4*>(out)[i] = v;
    }
}

// ---------------------------------------------------------------------------
// LayerNorm: one block per row of 1024, 256 threads; output tf32-rounded
// (LN output is consumed only as GEMM A operand)
// ---------------------------------------------------------------------------
__global__ void ln_kernel(const float* __restrict__ x,
                          const float* __restrict__ g,
                          const float* __restrict__ b,
                          float* __restrict__ out) {
    int row = blockIdx.x;
    int tid = threadIdx.x;
    const float4* xr = reinterpret_cast<const float4*>(x + (size_t)row * EE);
    float4 v = xr[tid];
    float s  = v.x + v.y + v.z + v.w;
    float sq = v.x*v.x + v.y*v.y + v.z*v.z + v.w*v.w;
    #pragma unroll
    for (int o = 16; o > 0; o >>= 1) {
        s  += __shfl_xor_sync(0xffffffff, s,  o);
        sq += __shfl_xor_sync(0xffffffff, sq, o);
    }
    __shared__ float rs[8], rq[8], mu_s, rstd_s;
    int warp = tid >> 5, lane = tid & 31;
    if (lane == 0) { rs[warp] = s; rq[warp] = sq; }
    __syncthreads();
    if (tid == 0) {
        float ts = 0.f, tq = 0.f;
        #pragma unroll
        for (int i = 0; i < 8; i++) { ts += rs[i]; tq += rq[i]; }
        float mu  = ts * (1.0f / EE);
        float var = tq * (1.0f / EE) - mu * mu;
        mu_s = mu;
        rstd_s = rsqrtf(var + 1e-5f);
    }
    __syncthreads();
    float mu = mu_s, rstd = rstd_s;
    float4 gv = reinterpret_cast<const float4*>(g)[tid];
    float4 bv = reinterpret_cast<const float4*>(b)[tid];
    float4 o;
    o.x = rtf32((v.x - mu) * rstd * gv.x + bv.x);
    o.y = rtf32((v.y - mu) * rstd * gv.y + bv.y);
    o.z = rtf32((v.z - mu) * rstd * gv.z + bv.z);
    o.w = rtf32((v.w - mu) * rstd * gv.w + bv.w);
    reinterpret_cast<float4*>(out + (size_t)row * EE)[tid] = o;
}

// ---------------------------------------------------------------------------
// GELU (tanh approximation, matching reference)
// ---------------------------------------------------------------------------
__device__ __forceinline__ float gelu_f(float x) {
    const float c = 0.7978845608028654f;
    float x3 = x * x * x;
    return 0.5f * x * (1.0f + tanhf(c * (x + 0.044715f * x3)));
}

// ---------------------------------------------------------------------------
// tf32 tensor-core GEMM: C[M,N] = A[M,K] @ W[K,N] + bias
//   (+GELU) (+residual) (+tf32-round output)
// 128x128x32 CTA tile, 8 warps (2x4), warp tile 64x32, mma.m16n8k8.tf32.
// cp.async double-buffered smem. A,W must already be tf32-rounded.
// Smem: As[2][128][36] + Bs[2][32][136] = 71680 B dynamic.
// ---------------------------------------------------------------------------
#define SM_A_STRIDE 36
#define SM_B_STRIDE 136
#define SM_A_BUF (128*SM_A_STRIDE)   // 4608 floats
#define SM_B_BUF (32*SM_B_STRIDE)    // 4352 floats
#define SM_B_BASE (2*SM_A_BUF)       // 9216
#define SMEM_BYTES ((2*SM_A_BUF + 2*SM_B_BUF)*4)  // 71680

template<bool GELU, bool RES, bool ROUND>
__global__ void __launch_bounds__(256, 2)
mma_gemm(const float* __restrict__ A, const float* __restrict__ W,
         const float* __restrict__ bias, const float* __restrict__ res,
         float* __restrict__ C, int M, int N, int K) {
    extern __shared__ float sm[];
    uint32_t sm_u = (uint32_t)__cvta_generic_to_shared(sm);

    const int tid  = threadIdx.x;
    const int lane = tid & 31;
    const int warp = tid >> 5;
    const int wm = warp >> 2;     // 0..1
    const int wn = warp & 3;      // 0..3
    const int g  = lane >> 2;     // 0..7
    const int tg = lane & 3;      // 0..3

    const int bm = blockIdx.y, bn = blockIdx.x;
    const float* Ab = A + (size_t)bm * 128 * K;
    const float* Wb = W + bn * 128;

    // staging thread mapping
    const int arow = tid >> 3;            // 0..31 (+32p)
    const int ac4  = (tid & 7) << 2;      // 0..28
    const int brow = warp;                // 0..7 (+8p)
    const int bn4  = lane << 2;           // 0..124

    float acc[4][4][4];
    #pragma unroll
    for (int i = 0; i < 4; i++)
        #pragma unroll
        for (int j = 0; j < 4; j++)
            #pragma unroll
            for (int c = 0; c < 4; c++) acc[i][j][c] = 0.f;

    auto issue = [&](int buf, int kt) {
        int k0 = kt * 32;
        uint32_t sA = sm_u + (uint32_t)(buf * SM_A_BUF) * 4;
        #pragma unroll
        for (int p = 0; p < 4; p++) {
            int r = arow + p * 32;
            cp16(sA + (uint32_t)(r * SM_A_STRIDE + ac4) * 4,
                 Ab + (size_t)r * K + k0 + ac4);
        }
        uint32_t sB = sm_u + (uint32_t)(SM_B_BASE + buf * SM_B_BUF) * 4;
        #pragma unroll
        for (int p = 0; p < 4; p++) {
            int kk = brow + p * 8;
            cp16(sB + (uint32_t)(kk * SM_B_STRIDE + bn4) * 4,
                 Wb + (size_t)(k0 + kk) * N + bn4);
        }
        asm volatile("cp.async.commit_group;\n");
    };

    const int KT = K >> 5;
    issue(0, 0);

    for (int kt = 0; kt < KT; kt++) {
        asm volatile("cp.async.wait_group 0;\n");
        __syncthreads();
        if (kt + 1 < KT) issue((kt + 1) & 1, kt + 1);

        const float* As = sm + (kt & 1) * SM_A_BUF;
        const float* Bs = sm + SM_B_BASE + (kt & 1) * SM_B_BUF;

        #pragma unroll
        for (int ks = 0; ks < 4; ks++) {
            const int k0 = ks * 8;
            uint32_t af[4][4];
            #pragma unroll
            for (int mi = 0; mi < 4; mi++) {
                int r = wm * 64 + mi * 16 + g;
                af[mi][0] = __float_as_uint(As[r * SM_A_STRIDE + k0 + tg]);
                af[mi][1] = __float_as_uint(As[(r + 8) * SM_A_STRIDE + k0 + tg]);
                af[mi][2] = __float_as_uint(As[r * SM_A_STRIDE + k0 + tg + 4]);
                af[mi][3] = __float_as_uint(As[(r + 8) * SM_A_STRIDE + k0 + tg + 4]);
            }
            uint32_t bf[4][2];
            #pragma unroll
            for (int ni = 0; ni < 4; ni++) {
                int n = wn * 32 + ni * 8 + g;
                bf[ni][0] = __float_as_uint(Bs[(k0 + tg) * SM_B_STRIDE + n]);
                bf[ni][1] = __float_as_uint(Bs[(k0 + tg + 4) * SM_B_STRIDE + n]);
            }
            #pragma unroll
            for (int mi = 0; mi < 4; mi++)
                #pragma unroll
                for (int ni = 0; ni < 4; ni++) {
                    asm volatile(
                        "mma.sync.aligned.m16n8k8.row.col.f32.tf32.tf32.f32 "
                        "{%0,%1,%2,%3}, {%4,%5,%6,%7}, {%8,%9}, {%0,%1,%2,%3};"
                        : "+f"(acc[mi][ni][0]), "+f"(acc[mi][ni][1]),
                          "+f"(acc[mi][ni][2]), "+f"(acc[mi][ni][3])
                        : "r"(af[mi][0]), "r"(af[mi][1]), "r"(af[mi][2]), "r"(af[mi][3]),
                          "r"(bf[ni][0]), "r"(bf[ni][1]));
                }
        }
        __syncthreads();
    }

    // Epilogue
    const int rowBase = bm * 128 + wm * 64;
    const int colBase = bn * 128 + wn * 32;
    #pragma unroll
    for (int mi = 0; mi < 4; mi++) {
        #pragma unroll
        for (int ni = 0; ni < 4; ni++) {
            int col = colBase + ni * 8 + 2 * tg;
            float bb0 = bias[col], bb1 = bias[col + 1];
            int r0 = rowBase + mi * 16 + g;
            int r1 = r0 + 8;
            float v0 = acc[mi][ni][0] + bb0;
            float v1 = acc[mi][ni][1] + bb1;
            float v2 = acc[mi][ni][2] + bb0;
            float v3 = acc[mi][ni][3] + bb1;
            if (GELU) { v0 = gelu_f(v0); v1 = gelu_f(v1); v2 = gelu_f(v2); v3 = gelu_f(v3); }
            if (RES) {
                const float2 rr0 = *reinterpret_cast<const float2*>(res + (size_t)r0 * N + col);
                const float2 rr1 = *reinterpret_cast<const float2*>(res + (size_t)r1 * N + col);
                v0 += rr0.x; v1 += rr0.y; v2 += rr1.x; v3 += rr1.y;
            }
            if (ROUND) { v0 = rtf32(v0); v1 = rtf32(v1); v2 = rtf32(v2); v3 = rtf32(v3); }
            *reinterpret_cast<float2*>(C + (size_t)r0 * N + col) = make_float2(v0, v1);
            *reinterpret_cast<float2*>(C + (size_t)r1 * N + col) = make_float2(v2, v3);
        }
    }
}

// ---------------------------------------------------------------------------
// Flash-style causal attention, fp32 (unchanged except tf32-rounded output,
// since attention output feeds the proj GEMM).
// ---------------------------------------------------------------------------
#define QTILE 32
#define KTILE 64

__global__ void __launch_bounds__(256)
attn_kernel(const float* __restrict__ qkv, float* __restrict__ out) {
    int qt0 = blockIdx.x * QTILE;
    int h   = blockIdx.y;
    int b   = blockIdx.z;
    int tid = threadIdx.x, lane = tid & 31, warp = tid >> 5;

    __shared__ float Qs[QTILE][DH];
    __shared__ float Kt[DH][KTILE + 1];
    __shared__ float Vs[KTILE][DH];

    const float* base = qkv + (size_t)b * TT * (3 * EE);

    #pragma unroll
    for (int it = 0; it < 2; it++) {
        int i = tid + it * 256;
        int r  = i >> 4;
        int d4 = (i & 15) << 2;
        *reinterpret_cast<float4*>(&Qs[r][d4]) =
            *reinterpret_cast<const float4*>(base + (size_t)(qt0 + r) * 3072 + h * 64 + d4);
    }

    float m[4], l[4], o0[4], o1[4];
    #pragma unroll
    for (int ri = 0; ri < 4; ri++) { m[ri] = -1e30f; l[ri] = 0.f; o0[ri] = 0.f; o1[ri] = 0.f; }

    int rmax = qt0 + QTILE - 1;
    for (int kt0 = 0; kt0 <= rmax; kt0 += KTILE) {
        __syncthreads();
        #pragma unroll
        for (int it = 0; it < 4; it++) {
            int i = tid + it * 256;
            int kk = i >> 4;
            int d4 = (i & 15) << 2;
            const float* kp = base + (size_t)(kt0 + kk) * 3072 + EE + h * 64 + d4;
            float4 k4 = *reinterpret_cast<const float4*>(kp);
            Kt[d4 + 0][kk] = k4.x;
            Kt[d4 + 1][kk] = k4.y;
            Kt[d4 + 2][kk] = k4.z;
            Kt[d4 + 3][kk] = k4.w;
            float4 v4 = *reinterpret_cast<const float4*>(kp + EE);
            *reinterpret_cast<float4*>(&Vs[kk][d4]) = v4;
        }
        __syncthreads();

        #pragma unroll
        for (int ri = 0; ri < 4; ri++) {
            int r = warp * 4 + ri;
            int qrow = qt0 + r;
            float s0 = 0.f, s1 = 0.f;
            #pragma unroll
            for (int d = 0; d < DH; d++) {
                float qd = Qs[r][d];
                s0 = fmaf(qd, Kt[d][lane],      s0);
                s1 = fmaf(qd, Kt[d][lane + 32], s1);
            }
            s0 *= 0.125f; s1 *= 0.125f;
            if (kt0 + lane      > qrow) s0 = -1e30f;
            if (kt0 + lane + 32 > qrow) s1 = -1e30f;

            float tm = fmaxf(s0, s1);
            #pragma unroll
            for (int o = 16; o > 0; o >>= 1)
                tm = fmaxf(tm, __shfl_xor_sync(0xffffffff, tm, o));
            float mn = fmaxf(m[ri], tm);

            float p0 = __expf(s0 - mn);
            float p1 = __expf(s1 - mn);
            float ps = p0 + p1;
            #pragma unroll
            for (int o = 16; o > 0; o >>= 1)
                ps += __shfl_xor_sync(0xffffffff, ps, o);

            float scale = __expf(m[ri] - mn);
            l[ri] = l[ri] * scale + ps;
            m[ri] = mn;
            o0[ri] *= scale;
            o1[ri] *= scale;

            #pragma unroll
            for (int j = 0; j < 32; j++) {
                float pj0 = __shfl_sync(0xffffffff, p0, j);
                float pj1 = __shfl_sync(0xffffffff, p1, j);
                o0[ri] = fmaf(pj0, Vs[j][lane],           o0[ri]);
                o0[ri] = fmaf(pj1, Vs[j + 32][lane],      o0[ri]);
                o1[ri] = fmaf(pj0, Vs[j][lane + 32],      o1[ri]);
                o1[ri] = fmaf(pj1, Vs[j + 32][lane + 32], o1[ri]);
            }
        }
    }

    #pragma unroll
    for (int ri = 0; ri < 4; ri++) {
        int qrow = qt0 + warp * 4 + ri;
        float inv = 1.0f / l[ri];
        size_t o = ((size_t)b * TT + qrow) * EE + h * 64 + lane;
        out[o]      = rtf32(o0[ri] * inv);
        out[o + 32] = rtf32(o1[ri] * inv);
    }
}

// ---------------------------------------------------------------------------
// Launch
// ---------------------------------------------------------------------------
extern "C" void kernel_launch(void* const* d_in, const int* in_sizes, int n_in,
                              void* d_out, int out_size) {
    const float* x        = (const float*)d_in[0];
    const float* c_attn_w = (const float*)d_in[1];
    const float* c_attn_b = (const float*)d_in[2];
    const float* c_proj_w = (const float*)d_in[3];
    const float* c_proj_b = (const float*)d_in[4];
    const float* mlp_w1   = (const float*)d_in[5];
    const float* mlp_b1   = (const float*)d_in[6];
    const float* mlp_w2   = (const float*)d_in[7];
    const float* mlp_b2   = (const float*)d_in[8];
    const float* ln1_g    = (const float*)d_in[9];
    const float* ln1_b    = (const float*)d_in[10];
    const float* ln2_g    = (const float*)d_in[11];
    const float* ln2_b    = (const float*)d_in[12];
    float* out = (float*)d_out;

    float *ln, *qkv, *att, *x2, *act, *w;
    cudaGetSymbolAddress((void**)&ln,  g_ln);
    cudaGetSymbolAddress((void**)&qkv, g_qkv);
    cudaGetSymbolAddress((void**)&att, g_att);
    cudaGetSymbolAddress((void**)&x2,  g_x2);
    cudaGetSymbolAddress((void**)&act, g_act);
    cudaGetSymbolAddress((void**)&w,   g_w);

    cudaFuncSetAttribute(mma_gemm<false, false, false>,
                         cudaFuncAttributeMaxDynamicSharedMemorySize, SMEM_BYTES);
    cudaFuncSetAttribute(mma_gemm<false, true, false>,
                         cudaFuncAttributeMaxDynamicSharedMemorySize, SMEM_BYTES);
    cudaFuncSetAttribute(mma_gemm<true, false, true>,
                         cudaFuncAttributeMaxDynamicSharedMemorySize, SMEM_BYTES);

    // Pre-round weights to tf32
    round_w_kernel<<<512, 256>>>(c_attn_w, w + W_ATTN_OFF, 3*EE*EE/4);
    round_w_kernel<<<512, 256>>>(c_proj_w, w + W_PROJ_OFF, EE*EE/4);
    round_w_kernel<<<512, 256>>>(mlp_w1,   w + W_MLP1_OFF, EE*FF/4);
    round_w_kernel<<<512, 256>>>(mlp_w2,   w + W_MLP2_OFF, FF*EE/4);

    // 1. LN1 (tf32-rounded output)
    ln_kernel<<<MM, 256>>>(x, ln1_g, ln1_b, ln);
    // 2. QKV = ln @ c_attn_w + b           [4096, 3072]  (fp32 output)
    mma_gemm<false, false, false><<<dim3(3*EE/128, MM/128), 256, SMEM_BYTES>>>(
        ln, w + W_ATTN_OFF, c_attn_b, nullptr, qkv, MM, 3*EE, EE);
    // 3. Attention (tf32-rounded output)
    attn_kernel<<<dim3(TT/QTILE, HH, BB), 256>>>(qkv, att);
    // 4. x2 = x + att @ c_proj_w + b       [4096, 1024]  (fp32 output)
    mma_gemm<false, true, false><<<dim3(EE/128, MM/128), 256, SMEM_BYTES>>>(
        att, w + W_PROJ_OFF, c_proj_b, x, x2, MM, EE, EE);
    // 5. LN2 (tf32-rounded output)
    ln_kernel<<<MM, 256>>>(x2, ln2_g, ln2_b, ln);
    // 6. act = gelu(h @ mlp_w1 + b1)       [4096, 4096]  (tf32-rounded output)
    mma_gemm<true, false, true><<<dim3(FF/128, MM/128), 256, SMEM_BYTES>>>(
        ln, w + W_MLP1_OFF, mlp_b1, nullptr, act, MM, FF, EE);
    // 7. out = x2 + act @ mlp_w2 + b2      [4096, 1024]  (fp32 output)
    mma_gemm<false, true, false><<<dim3(EE/128, MM/128), 256, SMEM_BYTES>>>(
        act, w + W_MLP2_OFF, mlp_b2, x2, out, MM, EE, FF);
}

// round 3
// speedup vs baseline: 4.1925x; 2.2876x over previous
#include <cuda_runtime.h>
#include <math.h>
#include <stdint.h>

// Problem constants
#define BB 2
#define TT 2048
#define EE 1024
#define HH 16
#define DH 64
#define FF 4096
#define MM (BB*TT)   // 4096 rows

// Scratch (device globals: no allocation allowed)
__device__ float g_ln [MM*EE];
__device__ float g_qkv[MM*3*EE];
__device__ float g_att[MM*EE];
__device__ float g_x2 [MM*EE];
__device__ float g_act[(size_t)MM*FF];

// ---------------------------------------------------------------------------
// Helpers
// ---------------------------------------------------------------------------
__device__ __forceinline__ float rtf32(float x) {
    uint32_t u;
    asm("cvt.rna.tf32.f32 %0, %1;" : "=r"(u) : "f"(x));
    return __uint_as_float(u);
}

__device__ __forceinline__ void cp16(uint32_t dst, const void* src) {
    asm volatile("cp.async.cg.shared.global [%0], [%1], 16;\n" :: "r"(dst), "l"(src));
}

#define MMA_TF32(d0,d1,d2,d3,a0,a1,a2,a3,b0,b1) \
    asm volatile( \
        "mma.sync.aligned.m16n8k8.row.col.f32.tf32.tf32.f32 " \
        "{%0,%1,%2,%3}, {%4,%5,%6,%7}, {%8,%9}, {%0,%1,%2,%3};" \
        : "+f"(d0), "+f"(d1), "+f"(d2), "+f"(d3) \
        : "r"(a0), "r"(a1), "r"(a2), "r"(a3), "r"(b0), "r"(b1))

// ---------------------------------------------------------------------------
// LayerNorm: one block per row of 1024, 256 threads
// ---------------------------------------------------------------------------
__global__ void ln_kernel(const float* __restrict__ x,
                          const float* __restrict__ g,
                          const float* __restrict__ b,
                          float* __restrict__ out) {
    int row = blockIdx.x;
    int tid = threadIdx.x;
    const float4* xr = reinterpret_cast<const float4*>(x + (size_t)row * EE);
    float4 v = xr[tid];
    float s  = v.x + v.y + v.z + v.w;
    float sq = v.x*v.x + v.y*v.y + v.z*v.z + v.w*v.w;
    #pragma unroll
    for (int o = 16; o > 0; o >>= 1) {
        s  += __shfl_xor_sync(0xffffffff, s,  o);
        sq += __shfl_xor_sync(0xffffffff, sq, o);
    }
    __shared__ float rs[8], rq[8], mu_s, rstd_s;
    int warp = tid >> 5, lane = tid & 31;
    if (lane == 0) { rs[warp] = s; rq[warp] = sq; }
    __syncthreads();
    if (tid == 0) {
        float ts = 0.f, tq = 0.f;
        #pragma unroll
        for (int i = 0; i < 8; i++) { ts += rs[i]; tq += rq[i]; }
        float mu  = ts * (1.0f / EE);
        float var = tq * (1.0f / EE) - mu * mu;
        mu_s = mu;
        rstd_s = rsqrtf(var + 1e-5f);
    }
    __syncthreads();
    float mu = mu_s, rstd = rstd_s;
    float4 gv = reinterpret_cast<const float4*>(g)[tid];
    float4 bv = reinterpret_cast<const float4*>(b)[tid];
    float4 o;
    o.x = (v.x - mu) * rstd * gv.x + bv.x;
    o.y = (v.y - mu) * rstd * gv.y + bv.y;
    o.z = (v.z - mu) * rstd * gv.z + bv.z;
    o.w = (v.w - mu) * rstd * gv.w + bv.w;
    reinterpret_cast<float4*>(out + (size_t)row * EE)[tid] = o;
}

__device__ __forceinline__ float gelu_f(float x) {
    const float c = 0.7978845608028654f;
    float x3 = x * x * x;
    return 0.5f * x * (1.0f + tanhf(c * (x + 0.044715f * x3)));
}

// ---------------------------------------------------------------------------
// tf32 tensor-core GEMM (raw fp32 operands; HW truncates to tf32)
// 128x128x32 CTA tile, 8 warps, warp tile 64x32, cp.async double-buffered.
// ---------------------------------------------------------------------------
#define SM_A_STRIDE 36
#define SM_B_STRIDE 136
#define SM_A_BUF (128*SM_A_STRIDE)
#define SM_B_BUF (32*SM_B_STRIDE)
#define SM_B_BASE (2*SM_A_BUF)
#define SMEM_BYTES ((2*SM_A_BUF + 2*SM_B_BUF)*4)  // 71680

template<bool GELU, bool RES>
__global__ void __launch_bounds__(256, 2)
mma_gemm(const float* __restrict__ A, const float* __restrict__ W,
         const float* __restrict__ bias, const float* __restrict__ res,
         float* __restrict__ C, int M, int N, int K) {
    extern __shared__ float sm[];
    uint32_t sm_u = (uint32_t)__cvta_generic_to_shared(sm);

    const int tid  = threadIdx.x;
    const int lane = tid & 31;
    const int warp = tid >> 5;
    const int wm = warp >> 2;
    const int wn = warp & 3;
    const int g  = lane >> 2;
    const int tg = lane & 3;

    const int bm = blockIdx.y, bn = blockIdx.x;
    const float* Ab = A + (size_t)bm * 128 * K;
    const float* Wb = W + bn * 128;

    const int arow = tid >> 3;
    const int ac4  = (tid & 7) << 2;
    const int brow = warp;
    const int bn4  = lane << 2;

    float acc[4][4][4];
    #pragma unroll
    for (int i = 0; i < 4; i++)
        #pragma unroll
        for (int j = 0; j < 4; j++)
            #pragma unroll
            for (int c = 0; c < 4; c++) acc[i][j][c] = 0.f;

    auto issue = [&](int buf, int kt) {
        int k0 = kt * 32;
        uint32_t sA = sm_u + (uint32_t)(buf * SM_A_BUF) * 4;
        #pragma unroll
        for (int p = 0; p < 4; p++) {
            int r = arow + p * 32;
            cp16(sA + (uint32_t)(r * SM_A_STRIDE + ac4) * 4,
                 Ab + (size_t)r * K + k0 + ac4);
        }
        uint32_t sB = sm_u + (uint32_t)(SM_B_BASE + buf * SM_B_BUF) * 4;
        #pragma unroll
        for (int p = 0; p < 4; p++) {
            int kk = brow + p * 8;
            cp16(sB + (uint32_t)(kk * SM_B_STRIDE + bn4) * 4,
                 Wb + (size_t)(k0 + kk) * N + bn4);
        }
        asm volatile("cp.async.commit_group;\n");
    };

    const int KT = K >> 5;
    issue(0, 0);

    for (int kt = 0; kt < KT; kt++) {
        if (kt + 1 < KT) {
            issue((kt + 1) & 1, kt + 1);
            asm volatile("cp.async.wait_group 1;\n");
        } else {
            asm volatile("cp.async.wait_group 0;\n");
        }
        __syncthreads();

        const float* As = sm + (kt & 1) * SM_A_BUF;
        const float* Bs = sm + SM_B_BASE + (kt & 1) * SM_B_BUF;

        #pragma unroll
        for (int ks = 0; ks < 4; ks++) {
            const int k0 = ks * 8;
            uint32_t af[4][4];
            #pragma unroll
            for (int mi = 0; mi < 4; mi++) {
                int r = wm * 64 + mi * 16 + g;
                af[mi][0] = __float_as_uint(As[r * SM_A_STRIDE + k0 + tg]);
                af[mi][1] = __float_as_uint(As[(r + 8) * SM_A_STRIDE + k0 + tg]);
                af[mi][2] = __float_as_uint(As[r * SM_A_STRIDE + k0 + tg + 4]);
                af[mi][3] = __float_as_uint(As[(r + 8) * SM_A_STRIDE + k0 + tg + 4]);
            }
            uint32_t bf[4][2];
            #pragma unroll
            for (int ni = 0; ni < 4; ni++) {
                int n = wn * 32 + ni * 8 + g;
                bf[ni][0] = __float_as_uint(Bs[(k0 + tg) * SM_B_STRIDE + n]);
                bf[ni][1] = __float_as_uint(Bs[(k0 + tg + 4) * SM_B_STRIDE + n]);
            }
            #pragma unroll
            for (int mi = 0; mi < 4; mi++)
                #pragma unroll
                for (int ni = 0; ni < 4; ni++)
                    MMA_TF32(acc[mi][ni][0], acc[mi][ni][1], acc[mi][ni][2], acc[mi][ni][3],
                             af[mi][0], af[mi][1], af[mi][2], af[mi][3],
                             bf[ni][0], bf[ni][1]);
        }
        __syncthreads();
    }

    const int rowBase = bm * 128 + wm * 64;
    const int colBase = bn * 128 + wn * 32;
    #pragma unroll
    for (int mi = 0; mi < 4; mi++) {
        #pragma unroll
        for (int ni = 0; ni < 4; ni++) {
            int col = colBase + ni * 8 + 2 * tg;
            float bb0 = bias[col], bb1 = bias[col + 1];
            int r0 = rowBase + mi * 16 + g;
            int r1 = r0 + 8;
            float v0 = acc[mi][ni][0] + bb0;
            float v1 = acc[mi][ni][1] + bb1;
            float v2 = acc[mi][ni][2] + bb0;
            float v3 = acc[mi][ni][3] + bb1;
            if (GELU) { v0 = gelu_f(v0); v1 = gelu_f(v1); v2 = gelu_f(v2); v3 = gelu_f(v3); }
            if (RES) {
                const float2 rr0 = *reinterpret_cast<const float2*>(res + (size_t)r0 * N + col);
                const float2 rr1 = *reinterpret_cast<const float2*>(res + (size_t)r1 * N + col);
                v0 += rr0.x; v1 += rr0.y; v2 += rr1.x; v3 += rr1.y;
            }
            *reinterpret_cast<float2*>(C + (size_t)r0 * N + col) = make_float2(v0, v1);
            *reinterpret_cast<float2*>(C + (size_t)r1 * N + col) = make_float2(v2, v3);
        }
    }
}

// ---------------------------------------------------------------------------
// Tensor-core flash attention (tf32 MMA for QK^T and P@V).
// CTA: 64 queries x 1 head x 1 batch. 4 warps, each owns 16 query rows.
// K tiles of 64 keys, cp.async double-buffered. Causal mask on diagonal tile.
// ---------------------------------------------------------------------------
#define KS_STRIDE 68
#define VS_STRIDE 72
#define PS_STRIDE 68
#define KS_BUF (64*KS_STRIDE)
#define VS_BUF (64*VS_STRIDE)
#define OFF_V (2*KS_BUF)
#define OFF_P (2*KS_BUF + 2*VS_BUF)
#define ATT_SMEM ((OFF_P + 64*PS_STRIDE)*4)   // 89088 bytes

__global__ void __launch_bounds__(128, 2)
attn_mma_kernel(const float* __restrict__ qkv, float* __restrict__ out) {
    extern __shared__ float sm[];
    uint32_t sm_u = (uint32_t)__cvta_generic_to_shared(sm);

    const int qt  = gridDim.x - 1 - blockIdx.x;   // long CTAs first
    const int qt0 = qt * 64;
    const int h   = blockIdx.y;
    const int b   = blockIdx.z;
    const int tid = threadIdx.x;
    const int lane = tid & 31;
    const int warp = tid >> 5;
    const int g  = lane >> 2;
    const int tg = lane & 3;
    const int r0 = warp * 16 + g;   // this thread's first query row (local)

    const float* base = qkv + (size_t)b * TT * (3 * EE);

    auto issueKV = [&](int buf, int kt) {
        int krow0 = kt * 64;
        uint32_t sK = sm_u + (uint32_t)(buf * KS_BUF) * 4;
        uint32_t sV = sm_u + (uint32_t)(OFF_V + buf * VS_BUF) * 4;
        #pragma unroll
        for (int it = 0; it < 8; it++) {
            int i = tid + it * 128;
            int row = i >> 4;
            int c4  = (i & 15) << 2;
            const float* src = base + (size_t)(krow0 + row) * 3072 + EE + h * 64 + c4;
            cp16(sK + (uint32_t)(row * KS_STRIDE + c4) * 4, src);
            cp16(sV + (uint32_t)(row * VS_STRIDE + c4) * 4, src + EE);
        }
        asm volatile("cp.async.commit_group;\n");
    };

    issueKV(0, 0);

    // Stage Q (pre-scaled by 1/8, RNA-rounded to tf32) into the P buffer
    #pragma unroll
    for (int it = 0; it < 8; it++) {
        int i = tid + it * 128;
        int row = i >> 4;
        int c4  = (i & 15) << 2;
        float4 q4 = *reinterpret_cast<const float4*>(
            base + (size_t)(qt0 + row) * 3072 + h * 64 + c4);
        q4.x = rtf32(q4.x * 0.125f);
        q4.y = rtf32(q4.y * 0.125f);
        q4.z = rtf32(q4.z * 0.125f);
        q4.w = rtf32(q4.w * 0.125f);
        *reinterpret_cast<float4*>(&sm[OFF_P + row * PS_STRIDE + c4]) = q4;
    }
    __syncthreads();

    // Preload Q fragments into registers (reused across all K tiles)
    uint32_t qa[8][4];
    #pragma unroll
    for (int kc = 0; kc < 8; kc++) {
        qa[kc][0] = __float_as_uint(sm[OFF_P + r0       * PS_STRIDE + kc * 8 + tg]);
        qa[kc][1] = __float_as_uint(sm[OFF_P + (r0 + 8) * PS_STRIDE + kc * 8 + tg]);
        qa[kc][2] = __float_as_uint(sm[OFF_P + r0       * PS_STRIDE + kc * 8 + tg + 4]);
        qa[kc][3] = __float_as_uint(sm[OFF_P + (r0 + 8) * PS_STRIDE + kc * 8 + tg + 4]);
    }

    float m0 = -1e30f, m1 = -1e30f, l0 = 0.f, l1 = 0.f;
    float ob[8][4];
    #pragma unroll
    for (int nt = 0; nt < 8; nt++)
        #pragma unroll
        for (int c = 0; c < 4; c++) ob[nt][c] = 0.f;

    const int nkt = qt + 1;
    for (int kt = 0; kt < nkt; kt++) {
        if (kt + 1 < nkt) {
            issueKV((kt + 1) & 1, kt + 1);
            asm volatile("cp.async.wait_group 1;\n");
        } else {
            asm volatile("cp.async.wait_group 0;\n");
        }
        __syncthreads();

        const float* Ks = sm + (kt & 1) * KS_BUF;
        const float* Vs = sm + OFF_V + (kt & 1) * VS_BUF;

        // S = Q @ K^T
        float sc[8][4];
        #pragma unroll
        for (int nt = 0; nt < 8; nt++)
            #pragma unroll
            for (int c = 0; c < 4; c++) sc[nt][c] = 0.f;

        #pragma unroll
        for (int kc = 0; kc < 8; kc++) {
            #pragma unroll
            for (int nt = 0; nt < 8; nt++) {
                uint32_t b0 = __float_as_uint(Ks[(nt * 8 + g) * KS_STRIDE + kc * 8 + tg]);
                uint32_t b1 = __float_as_uint(Ks[(nt * 8 + g) * KS_STRIDE + kc * 8 + tg + 4]);
                MMA_TF32(sc[nt][0], sc[nt][1], sc[nt][2], sc[nt][3],
                         qa[kc][0], qa[kc][1], qa[kc][2], qa[kc][3], b0, b1);
            }
        }

        // Causal mask (diagonal tile only)
        if (kt == nkt - 1) {
            int qrow0 = qt0 + r0;
            int qrow1 = qrow0 + 8;
            #pragma unroll
            for (int nt = 0; nt < 8; nt++) {
                int kc0 = kt * 64 + nt * 8 + 2 * tg;
                if (kc0     > qrow0) sc[nt][0] = -1e30f;
                if (kc0 + 1 > qrow0) sc[nt][1] = -1e30f;
                if (kc0     > qrow1) sc[nt][2] = -1e30f;
                if (kc0 + 1 > qrow1) sc[nt][3] = -1e30f;
            }
        }

        // Online softmax (rows r0 and r0+8)
        float rm0 = -1e30f, rm1 = -1e30f;
        #pragma unroll
        for (int nt = 0; nt < 8; nt++) {
            rm0 = fmaxf(rm0, fmaxf(sc[nt][0], sc[nt][1]));
            rm1 = fmaxf(rm1, fmaxf(sc[nt][2], sc[nt][3]));
        }
        rm0 = fmaxf(rm0, __shfl_xor_sync(0xffffffff, rm0, 1));
        rm0 = fmaxf(rm0, __shfl_xor_sync(0xffffffff, rm0, 2));
        rm1 = fmaxf(rm1, __shfl_xor_sync(0xffffffff, rm1, 1));
        rm1 = fmaxf(rm1, __shfl_xor_sync(0xffffffff, rm1, 2));
        float mn0 = fmaxf(m0, rm0);
        float mn1 = fmaxf(m1, rm1);

        float rs0 = 0.f, rs1 = 0.f;
        #pragma unroll
        for (int nt = 0; nt < 8; nt++) {
            sc[nt][0] = __expf(sc[nt][0] - mn0);
            sc[nt][1] = __expf(sc[nt][1] - mn0);
            sc[nt][2] = __expf(sc[nt][2] - mn1);
            sc[nt][3] = __expf(sc[nt][3] - mn1);
            rs0 += sc[nt][0] + sc[nt][1];
            rs1 += sc[nt][2] + sc[nt][3];
        }
        rs0 += __shfl_xor_sync(0xffffffff, rs0, 1);
        rs0 += __shfl_xor_sync(0xffffffff, rs0, 2);
        rs1 += __shfl_xor_sync(0xffffffff, rs1, 1);
        rs1 += __shfl_xor_sync(0xffffffff, rs1, 2);

        float scale0 = __expf(m0 - mn0);
        float scale1 = __expf(m1 - mn1);
        l0 = l0 * scale0 + rs0;
        l1 = l1 * scale1 + rs1;
        m0 = mn0; m1 = mn1;
        #pragma unroll
        for (int nt = 0; nt < 8; nt++) {
            ob[nt][0] *= scale0; ob[nt][1] *= scale0;
            ob[nt][2] *= scale1; ob[nt][3] *= scale1;
        }

        // Store P (RNA-rounded) to warp-private smem rows
        __syncwarp();
        #pragma unroll
        for (int nt = 0; nt < 8; nt++) {
            *reinterpret_cast<float2*>(&sm[OFF_P + r0 * PS_STRIDE + nt * 8 + 2 * tg]) =
                make_float2(rtf32(sc[nt][0]), rtf32(sc[nt][1]));
            *reinterpret_cast<float2*>(&sm[OFF_P + (r0 + 8) * PS_STRIDE + nt * 8 + 2 * tg]) =
                make_float2(rtf32(sc[nt][2]), rtf32(sc[nt][3]));
        }
        __syncwarp();

        // O += P @ V
        #pragma unroll
        for (int kc = 0; kc < 8; kc++) {
            uint32_t pa0 = __float_as_uint(sm[OFF_P + r0       * PS_STRIDE + kc * 8 + tg]);
            uint32_t pa1 = __float_as_uint(sm[OFF_P + (r0 + 8) * PS_STRIDE + kc * 8 + tg]);
            uint32_t pa2 = __float_as_uint(sm[OFF_P + r0       * PS_STRIDE + kc * 8 + tg + 4]);
            uint32_t pa3 = __float_as_uint(sm[OFF_P + (r0 + 8) * PS_STRIDE + kc * 8 + tg + 4]);
            #pragma unroll
            for (int nt = 0; nt < 8; nt++) {
                uint32_t vb0 = __float_as_uint(Vs[(kc * 8 + tg)     * VS_STRIDE + nt * 8 + g]);
                uint32_t vb1 = __float_as_uint(Vs[(kc * 8 + tg + 4) * VS_STRIDE + nt * 8 + g]);
                MMA_TF32(ob[nt][0], ob[nt][1], ob[nt][2], ob[nt][3],
                         pa0, pa1, pa2, pa3, vb0, vb1);
            }
        }
        __syncthreads();   // protect K/V buffers before next issue
    }

    // Epilogue: normalize and write
    float inv0 = 1.0f / l0;
    float inv1 = 1.0f / l1;
    size_t row0 = ((size_t)b * TT + qt0 + r0) * EE + h * 64;
    size_t row1 = row0 + 8 * EE;
    #pragma unroll
    for (int nt = 0; nt < 8; nt++) {
        int col = nt * 8 + 2 * tg;
        *reinterpret_cast<float2*>(out + row0 + col) =
            make_float2(ob[nt][0] * inv0, ob[nt][1] * inv0);
        *reinterpret_cast<float2*>(out + row1 + col) =
            make_float2(ob[nt][2] * inv1, ob[nt][3] * inv1);
    }
}

// ---------------------------------------------------------------------------
// Launch
// ---------------------------------------------------------------------------
extern "C" void kernel_launch(void* const* d_in, const int* in_sizes, int n_in,
                              void* d_out, int out_size) {
    const float* x        = (const float*)d_in[0];
    const float* c_attn_w = (const float*)d_in[1];
    const float* c_attn_b = (const float*)d_in[2];
    const float* c_proj_w = (const float*)d_in[3];
    const float* c_proj_b = (const float*)d_in[4];
    const float* mlp_w1   = (const float*)d_in[5];
    const float* mlp_b1   = (const float*)d_in[6];
    const float* mlp_w2   = (const float*)d_in[7];
    const float* mlp_b2   = (const float*)d_in[8];
    const float* ln1_g    = (const float*)d_in[9];
    const float* ln1_b    = (const float*)d_in[10];
    const float* ln2_g    = (const float*)d_in[11];
    const float* ln2_b    = (const float*)d_in[12];
    float* out = (float*)d_out;

    float *ln, *qkv, *att, *x2, *act;
    cudaGetSymbolAddress((void**)&ln,  g_ln);
    cudaGetSymbolAddress((void**)&qkv, g_qkv);
    cudaGetSymbolAddress((void**)&att, g_att);
    cudaGetSymbolAddress((void**)&x2,  g_x2);
    cudaGetSymbolAddress((void**)&act, g_act);

    cudaFuncSetAttribute(mma_gemm<false, false>,
                         cudaFuncAttributeMaxDynamicSharedMemorySize, SMEM_BYTES);
    cudaFuncSetAttribute(mma_gemm<false, true>,
                         cudaFuncAttributeMaxDynamicSharedMemorySize, SMEM_BYTES);
    cudaFuncSetAttribute(mma_gemm<true, false>,
                         cudaFuncAttributeMaxDynamicSharedMemorySize, SMEM_BYTES);
    cudaFuncSetAttribute(attn_mma_kernel,
                         cudaFuncAttributeMaxDynamicSharedMemorySize, ATT_SMEM);

    // 1. LN1
    ln_kernel<<<MM, 256>>>(x, ln1_g, ln1_b, ln);
    // 2. QKV = ln @ c_attn_w + b           [4096, 3072]
    mma_gemm<false, false><<<dim3(3*EE/128, MM/128), 256, SMEM_BYTES>>>(
        ln, c_attn_w, c_attn_b, nullptr, qkv, MM, 3*EE, EE);
    // 3. Attention (tensor-core flash)
    attn_mma_kernel<<<dim3(TT/64, HH, BB), 128, ATT_SMEM>>>(qkv, att);
    // 4. x2 = x + att @ c_proj_w + b       [4096, 1024]
    mma_gemm<false, true><<<dim3(EE/128, MM/128), 256, SMEM_BYTES>>>(
        att, c_proj_w, c_proj_b, x, x2, MM, EE, EE);
    // 5. LN2
    ln_kernel<<<MM, 256>>>(x2, ln2_g, ln2_b, ln);
    // 6. act = gelu(h @ mlp_w1 + b1)       [4096, 4096]
    mma_gemm<true, false><<<dim3(FF/128, MM/128), 256, SMEM_BYTES>>>(
        ln, mlp_w1, mlp_b1, nullptr, act, MM, FF, EE);
    // 7. out = x2 + act @ mlp_w2 + b2      [4096, 1024]
    mma_gemm<false, true><<<dim3(EE/128, MM/128), 256, SMEM_BYTES>>>(
        act, mlp_w2, mlp_b2, x2, out, MM, EE, FF);
}

// round 4
// speedup vs baseline: 4.1933x; 1.0002x over previous
#include <cuda_runtime.h>
#include <math.h>
#include <stdint.h>

// Problem constants
#define BB 2
#define TT 2048
#define EE 1024
#define HH 16
#define DH 64
#define FF 4096
#define MM (BB*TT)   // 4096 rows

// Scratch (device globals: no allocation allowed)
__device__ float g_ln [MM*EE];
__device__ float g_qkv[MM*3*EE];
__device__ float g_att[MM*EE];
__device__ float g_x2 [MM*EE];
__device__ float g_act[(size_t)MM*FF];

// ---------------------------------------------------------------------------
// Helpers
// ---------------------------------------------------------------------------
__device__ __forceinline__ float rtf32(float x) {
    uint32_t u;
    asm("cvt.rna.tf32.f32 %0, %1;" : "=r"(u) : "f"(x));
    return __uint_as_float(u);
}

__device__ __forceinline__ void cp16(uint32_t dst, const void* src) {
    asm volatile("cp.async.cg.shared.global [%0], [%1], 16;\n" :: "r"(dst), "l"(src));
}

#define MMA_TF32(d0,d1,d2,d3,a0,a1,a2,a3,b0,b1) \
    asm volatile( \
        "mma.sync.aligned.m16n8k8.row.col.f32.tf32.tf32.f32 " \
        "{%0,%1,%2,%3}, {%4,%5,%6,%7}, {%8,%9}, {%0,%1,%2,%3};" \
        : "+f"(d0), "+f"(d1), "+f"(d2), "+f"(d3) \
        : "r"(a0), "r"(a1), "r"(a2), "r"(a3), "r"(b0), "r"(b1))

// ---------------------------------------------------------------------------
// LayerNorm: one block per row of 1024, 256 threads
// ---------------------------------------------------------------------------
__global__ void ln_kernel(const float* __restrict__ x,
                          const float* __restrict__ g,
                          const float* __restrict__ b,
                          float* __restrict__ out) {
    int row = blockIdx.x;
    int tid = threadIdx.x;
    const float4* xr = reinterpret_cast<const float4*>(x + (size_t)row * EE);
    float4 v = xr[tid];
    float s  = v.x + v.y + v.z + v.w;
    float sq = v.x*v.x + v.y*v.y + v.z*v.z + v.w*v.w;
    #pragma unroll
    for (int o = 16; o > 0; o >>= 1) {
        s  += __shfl_xor_sync(0xffffffff, s,  o);
        sq += __shfl_xor_sync(0xffffffff, sq, o);
    }
    __shared__ float rs[8], rq[8], mu_s, rstd_s;
    int warp = tid >> 5, lane = tid & 31;
    if (lane == 0) { rs[warp] = s; rq[warp] = sq; }
    __syncthreads();
    if (tid == 0) {
        float ts = 0.f, tq = 0.f;
        #pragma unroll
        for (int i = 0; i < 8; i++) { ts += rs[i]; tq += rq[i]; }
        float mu  = ts * (1.0f / EE);
        float var = tq * (1.0f / EE) - mu * mu;
        mu_s = mu;
        rstd_s = rsqrtf(var + 1e-5f);
    }
    __syncthreads();
    float mu = mu_s, rstd = rstd_s;
    float4 gv = reinterpret_cast<const float4*>(g)[tid];
    float4 bv = reinterpret_cast<const float4*>(b)[tid];
    float4 o;
    o.x = (v.x - mu) * rstd * gv.x + bv.x;
    o.y = (v.y - mu) * rstd * gv.y + bv.y;
    o.z = (v.z - mu) * rstd * gv.z + bv.z;
    o.w = (v.w - mu) * rstd * gv.w + bv.w;
    reinterpret_cast<float4*>(out + (size_t)row * EE)[tid] = o;
}

__device__ __forceinline__ float gelu_f(float x) {
    const float c = 0.7978845608028654f;
    float x3 = x * x * x;
    return 0.5f * x * (1.0f + tanhf(c * (x + 0.044715f * x3)));
}

// ---------------------------------------------------------------------------
// tf32 tensor-core GEMM (raw fp32 operands; HW truncates to tf32)
// 128x128x32 CTA tile, 8 warps, warp tile 64x32.
// 3-stage cp.async pipeline, ONE __syncthreads per k-iteration:
//   iter kt: wait(group kt) -> sync -> issue(kt+2 into buf (kt+2)%3) -> compute(kt)
// issue target buf (kt+2)%3 == (kt-1)%3 was last read at iter kt-1; the sync
// at iter kt orders all warps past that read, so the overwrite is safe.
// ---------------------------------------------------------------------------
#define SM_A_STRIDE 36
#define SM_B_STRIDE 136
#define SM_A_BUF (128*SM_A_STRIDE)   // 4608 floats
#define SM_B_BUF (32*SM_B_STRIDE)    // 4352 floats
#define SM_B_BASE (3*SM_A_BUF)       // 13824
#define SMEM_BYTES ((3*SM_A_BUF + 3*SM_B_BUF)*4)  // 107520

template<bool GELU, bool RES>
__global__ void __launch_bounds__(256, 2)
mma_gemm(const float* __restrict__ A, const float* __restrict__ W,
         const float* __restrict__ bias, const float* __restrict__ res,
         float* __restrict__ C, int M, int N, int K) {
    extern __shared__ float sm[];
    uint32_t sm_u = (uint32_t)__cvta_generic_to_shared(sm);

    const int tid  = threadIdx.x;
    const int lane = tid & 31;
    const int warp = tid >> 5;
    const int wm = warp >> 2;
    const int wn = warp & 3;
    const int g  = lane >> 2;
    const int tg = lane & 3;

    const int bm = blockIdx.y, bn = blockIdx.x;
    const float* Ab = A + (size_t)bm * 128 * K;
    const float* Wb = W + bn * 128;

    const int arow = tid >> 3;
    const int ac4  = (tid & 7) << 2;
    const int brow = warp;
    const int bn4  = lane << 2;

    float acc[4][4][4];
    #pragma unroll
    for (int i = 0; i < 4; i++)
        #pragma unroll
        for (int j = 0; j < 4; j++)
            #pragma unroll
            for (int c = 0; c < 4; c++) acc[i][j][c] = 0.f;

    auto issue = [&](int buf, int kt) {
        int k0 = kt * 32;
        uint32_t sA = sm_u + (uint32_t)(buf * SM_A_BUF) * 4;
        #pragma unroll
        for (int p = 0; p < 4; p++) {
            int r = arow + p * 32;
            cp16(sA + (uint32_t)(r * SM_A_STRIDE + ac4) * 4,
                 Ab + (size_t)r * K + k0 + ac4);
        }
        uint32_t sB = sm_u + (uint32_t)(SM_B_BASE + buf * SM_B_BUF) * 4;
        #pragma unroll
        for (int p = 0; p < 4; p++) {
            int kk = brow + p * 8;
            cp16(sB + (uint32_t)(kk * SM_B_STRIDE + bn4) * 4,
                 Wb + (size_t)(k0 + kk) * N + bn4);
        }
        asm volatile("cp.async.commit_group;\n");
    };

    const int KT = K >> 5;   // >= 32 here
    issue(0, 0);
    issue(1, 1);

    int rbuf = 0, ibuf = 2;
    for (int kt = 0; kt < KT; kt++) {
        if (kt + 1 < KT) {
            asm volatile("cp.async.wait_group 1;\n");
        } else {
            asm volatile("cp.async.wait_group 0;\n");
        }
        __syncthreads();
        if (kt + 2 < KT) {
            issue(ibuf, kt + 2);
            if (++ibuf == 3) ibuf = 0;
        }

        const float* As = sm + rbuf * SM_A_BUF;
        const float* Bs = sm + SM_B_BASE + rbuf * SM_B_BUF;
        if (++rbuf == 3) rbuf = 0;

        #pragma unroll
        for (int ks = 0; ks < 4; ks++) {
            const int k0 = ks * 8;
            uint32_t af[4][4];
            #pragma unroll
            for (int mi = 0; mi < 4; mi++) {
                int r = wm * 64 + mi * 16 + g;
                af[mi][0] = __float_as_uint(As[r * SM_A_STRIDE + k0 + tg]);
                af[mi][1] = __float_as_uint(As[(r + 8) * SM_A_STRIDE + k0 + tg]);
                af[mi][2] = __float_as_uint(As[r * SM_A_STRIDE + k0 + tg + 4]);
                af[mi][3] = __float_as_uint(As[(r + 8) * SM_A_STRIDE + k0 + tg + 4]);
            }
            uint32_t bf[4][2];
            #pragma unroll
            for (int ni = 0; ni < 4; ni++) {
                int n = wn * 32 + ni * 8 + g;
                bf[ni][0] = __float_as_uint(Bs[(k0 + tg) * SM_B_STRIDE + n]);
                bf[ni][1] = __float_as_uint(Bs[(k0 + tg + 4) * SM_B_STRIDE + n]);
            }
            #pragma unroll
            for (int mi = 0; mi < 4; mi++)
                #pragma unroll
                for (int ni = 0; ni < 4; ni++)
                    MMA_TF32(acc[mi][ni][0], acc[mi][ni][1], acc[mi][ni][2], acc[mi][ni][3],
                             af[mi][0], af[mi][1], af[mi][2], af[mi][3],
                             bf[ni][0], bf[ni][1]);
        }
    }

    const int rowBase = bm * 128 + wm * 64;
    const int colBase = bn * 128 + wn * 32;
    #pragma unroll
    for (int mi = 0; mi < 4; mi++) {
        #pragma unroll
        for (int ni = 0; ni < 4; ni++) {
            int col = colBase + ni * 8 + 2 * tg;
            float bb0 = bias[col], bb1 = bias[col + 1];
            int r0 = rowBase + mi * 16 + g;
            int r1 = r0 + 8;
            float v0 = acc[mi][ni][0] + bb0;
            float v1 = acc[mi][ni][1] + bb1;
            float v2 = acc[mi][ni][2] + bb0;
            float v3 = acc[mi][ni][3] + bb1;
            if (GELU) { v0 = gelu_f(v0); v1 = gelu_f(v1); v2 = gelu_f(v2); v3 = gelu_f(v3); }
            if (RES) {
                const float2 rr0 = *reinterpret_cast<const float2*>(res + (size_t)r0 * N + col);
                const float2 rr1 = *reinterpret_cast<const float2*>(res + (size_t)r1 * N + col);
                v0 += rr0.x; v1 += rr0.y; v2 += rr1.x; v3 += rr1.y;
            }
            *reinterpret_cast<float2*>(C + (size_t)r0 * N + col) = make_float2(v0, v1);
            *reinterpret_cast<float2*>(C + (size_t)r1 * N + col) = make_float2(v2, v3);
        }
    }
}

// ---------------------------------------------------------------------------
// Tensor-core flash attention (tf32 MMA for QK^T and P@V).
// CTA: 64 queries x 1 head x 1 batch. 4 warps, each owns 16 query rows.
// K tiles of 64 keys, cp.async double-buffered. Causal mask on diagonal tile.
// ---------------------------------------------------------------------------
#define KS_STRIDE 68
#define VS_STRIDE 72
#define PS_STRIDE 68
#define KS_BUF (64*KS_STRIDE)
#define VS_BUF (64*VS_STRIDE)
#define OFF_V (2*KS_BUF)
#define OFF_P (2*KS_BUF + 2*VS_BUF)
#define ATT_SMEM ((OFF_P + 64*PS_STRIDE)*4)   // 89088 bytes

__global__ void __launch_bounds__(128, 2)
attn_mma_kernel(const float* __restrict__ qkv, float* __restrict__ out) {
    extern __shared__ float sm[];
    uint32_t sm_u = (uint32_t)__cvta_generic_to_shared(sm);

    const int qt  = gridDim.x - 1 - blockIdx.x;   // long CTAs first
    const int qt0 = qt * 64;
    const int h   = blockIdx.y;
    const int b   = blockIdx.z;
    const int tid = threadIdx.x;
    const int lane = tid & 31;
    const int warp = tid >> 5;
    const int g  = lane >> 2;
    const int tg = lane & 3;
    const int r0 = warp * 16 + g;   // this thread's first query row (local)

    const float* base = qkv + (size_t)b * TT * (3 * EE);

    auto issueKV = [&](int buf, int kt) {
        int krow0 = kt * 64;
        uint32_t sK = sm_u + (uint32_t)(buf * KS_BUF) * 4;
        uint32_t sV = sm_u + (uint32_t)(OFF_V + buf * VS_BUF) * 4;
        #pragma unroll
        for (int it = 0; it < 8; it++) {
            int i = tid + it * 128;
            int row = i >> 4;
            int c4  = (i & 15) << 2;
            const float* src = base + (size_t)(krow0 + row) * 3072 + EE + h * 64 + c4;
            cp16(sK + (uint32_t)(row * KS_STRIDE + c4) * 4, src);
            cp16(sV + (uint32_t)(row * VS_STRIDE + c4) * 4, src + EE);
        }
        asm volatile("cp.async.commit_group;\n");
    };

    issueKV(0, 0);

    // Stage Q (pre-scaled by 1/8, RNA-rounded to tf32) into the P buffer
    #pragma unroll
    for (int it = 0; it < 8; it++) {
        int i = tid + it * 128;
        int row = i >> 4;
        int c4  = (i & 15) << 2;
        float4 q4 = *reinterpret_cast<const float4*>(
            base + (size_t)(qt0 + row) * 3072 + h * 64 + c4);
        q4.x = rtf32(q4.x * 0.125f);
        q4.y = rtf32(q4.y * 0.125f);
        q4.z = rtf32(q4.z * 0.125f);
        q4.w = rtf32(q4.w * 0.125f);
        *reinterpret_cast<float4*>(&sm[OFF_P + row * PS_STRIDE + c4]) = q4;
    }
    __syncthreads();

    // Preload Q fragments into registers (reused across all K tiles)
    uint32_t qa[8][4];
    #pragma unroll
    for (int kc = 0; kc < 8; kc++) {
        qa[kc][0] = __float_as_uint(sm[OFF_P + r0       * PS_STRIDE + kc * 8 + tg]);
        qa[kc][1] = __float_as_uint(sm[OFF_P + (r0 + 8) * PS_STRIDE + kc * 8 + tg]);
        qa[kc][2] = __float_as_uint(sm[OFF_P + r0       * PS_STRIDE + kc * 8 + tg + 4]);
        qa[kc][3] = __float_as_uint(sm[OFF_P + (r0 + 8) * PS_STRIDE + kc * 8 + tg + 4]);
    }

    float m0 = -1e30f, m1 = -1e30f, l0 = 0.f, l1 = 0.f;
    float ob[8][4];
    #pragma unroll
    for (int nt = 0; nt < 8; nt++)
        #pragma unroll
        for (int c = 0; c < 4; c++) ob[nt][c] = 0.f;

    const int nkt = qt + 1;
    for (int kt = 0; kt < nkt; kt++) {
        if (kt + 1 < nkt) {
            issueKV((kt + 1) & 1, kt + 1);
            asm volatile("cp.async.wait_group 1;\n");
        } else {
            asm volatile("cp.async.wait_group 0;\n");
        }
        __syncthreads();

        const float* Ks = sm + (kt & 1) * KS_BUF;
        const float* Vs = sm + OFF_V + (kt & 1) * VS_BUF;

        // S = Q @ K^T
        float sc[8][4];
        #pragma unroll
        for (int nt = 0; nt < 8; nt++)
            #pragma unroll
            for (int c = 0; c < 4; c++) sc[nt][c] = 0.f;

        #pragma unroll
        for (int kc = 0; kc < 8; kc++) {
            #pragma unroll
            for (int nt = 0; nt < 8; nt++) {
                uint32_t b0 = __float_as_uint(Ks[(nt * 8 + g) * KS_STRIDE + kc * 8 + tg]);
                uint32_t b1 = __float_as_uint(Ks[(nt * 8 + g) * KS_STRIDE + kc * 8 + tg + 4]);
                MMA_TF32(sc[nt][0], sc[nt][1], sc[nt][2], sc[nt][3],
                         qa[kc][0], qa[kc][1], qa[kc][2], qa[kc][3], b0, b1);
            }
        }

        // Causal mask (diagonal tile only)
        if (kt == nkt - 1) {
            int qrow0 = qt0 + r0;
            int qrow1 = qrow0 + 8;
            #pragma unroll
            for (int nt = 0; nt < 8; nt++) {
                int kc0 = kt * 64 + nt * 8 + 2 * tg;
                if (kc0     > qrow0) sc[nt][0] = -1e30f;
                if (kc0 + 1 > qrow0) sc[nt][1] = -1e30f;
                if (kc0     > qrow1) sc[nt][2] = -1e30f;
                if (kc0 + 1 > qrow1) sc[nt][3] = -1e30f;
            }
        }

        // Online softmax (rows r0 and r0+8)
        float rm0 = -1e30f, rm1 = -1e30f;
        #pragma unroll
        for (int nt = 0; nt < 8; nt++) {
            rm0 = fmaxf(rm0, fmaxf(sc[nt][0], sc[nt][1]));
            rm1 = fmaxf(rm1, fmaxf(sc[nt][2], sc[nt][3]));
        }
        rm0 = fmaxf(rm0, __shfl_xor_sync(0xffffffff, rm0, 1));
        rm0 = fmaxf(rm0, __shfl_xor_sync(0xffffffff, rm0, 2));
        rm1 = fmaxf(rm1, __shfl_xor_sync(0xffffffff, rm1, 1));
        rm1 = fmaxf(rm1, __shfl_xor_sync(0xffffffff, rm1, 2));
        float mn0 = fmaxf(m0, rm0);
        float mn1 = fmaxf(m1, rm1);

        float rs0 = 0.f, rs1 = 0.f;
        #pragma unroll
        for (int nt = 0; nt < 8; nt++) {
            sc[nt][0] = __expf(sc[nt][0] - mn0);
            sc[nt][1] = __expf(sc[nt][1] - mn0);
            sc[nt][2] = __expf(sc[nt][2] - mn1);
            sc[nt][3] = __expf(sc[nt][3] - mn1);
            rs0 += sc[nt][0] + sc[nt][1];
            rs1 += sc[nt][2] + sc[nt][3];
        }
        rs0 += __shfl_xor_sync(0xffffffff, rs0, 1);
        rs0 += __shfl_xor_sync(0xffffffff, rs0, 2);
        rs1 += __shfl_xor_sync(0xffffffff, rs1, 1);
        rs1 += __shfl_xor_sync(0xffffffff, rs1, 2);

        float scale0 = __expf(m0 - mn0);
        float scale1 = __expf(m1 - mn1);
        l0 = l0 * scale0 + rs0;
        l1 = l1 * scale1 + rs1;
        m0 = mn0; m1 = mn1;
        #pragma unroll
        for (int nt = 0; nt < 8; nt++) {
            ob[nt][0] *= scale0; ob[nt][1] *= scale0;
            ob[nt][2] *= scale1; ob[nt][3] *= scale1;
        }

        // Store P (RNA-rounded) to warp-private smem rows
        __syncwarp();
        #pragma unroll
        for (int nt = 0; nt < 8; nt++) {
            *reinterpret_cast<float2*>(&sm[OFF_P + r0 * PS_STRIDE + nt * 8 + 2 * tg]) =
                make_float2(rtf32(sc[nt][0]), rtf32(sc[nt][1]));
            *reinterpret_cast<float2*>(&sm[OFF_P + (r0 + 8) * PS_STRIDE + nt * 8 + 2 * tg]) =
                make_float2(rtf32(sc[nt][2]), rtf32(sc[nt][3]));
        }
        __syncwarp();

        // O += P @ V
        #pragma unroll
        for (int kc = 0; kc < 8; kc++) {
            uint32_t pa0 = __float_as_uint(sm[OFF_P + r0       * PS_STRIDE + kc * 8 + tg]);
            uint32_t pa1 = __float_as_uint(sm[OFF_P + (r0 + 8) * PS_STRIDE + kc * 8 + tg]);
            uint32_t pa2 = __float_as_uint(sm[OFF_P + r0       * PS_STRIDE + kc * 8 + tg + 4]);
            uint32_t pa3 = __float_as_uint(sm[OFF_P + (r0 + 8) * PS_STRIDE + kc * 8 + tg + 4]);
            #pragma unroll
            for (int nt = 0; nt < 8; nt++) {
                uint32_t vb0 = __float_as_uint(Vs[(kc * 8 + tg)     * VS_STRIDE + nt * 8 + g]);
                uint32_t vb1 = __float_as_uint(Vs[(kc * 8 + tg + 4) * VS_STRIDE + nt * 8 + g]);
                MMA_TF32(ob[nt][0], ob[nt][1], ob[nt][2], ob[nt][3],
                         pa0, pa1, pa2, pa3, vb0, vb1);
            }
        }
        __syncthreads();   // protect K/V buffers before next issue
    }

    // Epilogue: normalize and write
    float inv0 = 1.0f / l0;
    float inv1 = 1.0f / l1;
    size_t row0 = ((size_t)b * TT + qt0 + r0) * EE + h * 64;
    size_t row1 = row0 + 8 * EE;
    #pragma unroll
    for (int nt = 0; nt < 8; nt++) {
        int col = nt * 8 + 2 * tg;
        *reinterpret_cast<float2*>(out + row0 + col) =
            make_float2(ob[nt][0] * inv0, ob[nt][1] * inv0);
        *reinterpret_cast<float2*>(out + row1 + col) =
            make_float2(ob[nt][2] * inv1, ob[nt][3] * inv1);
    }
}

// ---------------------------------------------------------------------------
// Launch
// ---------------------------------------------------------------------------
extern "C" void kernel_launch(void* const* d_in, const int* in_sizes, int n_in,
                              void* d_out, int out_size) {
    const float* x        = (const float*)d_in[0];
    const float* c_attn_w = (const float*)d_in[1];
    const float* c_attn_b = (const float*)d_in[2];
    const float* c_proj_w = (const float*)d_in[3];
    const float* c_proj_b = (const float*)d_in[4];
    const float* mlp_w1   = (const float*)d_in[5];
    const float* mlp_b1   = (const float*)d_in[6];
    const float* mlp_w2   = (const float*)d_in[7];
    const float* mlp_b2   = (const float*)d_in[8];
    const float* ln1_g    = (const float*)d_in[9];
    const float* ln1_b    = (const float*)d_in[10];
    const float* ln2_g    = (const float*)d_in[11];
    const float* ln2_b    = (const float*)d_in[12];
    float* out = (float*)d_out;

    float *ln, *qkv, *att, *x2, *act;
    cudaGetSymbolAddress((void**)&ln,  g_ln);
    cudaGetSymbolAddress((void**)&qkv, g_qkv);
    cudaGetSymbolAddress((void**)&att, g_att);
    cudaGetSymbolAddress((void**)&x2,  g_x2);
    cudaGetSymbolAddress((void**)&act, g_act);

    cudaFuncSetAttribute(mma_gemm<false, false>,
                         cudaFuncAttributeMaxDynamicSharedMemorySize, SMEM_BYTES);
    cudaFuncSetAttribute(mma_gemm<false, true>,
                         cudaFuncAttributeMaxDynamicSharedMemorySize, SMEM_BYTES);
    cudaFuncSetAttribute(mma_gemm<true, false>,
                         cudaFuncAttributeMaxDynamicSharedMemorySize, SMEM_BYTES);
    cudaFuncSetAttribute(attn_mma_kernel,
                         cudaFuncAttributeMaxDynamicSharedMemorySize, ATT_SMEM);

    // 1. LN1
    ln_kernel<<<MM, 256>>>(x, ln1_g, ln1_b, ln);
    // 2. QKV = ln @ c_attn_w + b           [4096, 3072]
    mma_gemm<false, false><<<dim3(3*EE/128, MM/128), 256, SMEM_BYTES>>>(
        ln, c_attn_w, c_attn_b, nullptr, qkv, MM, 3*EE, EE);
    // 3. Attention (tensor-core flash)
    attn_mma_kernel<<<dim3(TT/64, HH, BB), 128, ATT_SMEM>>>(qkv, att);
    // 4. x2 = x + att @ c_proj_w + b       [4096, 1024]
    mma_gemm<false, true><<<dim3(EE/128, MM/128), 256, SMEM_BYTES>>>(
        att, c_proj_w, c_proj_b, x, x2, MM, EE, EE);
    // 5. LN2
    ln_kernel<<<MM, 256>>>(x2, ln2_g, ln2_b, ln);
    // 6. act = gelu(h @ mlp_w1 + b1)       [4096, 4096]
    mma_gemm<true, false><<<dim3(FF/128, MM/128), 256, SMEM_BYTES>>>(
        ln, mlp_w1, mlp_b1, nullptr, act, MM, FF, EE);
    // 7. out = x2 + act @ mlp_w2 + b2      [4096, 1024]
    mma_gemm<false, true><<<dim3(EE/128, MM/128), 256, SMEM_BYTES>>>(
        act, mlp_w2, mlp_b2, x2, out, MM, EE, FF);
}

// round 6
// speedup vs baseline: 4.7975x; 1.1441x over previous
#include <cuda_runtime.h>
#include <math.h>
#include <stdint.h>

// Problem constants
#define BB 2
#define TT 2048
#define EE 1024
#define HH 16
#define DH 64
#define FF 4096
#define MM (BB*TT)   // 4096 rows

// Scratch (device globals: no allocation allowed)
__device__ float g_ln [MM*EE];
__device__ float g_qkv[MM*3*EE];
__device__ float g_att[MM*EE];
__device__ float g_x2 [MM*EE];
__device__ float g_act[(size_t)MM*FF];
__device__ float g_w  [12*1024*1024];   // transposed weights [N][K]

#define WT_ATTN_OFF 0                        // [3072][1024]
#define WT_PROJ_OFF (3*EE*EE)                // [1024][1024]
#define WT_MLP1_OFF (WT_PROJ_OFF + EE*EE)    // [4096][1024]
#define WT_MLP2_OFF (WT_MLP1_OFF + EE*FF)    // [1024][4096]

// ---------------------------------------------------------------------------
// Helpers
// ---------------------------------------------------------------------------
__device__ __forceinline__ float rtf32(float x) {
    uint32_t u;
    asm("cvt.rna.tf32.f32 %0, %1;" : "=r"(u) : "f"(x));
    return __uint_as_float(u);
}

__device__ __forceinline__ void cp16(uint32_t dst, const void* src) {
    asm volatile("cp.async.cg.shared.global [%0], [%1], 16;\n" :: "r"(dst), "l"(src));
}

#define MMA_TF32(d0,d1,d2,d3,a0,a1,a2,a3,b0,b1) \
    asm volatile( \
        "mma.sync.aligned.m16n8k8.row.col.f32.tf32.tf32.f32 " \
        "{%0,%1,%2,%3}, {%4,%5,%6,%7}, {%8,%9}, {%0,%1,%2,%3};" \
        : "+f"(d0), "+f"(d1), "+f"(d2), "+f"(d3) \
        : "r"(a0), "r"(a1), "r"(a2), "r"(a3), "r"(b0), "r"(b1))

#define LDSM_X4(r0,r1,r2,r3,addr) \
    asm volatile("ldmatrix.sync.aligned.m8n8.x4.shared.b16 {%0,%1,%2,%3}, [%4];" \
        : "=r"(r0), "=r"(r1), "=r"(r2), "=r"(r3) : "r"(addr))

// ---------------------------------------------------------------------------
// Weight transpose: in[R][C] -> out[C][R]
// ---------------------------------------------------------------------------
__global__ void transpose_kernel(const float* __restrict__ in,
                                 float* __restrict__ out, int R, int C) {
    __shared__ float tile[32][33];
    int x = blockIdx.x * 32 + threadIdx.x;
    int y0 = blockIdx.y * 32;
    #pragma unroll
    for (int j = threadIdx.y; j < 32; j += 8)
        tile[j][threadIdx.x] = in[(size_t)(y0 + j) * C + x];
    __syncthreads();
    int ox = y0 + threadIdx.x;
    int oy0 = blockIdx.x * 32;
    #pragma unroll
    for (int j = threadIdx.y; j < 32; j += 8)
        out[(size_t)(oy0 + j) * R + ox] = tile[threadIdx.x][j];
}

// ---------------------------------------------------------------------------
// LayerNorm: one block per row of 1024, 256 threads
// ---------------------------------------------------------------------------
__global__ void ln_kernel(const float* __restrict__ x,
                          const float* __restrict__ g,
                          const float* __restrict__ b,
                          float* __restrict__ out) {
    int row = blockIdx.x;
    int tid = threadIdx.x;
    const float4* xr = reinterpret_cast<const float4*>(x + (size_t)row * EE);
    float4 v = xr[tid];
    float s  = v.x + v.y + v.z + v.w;
    float sq = v.x*v.x + v.y*v.y + v.z*v.z + v.w*v.w;
    #pragma unroll
    for (int o = 16; o > 0; o >>= 1) {
        s  += __shfl_xor_sync(0xffffffff, s,  o);
        sq += __shfl_xor_sync(0xffffffff, sq, o);
    }
    __shared__ float rs[8], rq[8], mu_s, rstd_s;
    int warp = tid >> 5, lane = tid & 31;
    if (lane == 0) { rs[warp] = s; rq[warp] = sq; }
    __syncthreads();
    if (tid == 0) {
        float ts = 0.f, tq = 0.f;
        #pragma unroll
        for (int i = 0; i < 8; i++) { ts += rs[i]; tq += rq[i]; }
        float mu  = ts * (1.0f / EE);
        float var = tq * (1.0f / EE) - mu * mu;
        mu_s = mu;
        rstd_s = rsqrtf(var + 1e-5f);
    }
    __syncthreads();
    float mu = mu_s, rstd = rstd_s;
    float4 gv = reinterpret_cast<const float4*>(g)[tid];
    float4 bv = reinterpret_cast<const float4*>(b)[tid];
    float4 o;
    o.x = (v.x - mu) * rstd * gv.x + bv.x;
    o.y = (v.y - mu) * rstd * gv.y + bv.y;
    o.z = (v.z - mu) * rstd * gv.z + bv.z;
    o.w = (v.w - mu) * rstd * gv.w + bv.w;
    reinterpret_cast<float4*>(out + (size_t)row * EE)[tid] = o;
}

__device__ __forceinline__ float gelu_f(float x) {
    const float c = 0.7978845608028654f;
    float x3 = x * x * x;
    return 0.5f * x * (1.0f + tanhf(c * (x + 0.044715f * x3)));
}

// ---------------------------------------------------------------------------
// tf32 tensor-core GEMM via mma.sync, ldmatrix-fed fragments.
// C[M,N] = A[M,K] @ Wt[N,K]^T + bias (+GELU) (+residual)
// CTA 128x128x32, 8 warps (2x4), warp tile 64x32.
// Smem per stage: A[128 rows m][32 k] + B[128 rows n][32 k], 128B rows,
// SW128 swizzle; 3 stages = 96 KB; one __syncthreads per k-iteration.
// ---------------------------------------------------------------------------
#define GSTAGE 32768                       // bytes per stage (A 16K + B 16K)
#define GSMEM_BYTES (3*GSTAGE)             // 98304

template<bool GELU, bool RES>
__global__ void __launch_bounds__(256, 2)
mma_gemm(const float* __restrict__ A, const float* __restrict__ Wt,
         const float* __restrict__ bias, const float* __restrict__ res,
         float* __restrict__ C, int M, int N, int K) {
    extern __shared__ float smf[];
    const uint32_t sm_u = (uint32_t)__cvta_generic_to_shared(smf);

    const int tid  = threadIdx.x;
    const int lane = tid & 31;
    const int warp = tid >> 5;
    const int wm = warp >> 2;     // 0..1
    const int wn = warp & 3;      // 0..3
    const int g  = lane >> 2;
    const int tg = lane & 3;

    const int bm = blockIdx.y, bn = blockIdx.x;
    const float* Ab = A  + (size_t)bm * 128 * K;
    const float* Bb = Wt + (size_t)bn * 128 * K;

    // ldmatrix per-lane addressing
    const int j    = lane & 7;        // row-within-tile supplier
    const int tile = lane >> 3;       // which 8x8 tile this lane feeds
    const uint32_t jm = (uint32_t)(j * 16);           // swizzle mask
    // A tiles: {rows +0/+8} x {chunk +0/+16}
    const uint32_t aRowSel = (uint32_t)((tile & 1) * 8);
    const uint32_t aC16    = (uint32_t)((tile >> 1) * 16);
    // B tiles: {n-block +0/+8} x {chunk +0/+16}
    const uint32_t bRowSel = (uint32_t)((tile >> 1) * 8);
    const uint32_t bC16    = (uint32_t)((tile & 1) * 16);

    uint32_t aRow[4], bRow[2];
    #pragma unroll
    for (int mi = 0; mi < 4; mi++)
        aRow[mi] = (uint32_t)(wm * 64 + mi * 16 + j) * 128 + aRowSel * 128;
    #pragma unroll
    for (int bi = 0; bi < 2; bi++)
        bRow[bi] = 16384u + ((uint32_t)(wn * 32 + bi * 16 + j) + bRowSel) * 128;

    // staging mapping: 1024 cp16 per operand / 256 threads = 4 each
    const int srow = tid >> 3;             // 0..31 (+32p)
    const int sch  = (tid & 7) << 4;       // byte chunk 0..112

    float acc[4][4][4];
    #pragma unroll
    for (int i = 0; i < 4; i++)
        #pragma unroll
        for (int jj = 0; jj < 4; jj++)
            #pragma unroll
            for (int c = 0; c < 4; c++) acc[i][jj][c] = 0.f;

    auto issue = [&](int stage, int kt) {
        uint32_t sA = sm_u + (uint32_t)stage * GSTAGE;
        uint32_t sB = sA + 16384u;
        int kc = kt * 32 + (sch >> 2);
        #pragma unroll
        for (int p = 0; p < 4; p++) {
            int r = srow + p * 32;
            uint32_t dst = (uint32_t)(r * 128) + ((uint32_t)sch ^ ((uint32_t)(r & 7) * 16));
            cp16(sA + dst, Ab + (size_t)r * K + kc);
            cp16(sB + dst, Bb + (size_t)r * K + kc);
        }
        asm volatile("cp.async.commit_group;\n");
    };

    const int KT = K >> 5;
    issue(0, 0);
    issue(1, 1);

    int rbuf = 0, ibuf = 2;
    for (int kt = 0; kt < KT; kt++) {
        if (kt + 1 < KT) {
            asm volatile("cp.async.wait_group 1;\n");
        } else {
            asm volatile("cp.async.wait_group 0;\n");
        }
        __syncthreads();
        if (kt + 2 < KT) {
            issue(ibuf, kt + 2);
            if (++ibuf == 3) ibuf = 0;
        }

        const uint32_t stBase = sm_u + (uint32_t)rbuf * GSTAGE;
        if (++rbuf == 3) rbuf = 0;

        #pragma unroll
        for (int ks = 0; ks < 4; ks++) {
            const uint32_t koffA = ((uint32_t)(ks * 32) + aC16) ^ jm;
            const uint32_t koffB = ((uint32_t)(ks * 32) + bC16) ^ jm;

            uint32_t af[4][4];
            #pragma unroll
            for (int mi = 0; mi < 4; mi++)
                LDSM_X4(af[mi][0], af[mi][1], af[mi][2], af[mi][3],
                        stBase + aRow[mi] + koffA);

            uint32_t bf[4][2];
            LDSM_X4(bf[0][0], bf[0][1], bf[1][0], bf[1][1],
                    stBase + bRow[0] + koffB);
            LDSM_X4(bf[2][0], bf[2][1], bf[3][0], bf[3][1],
                    stBase + bRow[1] + koffB);

            #pragma unroll
            for (int mi = 0; mi < 4; mi++)
                #pragma unroll
                for (int ni = 0; ni < 4; ni++)
                    MMA_TF32(acc[mi][ni][0], acc[mi][ni][1], acc[mi][ni][2], acc[mi][ni][3],
                             af[mi][0], af[mi][1], af[mi][2], af[mi][3],
                             bf[ni][0], bf[ni][1]);
        }
    }

    const int rowBase = bm * 128 + wm * 64;
    const int colBase = bn * 128 + wn * 32;
    #pragma unroll
    for (int mi = 0; mi < 4; mi++) {
        #pragma unroll
        for (int ni = 0; ni < 4; ni++) {
            int col = colBase + ni * 8 + 2 * tg;
            float bb0 = bias[col], bb1 = bias[col + 1];
            int r0 = rowBase + mi * 16 + g;
            int r1 = r0 + 8;
            float v0 = acc[mi][ni][0] + bb0;
            float v1 = acc[mi][ni][1] + bb1;
            float v2 = acc[mi][ni][2] + bb0;
            float v3 = acc[mi][ni][3] + bb1;
            if (GELU) { v0 = gelu_f(v0); v1 = gelu_f(v1); v2 = gelu_f(v2); v3 = gelu_f(v3); }
            if (RES) {
                const float2 rr0 = *reinterpret_cast<const float2*>(res + (size_t)r0 * N + col);
                const float2 rr1 = *reinterpret_cast<const float2*>(res + (size_t)r1 * N + col);
                v0 += rr0.x; v1 += rr0.y; v2 += rr1.x; v3 += rr1.y;
            }
            *reinterpret_cast<float2*>(C + (size_t)r0 * N + col) = make_float2(v0, v1);
            *reinterpret_cast<float2*>(C + (size_t)r1 * N + col) = make_float2(v2, v3);
        }
    }
}

// ---------------------------------------------------------------------------
// Tensor-core flash attention (tf32 mma.sync) — unchanged (~50us)
// ---------------------------------------------------------------------------
#define KS_STRIDE 68
#define VS_STRIDE 72
#define PS_STRIDE 68
#define KS_BUF (64*KS_STRIDE)
#define VS_BUF (64*VS_STRIDE)
#define OFF_V (2*KS_BUF)
#define OFF_P (2*KS_BUF + 2*VS_BUF)
#define ATT_SMEM ((OFF_P + 64*PS_STRIDE)*4)   // 89088 bytes

__global__ void __launch_bounds__(128, 2)
attn_mma_kernel(const float* __restrict__ qkv, float* __restrict__ out) {
    extern __shared__ float sm[];
    uint32_t sm_u = (uint32_t)__cvta_generic_to_shared(sm);

    const int qt  = gridDim.x - 1 - blockIdx.x;
    const int qt0 = qt * 64;
    const int h   = blockIdx.y;
    const int b   = blockIdx.z;
    const int tid = threadIdx.x;
    const int lane = tid & 31;
    const int warp = tid >> 5;
    const int g  = lane >> 2;
    const int tg = lane & 3;
    const int r0 = warp * 16 + g;

    const float* base = qkv + (size_t)b * TT * (3 * EE);

    auto issueKV = [&](int buf, int kt) {
        int krow0 = kt * 64;
        uint32_t sK = sm_u + (uint32_t)(buf * KS_BUF) * 4;
        uint32_t sV = sm_u + (uint32_t)(OFF_V + buf * VS_BUF) * 4;
        #pragma unroll
        for (int it = 0; it < 8; it++) {
            int i = tid + it * 128;
            int row = i >> 4;
            int c4  = (i & 15) << 2;
            const float* src = base + (size_t)(krow0 + row) * 3072 + EE + h * 64 + c4;
            cp16(sK + (uint32_t)(row * KS_STRIDE + c4) * 4, src);
            cp16(sV + (uint32_t)(row * VS_STRIDE + c4) * 4, src + EE);
        }
        asm volatile("cp.async.commit_group;\n");
    };

    issueKV(0, 0);

    #pragma unroll
    for (int it = 0; it < 8; it++) {
        int i = tid + it * 128;
        int row = i >> 4;
        int c4  = (i & 15) << 2;
        float4 q4 = *reinterpret_cast<const float4*>(
            base + (size_t)(qt0 + row) * 3072 + h * 64 + c4);
        q4.x = rtf32(q4.x * 0.125f);
        q4.y = rtf32(q4.y * 0.125f);
        q4.z = rtf32(q4.z * 0.125f);
        q4.w = rtf32(q4.w * 0.125f);
        *reinterpret_cast<float4*>(&sm[OFF_P + row * PS_STRIDE + c4]) = q4;
    }
    __syncthreads();

    uint32_t qa[8][4];
    #pragma unroll
    for (int kc = 0; kc < 8; kc++) {
        qa[kc][0] = __float_as_uint(sm[OFF_P + r0       * PS_STRIDE + kc * 8 + tg]);
        qa[kc][1] = __float_as_uint(sm[OFF_P + (r0 + 8) * PS_STRIDE + kc * 8 + tg]);
        qa[kc][2] = __float_as_uint(sm[OFF_P + r0       * PS_STRIDE + kc * 8 + tg + 4]);
        qa[kc][3] = __float_as_uint(sm[OFF_P + (r0 + 8) * PS_STRIDE + kc * 8 + tg + 4]);
    }

    float m0 = -1e30f, m1 = -1e30f, l0 = 0.f, l1 = 0.f;
    float ob[8][4];
    #pragma unroll
    for (int nt = 0; nt < 8; nt++)
        #pragma unroll
        for (int c = 0; c < 4; c++) ob[nt][c] = 0.f;

    const int nkt = qt + 1;
    for (int kt = 0; kt < nkt; kt++) {
        if (kt + 1 < nkt) {
            issueKV((kt + 1) & 1, kt + 1);
            asm volatile("cp.async.wait_group 1;\n");
        } else {
            asm volatile("cp.async.wait_group 0;\n");
        }
        __syncthreads();

        const float* Ks = sm + (kt & 1) * KS_BUF;
        const float* Vs = sm + OFF_V + (kt & 1) * VS_BUF;

        float sc[8][4];
        #pragma unroll
        for (int nt = 0; nt < 8; nt++)
            #pragma unroll
            for (int c = 0; c < 4; c++) sc[nt][c] = 0.f;

        #pragma unroll
        for (int kc = 0; kc < 8; kc++) {
            #pragma unroll
            for (int nt = 0; nt < 8; nt++) {
                uint32_t b0 = __float_as_uint(Ks[(nt * 8 + g) * KS_STRIDE + kc * 8 + tg]);
                uint32_t b1 = __float_as_uint(Ks[(nt * 8 + g) * KS_STRIDE + kc * 8 + tg + 4]);
                MMA_TF32(sc[nt][0], sc[nt][1], sc[nt][2], sc[nt][3],
                         qa[kc][0], qa[kc][1], qa[kc][2], qa[kc][3], b0, b1);
            }
        }

        if (kt == nkt - 1) {
            int qrow0 = qt0 + r0;
            int qrow1 = qrow0 + 8;
            #pragma unroll
            for (int nt = 0; nt < 8; nt++) {
                int kc0 = kt * 64 + nt * 8 + 2 * tg;
                if (kc0     > qrow0) sc[nt][0] = -1e30f;
                if (kc0 + 1 > qrow0) sc[nt][1] = -1e30f;
                if (kc0     > qrow1) sc[nt][2] = -1e30f;
                if (kc0 + 1 > qrow1) sc[nt][3] = -1e30f;
            }
        }

        float rm0 = -1e30f, rm1 = -1e30f;
        #pragma unroll
        for (int nt = 0; nt < 8; nt++) {
            rm0 = fmaxf(rm0, fmaxf(sc[nt][0], sc[nt][1]));
            rm1 = fmaxf(rm1, fmaxf(sc[nt][2], sc[nt][3]));
        }
        rm0 = fmaxf(rm0, __shfl_xor_sync(0xffffffff, rm0, 1));
        rm0 = fmaxf(rm0, __shfl_xor_sync(0xffffffff, rm0, 2));
        rm1 = fmaxf(rm1, __shfl_xor_sync(0xffffffff, rm1, 1));
        rm1 = fmaxf(rm1, __shfl_xor_sync(0xffffffff, rm1, 2));
        float mn0 = fmaxf(m0, rm0);
        float mn1 = fmaxf(m1, rm1);

        float rs0 = 0.f, rs1 = 0.f;
        #pragma unroll
        for (int nt = 0; nt < 8; nt++) {
            sc[nt][0] = __expf(sc[nt][0] - mn0);
            sc[nt][1] = __expf(sc[nt][1] - mn0);
            sc[nt][2] = __expf(sc[nt][2] - mn1);
            sc[nt][3] = __expf(sc[nt][3] - mn1);
            rs0 += sc[nt][0] + sc[nt][1];
            rs1 += sc[nt][2] + sc[nt][3];
        }
        rs0 += __shfl_xor_sync(0xffffffff, rs0, 1);
        rs0 += __shfl_xor_sync(0xffffffff, rs0, 2);
        rs1 += __shfl_xor_sync(0xffffffff, rs1, 1);
        rs1 += __shfl_xor_sync(0xffffffff, rs1, 2);

        float scale0 = __expf(m0 - mn0);
        float scale1 = __expf(m1 - mn1);
        l0 = l0 * scale0 + rs0;
        l1 = l1 * scale1 + rs1;
        m0 = mn0; m1 = mn1;
        #pragma unroll
        for (int nt = 0; nt < 8; nt++) {
            ob[nt][0] *= scale0; ob[nt][1] *= scale0;
            ob[nt][2] *= scale1; ob[nt][3] *= scale1;
        }

        __syncwarp();
        #pragma unroll
        for (int nt = 0; nt < 8; nt++) {
            *reinterpret_cast<float2*>(&sm[OFF_P + r0 * PS_STRIDE + nt * 8 + 2 * tg]) =
                make_float2(rtf32(sc[nt][0]), rtf32(sc[nt][1]));
            *reinterpret_cast<float2*>(&sm[OFF_P + (r0 + 8) * PS_STRIDE + nt * 8 + 2 * tg]) =
                make_float2(rtf32(sc[nt][2]), rtf32(sc[nt][3]));
        }
        __syncwarp();

        #pragma unroll
        for (int kc = 0; kc < 8; kc++) {
            uint32_t pa0 = __float_as_uint(sm[OFF_P + r0       * PS_STRIDE + kc * 8 + tg]);
            uint32_t pa1 = __float_as_uint(sm[OFF_P + (r0 + 8) * PS_STRIDE + kc * 8 + tg]);
            uint32_t pa2 = __float_as_uint(sm[OFF_P + r0       * PS_STRIDE + kc * 8 + tg + 4]);
            uint32_t pa3 = __float_as_uint(sm[OFF_P + (r0 + 8) * PS_STRIDE + kc * 8 + tg + 4]);
            #pragma unroll
            for (int nt = 0; nt < 8; nt++) {
                uint32_t vb0 = __float_as_uint(Vs[(kc * 8 + tg)     * VS_STRIDE + nt * 8 + g]);
                uint32_t vb1 = __float_as_uint(Vs[(kc * 8 + tg + 4) * VS_STRIDE + nt * 8 + g]);
                MMA_TF32(ob[nt][0], ob[nt][1], ob[nt][2], ob[nt][3],
                         pa0, pa1, pa2, pa3, vb0, vb1);
            }
        }
        __syncthreads();
    }

    float inv0 = 1.0f / l0;
    float inv1 = 1.0f / l1;
    size_t row0 = ((size_t)b * TT + qt0 + r0) * EE + h * 64;
    size_t row1 = row0 + 8 * EE;
    #pragma unroll
    for (int nt = 0; nt < 8; nt++) {
        int col = nt * 8 + 2 * tg;
        *reinterpret_cast<float2*>(out + row0 + col) =
            make_float2(ob[nt][0] * inv0, ob[nt][1] * inv0);
        *reinterpret_cast<float2*>(out + row1 + col) =
            make_float2(ob[nt][2] * inv1, ob[nt][3] * inv1);
    }
}

// ---------------------------------------------------------------------------
// Launch
// ---------------------------------------------------------------------------
extern "C" void kernel_launch(void* const* d_in, const int* in_sizes, int n_in,
                              void* d_out, int out_size) {
    const float* x        = (const float*)d_in[0];
    const float* c_attn_w = (const float*)d_in[1];
    const float* c_attn_b = (const float*)d_in[2];
    const float* c_proj_w = (const float*)d_in[3];
    const float* c_proj_b = (const float*)d_in[4];
    const float* mlp_w1   = (const float*)d_in[5];
    const float* mlp_b1   = (const float*)d_in[6];
    const float* mlp_w2   = (const float*)d_in[7];
    const float* mlp_b2   = (const float*)d_in[8];
    const float* ln1_g    = (const float*)d_in[9];
    const float* ln1_b    = (const float*)d_in[10];
    const float* ln2_g    = (const float*)d_in[11];
    const float* ln2_b    = (const float*)d_in[12];
    float* out = (float*)d_out;

    float *ln, *qkv, *att, *x2, *act, *w;
    cudaGetSymbolAddress((void**)&ln,  g_ln);
    cudaGetSymbolAddress((void**)&qkv, g_qkv);
    cudaGetSymbolAddress((void**)&att, g_att);
    cudaGetSymbolAddress((void**)&x2,  g_x2);
    cudaGetSymbolAddress((void**)&act, g_act);
    cudaGetSymbolAddress((void**)&w,   g_w);

    cudaFuncSetAttribute(mma_gemm<false, false>,
                         cudaFuncAttributeMaxDynamicSharedMemorySize, GSMEM_BYTES);
    cudaFuncSetAttribute(mma_gemm<false, true>,
                         cudaFuncAttributeMaxDynamicSharedMemorySize, GSMEM_BYTES);
    cudaFuncSetAttribute(mma_gemm<true, false>,
                         cudaFuncAttributeMaxDynamicSharedMemorySize, GSMEM_BYTES);
    cudaFuncSetAttribute(attn_mma_kernel,
                         cudaFuncAttributeMaxDynamicSharedMemorySize, ATT_SMEM);

    // 0. Transpose weights: W[K][N] -> Wt[N][K]
    transpose_kernel<<<dim3(3*EE/32, EE/32), dim3(32, 8)>>>(c_attn_w, w + WT_ATTN_OFF, EE, 3*EE);
    transpose_kernel<<<dim3(EE/32,   EE/32), dim3(32, 8)>>>(c_proj_w, w + WT_PROJ_OFF, EE, EE);
    transpose_kernel<<<dim3(FF/32,   EE/32), dim3(32, 8)>>>(mlp_w1,   w + WT_MLP1_OFF, EE, FF);
    transpose_kernel<<<dim3(EE/32,   FF/32), dim3(32, 8)>>>(mlp_w2,   w + WT_MLP2_OFF, FF, EE);

    // 1. LN1
    ln_kernel<<<MM, 256>>>(x, ln1_g, ln1_b, ln);
    // 2. QKV = ln @ c_attn_w + b           [4096, 3072]
    mma_gemm<false, false><<<dim3(3*EE/128, MM/128), 256, GSMEM_BYTES>>>(
        ln, w + WT_ATTN_OFF, c_attn_b, nullptr, qkv, MM, 3*EE, EE);
    // 3. Attention
    attn_mma_kernel<<<dim3(TT/64, HH, BB), 128, ATT_SMEM>>>(qkv, att);
    // 4. x2 = x + att @ c_proj_w + b       [4096, 1024]
    mma_gemm<false, true><<<dim3(EE/128, MM/128), 256, GSMEM_BYTES>>>(
        att, w + WT_PROJ_OFF, c_proj_b, x, x2, MM, EE, EE);
    // 5. LN2
    ln_kernel<<<MM, 256>>>(x2, ln2_g, ln2_b, ln);
    // 6. act = gelu(h @ mlp_w1 + b1)       [4096, 4096]
    mma_gemm<true, false><<<dim3(FF/128, MM/128), 256, GSMEM_BYTES>>>(
        ln, w + WT_MLP1_OFF, mlp_b1, nullptr, act, MM, FF, EE);
    // 7. out = x2 + act @ mlp_w2 + b2      [4096, 1024]
    mma_gemm<false, true><<<dim3(EE/128, MM/128), 256, GSMEM_BYTES>>>(
        act, w + WT_MLP2_OFF, mlp_b2, x2, out, MM, EE, FF);
}

// round 7
// speedup vs baseline: 7.0094x; 1.4611x over previous
#include <cuda_runtime.h>
#include <cuda_fp16.h>
#include <math.h>
#include <stdint.h>

// Problem constants
#define BB 2
#define TT 2048
#define EE 1024
#define HH 16
#define DH 64
#define FF 4096
#define MM (BB*TT)   // 4096 rows

// Scratch (device globals: no allocation allowed)
__device__ float g_ln [MM*EE];      // used as __half (half the space)
__device__ float g_qkv[MM*3*EE];    // fp32 (attention input)
__device__ float g_att[MM*EE];      // used as __half
__device__ float g_x2 [MM*EE];      // fp32
__device__ float g_act[(size_t)MM*FF]; // used as __half
__device__ float g_w  [6*1024*1024];   // fp16 transposed weights (12M halves)

#define WT_ATTN_OFF 0                        // [3072][1024]
#define WT_PROJ_OFF (3*EE*EE)                // [1024][1024]
#define WT_MLP1_OFF (WT_PROJ_OFF + EE*EE)    // [4096][1024]
#define WT_MLP2_OFF (WT_MLP1_OFF + EE*FF)    // [1024][4096]

// ---------------------------------------------------------------------------
// Helpers
// ---------------------------------------------------------------------------
__device__ __forceinline__ float rtf32(float x) {
    uint32_t u;
    asm("cvt.rna.tf32.f32 %0, %1;" : "=r"(u) : "f"(x));
    return __uint_as_float(u);
}

__device__ __forceinline__ void cp16(uint32_t dst, const void* src) {
    asm volatile("cp.async.cg.shared.global [%0], [%1], 16;\n" :: "r"(dst), "l"(src));
}

#define MMA_F16(d0,d1,d2,d3,a0,a1,a2,a3,b0,b1) \
    asm volatile( \
        "mma.sync.aligned.m16n8k16.row.col.f32.f16.f16.f32 " \
        "{%0,%1,%2,%3}, {%4,%5,%6,%7}, {%8,%9}, {%0,%1,%2,%3};" \
        : "+f"(d0), "+f"(d1), "+f"(d2), "+f"(d3) \
        : "r"(a0), "r"(a1), "r"(a2), "r"(a3), "r"(b0), "r"(b1))

#define MMA_TF32(d0,d1,d2,d3,a0,a1,a2,a3,b0,b1) \
    asm volatile( \
        "mma.sync.aligned.m16n8k8.row.col.f32.tf32.tf32.f32 " \
        "{%0,%1,%2,%3}, {%4,%5,%6,%7}, {%8,%9}, {%0,%1,%2,%3};" \
        : "+f"(d0), "+f"(d1), "+f"(d2), "+f"(d3) \
        : "r"(a0), "r"(a1), "r"(a2), "r"(a3), "r"(b0), "r"(b1))

#define LDSM_X4(r0,r1,r2,r3,addr) \
    asm volatile("ldmatrix.sync.aligned.m8n8.x4.shared.b16 {%0,%1,%2,%3}, [%4];" \
        : "=r"(r0), "=r"(r1), "=r"(r2), "=r"(r3) : "r"(addr))

// ---------------------------------------------------------------------------
// Weight transpose + fp16 convert: in[R][C] fp32 -> out[C][R] fp16
// ---------------------------------------------------------------------------
__global__ void transpose_h_kernel(const float* __restrict__ in,
                                   __half* __restrict__ out, int R, int C) {
    __shared__ float tile[32][33];
    int x = blockIdx.x * 32 + threadIdx.x;
    int y0 = blockIdx.y * 32;
    #pragma unroll
    for (int j = threadIdx.y; j < 32; j += 8)
        tile[j][threadIdx.x] = in[(size_t)(y0 + j) * C + x];
    __syncthreads();
    int ox = y0 + threadIdx.x;
    int oy0 = blockIdx.x * 32;
    #pragma unroll
    for (int j = threadIdx.y; j < 32; j += 8)
        out[(size_t)(oy0 + j) * R + ox] = __float2half_rn(tile[threadIdx.x][j]);
}

// ---------------------------------------------------------------------------
// LayerNorm: one block per row of 1024, 256 threads, fp16 output
// ---------------------------------------------------------------------------
__global__ void ln_kernel(const float* __restrict__ x,
                          const float* __restrict__ g,
                          const float* __restrict__ b,
                          __half* __restrict__ out) {
    int row = blockIdx.x;
    int tid = threadIdx.x;
    const float4* xr = reinterpret_cast<const float4*>(x + (size_t)row * EE);
    float4 v = xr[tid];
    float s  = v.x + v.y + v.z + v.w;
    float sq = v.x*v.x + v.y*v.y + v.z*v.z + v.w*v.w;
    #pragma unroll
    for (int o = 16; o > 0; o >>= 1) {
        s  += __shfl_xor_sync(0xffffffff, s,  o);
        sq += __shfl_xor_sync(0xffffffff, sq, o);
    }
    __shared__ float rs[8], rq[8], mu_s, rstd_s;
    int warp = tid >> 5, lane = tid & 31;
    if (lane == 0) { rs[warp] = s; rq[warp] = sq; }
    __syncthreads();
    if (tid == 0) {
        float ts = 0.f, tq = 0.f;
        #pragma unroll
        for (int i = 0; i < 8; i++) { ts += rs[i]; tq += rq[i]; }
        float mu  = ts * (1.0f / EE);
        float var = tq * (1.0f / EE) - mu * mu;
        mu_s = mu;
        rstd_s = rsqrtf(var + 1e-5f);
    }
    __syncthreads();
    float mu = mu_s, rstd = rstd_s;
    float4 gv = reinterpret_cast<const float4*>(g)[tid];
    float4 bv = reinterpret_cast<const float4*>(b)[tid];
    __half2 h0 = __floats2half2_rn((v.x - mu) * rstd * gv.x + bv.x,
                                   (v.y - mu) * rstd * gv.y + bv.y);
    __half2 h1 = __floats2half2_rn((v.z - mu) * rstd * gv.z + bv.z,
                                   (v.w - mu) * rstd * gv.w + bv.w);
    __half2* op = reinterpret_cast<__half2*>(out + (size_t)row * EE);
    op[tid * 2]     = h0;
    op[tid * 2 + 1] = h1;
}

__device__ __forceinline__ float gelu_f(float x) {
    const float c = 0.7978845608028654f;
    float x3 = x * x * x;
    return 0.5f * x * (1.0f + tanhf(c * (x + 0.044715f * x3)));
}

// ---------------------------------------------------------------------------
// fp16 tensor-core GEMM via mma.m16n8k16, ldmatrix-fed, fp32 accumulate.
// C[M,N] = A[M,K] @ Wt[N,K]^T + bias (+GELU) (+residual) (-> fp32 or fp16)
// CTA 128x128x64, 8 warps (2x4), warp tile 64x32.
// Smem per stage: A[128][64 halves] + B[128][64 halves], 128B rows, SW128;
// 3 stages = 96 KB; one __syncthreads per k-iteration.
// ---------------------------------------------------------------------------
#define GSTAGE 32768                       // bytes per stage (A 16K + B 16K)
#define GSMEM_BYTES (3*GSTAGE)             // 98304

template<bool GELU, bool RES, bool OUTH>
__global__ void __launch_bounds__(256, 2)
mma_gemm(const __half* __restrict__ A, const __half* __restrict__ Wt,
         const float* __restrict__ bias, const float* __restrict__ res,
         void* __restrict__ Cv, int M, int N, int K) {
    extern __shared__ float smf[];
    const uint32_t sm_u = (uint32_t)__cvta_generic_to_shared(smf);

    const int tid  = threadIdx.x;
    const int lane = tid & 31;
    const int warp = tid >> 5;
    const int wm = warp >> 2;     // 0..1
    const int wn = warp & 3;      // 0..3
    const int g  = lane >> 2;
    const int tg = lane & 3;

    const int bm = blockIdx.y, bn = blockIdx.x;
    const __half* Ab = A  + (size_t)bm * 128 * K;
    const __half* Bb = Wt + (size_t)bn * 128 * K;

    // ldmatrix per-lane addressing
    const int j    = lane & 7;
    const int tile = lane >> 3;
    const uint32_t jm = (uint32_t)(j * 16);
    // A tiles: {rows +0/+8} x {k-chunk +0/+16B}
    const uint32_t aRowSel = (uint32_t)((tile & 1) * 8);
    const uint32_t aC16    = (uint32_t)((tile >> 1) * 16);
    // B tiles: {n +0/+8} x {k-chunk +0/+16B}
    const uint32_t bRowSel = (uint32_t)((tile >> 1) * 8);
    const uint32_t bC16    = (uint32_t)((tile & 1) * 16);

    uint32_t aRow[4], bRow[2];
    #pragma unroll
    for (int mi = 0; mi < 4; mi++)
        aRow[mi] = ((uint32_t)(wm * 64 + mi * 16 + j) + aRowSel) * 128;
    #pragma unroll
    for (int bi = 0; bi < 2; bi++)
        bRow[bi] = 16384u + ((uint32_t)(wn * 32 + bi * 16 + j) + bRowSel) * 128;

    // staging: 128 rows x 8 chunks(16B) per operand = 1024 cp16 / 256 thr = 4
    const int srow = tid >> 3;
    const int sch  = (tid & 7) << 4;       // byte chunk 0..112 (= 8 halves)

    float acc[4][4][4];
    #pragma unroll
    for (int i = 0; i < 4; i++)
        #pragma unroll
        for (int jj = 0; jj < 4; jj++)
            #pragma unroll
            for (int c = 0; c < 4; c++) acc[i][jj][c] = 0.f;

    auto issue = [&](int stage, int kt) {
        uint32_t sA = sm_u + (uint32_t)stage * GSTAGE;
        uint32_t sB = sA + 16384u;
        int kc = kt * 64 + (sch >> 1);     // half index
        #pragma unroll
        for (int p = 0; p < 4; p++) {
            int r = srow + p * 32;
            uint32_t dst = (uint32_t)(r * 128) + ((uint32_t)sch ^ ((uint32_t)(r & 7) * 16));
            cp16(sA + dst, Ab + (size_t)r * K + kc);
            cp16(sB + dst, Bb + (size_t)r * K + kc);
        }
        asm volatile("cp.async.commit_group;\n");
    };

    const int KT = K >> 6;
    issue(0, 0);
    issue(1, 1);

    int rbuf = 0, ibuf = 2;
    for (int kt = 0; kt < KT; kt++) {
        if (kt + 1 < KT) {
            asm volatile("cp.async.wait_group 1;\n");
        } else {
            asm volatile("cp.async.wait_group 0;\n");
        }
        __syncthreads();
        if (kt + 2 < KT) {
            issue(ibuf, kt + 2);
            if (++ibuf == 3) ibuf = 0;
        }

        const uint32_t stBase = sm_u + (uint32_t)rbuf * GSTAGE;
        if (++rbuf == 3) rbuf = 0;

        #pragma unroll
        for (int ks = 0; ks < 4; ks++) {     // 4 x k16 steps per 64-K tile
            const uint32_t koffA = ((uint32_t)(ks * 32) + aC16) ^ jm;
            const uint32_t koffB = ((uint32_t)(ks * 32) + bC16) ^ jm;

            uint32_t af[4][4];
            #pragma unroll
            for (int mi = 0; mi < 4; mi++)
                LDSM_X4(af[mi][0], af[mi][1], af[mi][2], af[mi][3],
                        stBase + aRow[mi] + koffA);

            uint32_t bf[4][2];
            LDSM_X4(bf[0][0], bf[0][1], bf[1][0], bf[1][1],
                    stBase + bRow[0] + koffB);
            LDSM_X4(bf[2][0], bf[2][1], bf[3][0], bf[3][1],
                    stBase + bRow[1] + koffB);

            #pragma unroll
            for (int mi = 0; mi < 4; mi++)
                #pragma unroll
                for (int ni = 0; ni < 4; ni++)
                    MMA_F16(acc[mi][ni][0], acc[mi][ni][1], acc[mi][ni][2], acc[mi][ni][3],
                            af[mi][0], af[mi][1], af[mi][2], af[mi][3],
                            bf[ni][0], bf[ni][1]);
        }
    }

    const int rowBase = bm * 128 + wm * 64;
    const int colBase = bn * 128 + wn * 32;
    float* Cf = (float*)Cv;
    __half* Ch = (__half*)Cv;
    #pragma unroll
    for (int mi = 0; mi < 4; mi++) {
        #pragma unroll
        for (int ni = 0; ni < 4; ni++) {
            int col = colBase + ni * 8 + 2 * tg;
            float bb0 = bias[col], bb1 = bias[col + 1];
            int r0 = rowBase + mi * 16 + g;
            int r1 = r0 + 8;
            float v0 = acc[mi][ni][0] + bb0;
            float v1 = acc[mi][ni][1] + bb1;
            float v2 = acc[mi][ni][2] + bb0;
            float v3 = acc[mi][ni][3] + bb1;
            if (GELU) { v0 = gelu_f(v0); v1 = gelu_f(v1); v2 = gelu_f(v2); v3 = gelu_f(v3); }
            if (RES) {
                const float2 rr0 = *reinterpret_cast<const float2*>(res + (size_t)r0 * N + col);
                const float2 rr1 = *reinterpret_cast<const float2*>(res + (size_t)r1 * N + col);
                v0 += rr0.x; v1 += rr0.y; v2 += rr1.x; v3 += rr1.y;
            }
            if (OUTH) {
                *reinterpret_cast<__half2*>(Ch + (size_t)r0 * N + col) = __floats2half2_rn(v0, v1);
                *reinterpret_cast<__half2*>(Ch + (size_t)r1 * N + col) = __floats2half2_rn(v2, v3);
            } else {
                *reinterpret_cast<float2*>(Cf + (size_t)r0 * N + col) = make_float2(v0, v1);
                *reinterpret_cast<float2*>(Cf + (size_t)r1 * N + col) = make_float2(v2, v3);
            }
        }
    }
}

// ---------------------------------------------------------------------------
// Tensor-core flash attention (tf32 mma.sync internally, fp16 output).
// ---------------------------------------------------------------------------
#define KS_STRIDE 68
#define VS_STRIDE 72
#define PS_STRIDE 68
#define KS_BUF (64*KS_STRIDE)
#define VS_BUF (64*VS_STRIDE)
#define OFF_V (2*KS_BUF)
#define OFF_P (2*KS_BUF + 2*VS_BUF)
#define ATT_SMEM ((OFF_P + 64*PS_STRIDE)*4)   // 89088 bytes

__global__ void __launch_bounds__(128, 2)
attn_mma_kernel(const float* __restrict__ qkv, __half* __restrict__ out) {
    extern __shared__ float sm[];
    uint32_t sm_u = (uint32_t)__cvta_generic_to_shared(sm);

    const int qt  = gridDim.x - 1 - blockIdx.x;
    const int qt0 = qt * 64;
    const int h   = blockIdx.y;
    const int b   = blockIdx.z;
    const int tid = threadIdx.x;
    const int lane = tid & 31;
    const int warp = tid >> 5;
    const int g  = lane >> 2;
    const int tg = lane & 3;
    const int r0 = warp * 16 + g;

    const float* base = qkv + (size_t)b * TT * (3 * EE);

    auto issueKV = [&](int buf, int kt) {
        int krow0 = kt * 64;
        uint32_t sK = sm_u + (uint32_t)(buf * KS_BUF) * 4;
        uint32_t sV = sm_u + (uint32_t)(OFF_V + buf * VS_BUF) * 4;
        #pragma unroll
        for (int it = 0; it < 8; it++) {
            int i = tid + it * 128;
            int row = i >> 4;
            int c4  = (i & 15) << 2;
            const float* src = base + (size_t)(krow0 + row) * 3072 + EE + h * 64 + c4;
            cp16(sK + (uint32_t)(row * KS_STRIDE + c4) * 4, src);
            cp16(sV + (uint32_t)(row * VS_STRIDE + c4) * 4, src + EE);
        }
        asm volatile("cp.async.commit_group;\n");
    };

    issueKV(0, 0);

    #pragma unroll
    for (int it = 0; it < 8; it++) {
        int i = tid + it * 128;
        int row = i >> 4;
        int c4  = (i & 15) << 2;
        float4 q4 = *reinterpret_cast<const float4*>(
            base + (size_t)(qt0 + row) * 3072 + h * 64 + c4);
        q4.x = rtf32(q4.x * 0.125f);
        q4.y = rtf32(q4.y * 0.125f);
        q4.z = rtf32(q4.z * 0.125f);
        q4.w = rtf32(q4.w * 0.125f);
        *reinterpret_cast<float4*>(&sm[OFF_P + row * PS_STRIDE + c4]) = q4;
    }
    __syncthreads();

    uint32_t qa[8][4];
    #pragma unroll
    for (int kc = 0; kc < 8; kc++) {
        qa[kc][0] = __float_as_uint(sm[OFF_P + r0       * PS_STRIDE + kc * 8 + tg]);
        qa[kc][1] = __float_as_uint(sm[OFF_P + (r0 + 8) * PS_STRIDE + kc * 8 + tg]);
        qa[kc][2] = __float_as_uint(sm[OFF_P + r0       * PS_STRIDE + kc * 8 + tg + 4]);
        qa[kc][3] = __float_as_uint(sm[OFF_P + (r0 + 8) * PS_STRIDE + kc * 8 + tg + 4]);
    }

    float m0 = -1e30f, m1 = -1e30f, l0 = 0.f, l1 = 0.f;
    float ob[8][4];
    #pragma unroll
    for (int nt = 0; nt < 8; nt++)
        #pragma unroll
        for (int c = 0; c < 4; c++) ob[nt][c] = 0.f;

    const int nkt = qt + 1;
    for (int kt = 0; kt < nkt; kt++) {
        if (kt + 1 < nkt) {
            issueKV((kt + 1) & 1, kt + 1);
            asm volatile("cp.async.wait_group 1;\n");
        } else {
            asm volatile("cp.async.wait_group 0;\n");
        }
        __syncthreads();

        const float* Ks = sm + (kt & 1) * KS_BUF;
        const float* Vs = sm + OFF_V + (kt & 1) * VS_BUF;

        float sc[8][4];
        #pragma unroll
        for (int nt = 0; nt < 8; nt++)
            #pragma unroll
            for (int c = 0; c < 4; c++) sc[nt][c] = 0.f;

        #pragma unroll
        for (int kc = 0; kc < 8; kc++) {
            #pragma unroll
            for (int nt = 0; nt < 8; nt++) {
                uint32_t b0 = __float_as_uint(Ks[(nt * 8 + g) * KS_STRIDE + kc * 8 + tg]);
                uint32_t b1 = __float_as_uint(Ks[(nt * 8 + g) * KS_STRIDE + kc * 8 + tg + 4]);
                MMA_TF32(sc[nt][0], sc[nt][1], sc[nt][2], sc[nt][3],
                         qa[kc][0], qa[kc][1], qa[kc][2], qa[kc][3], b0, b1);
            }
        }

        if (kt == nkt - 1) {
            int qrow0 = qt0 + r0;
            int qrow1 = qrow0 + 8;
            #pragma unroll
            for (int nt = 0; nt < 8; nt++) {
                int kc0 = kt * 64 + nt * 8 + 2 * tg;
                if (kc0     > qrow0) sc[nt][0] = -1e30f;
                if (kc0 + 1 > qrow0) sc[nt][1] = -1e30f;
                if (kc0     > qrow1) sc[nt][2] = -1e30f;
                if (kc0 + 1 > qrow1) sc[nt][3] = -1e30f;
            }
        }

        float rm0 = -1e30f, rm1 = -1e30f;
        #pragma unroll
        for (int nt = 0; nt < 8; nt++) {
            rm0 = fmaxf(rm0, fmaxf(sc[nt][0], sc[nt][1]));
            rm1 = fmaxf(rm1, fmaxf(sc[nt][2], sc[nt][3]));
        }
        rm0 = fmaxf(rm0, __shfl_xor_sync(0xffffffff, rm0, 1));
        rm0 = fmaxf(rm0, __shfl_xor_sync(0xffffffff, rm0, 2));
        rm1 = fmaxf(rm1, __shfl_xor_sync(0xffffffff, rm1, 1));
        rm1 = fmaxf(rm1, __shfl_xor_sync(0xffffffff, rm1, 2));
        float mn0 = fmaxf(m0, rm0);
        float mn1 = fmaxf(m1, rm1);

        float rs0 = 0.f, rs1 = 0.f;
        #pragma unroll
        for (int nt = 0; nt < 8; nt++) {
            sc[nt][0] = __expf(sc[nt][0] - mn0);
            sc[nt][1] = __expf(sc[nt][1] - mn0);
            sc[nt][2] = __expf(sc[nt][2] - mn1);
            sc[nt][3] = __expf(sc[nt][3] - mn1);
            rs0 += sc[nt][0] + sc[nt][1];
            rs1 += sc[nt][2] + sc[nt][3];
        }
        rs0 += __shfl_xor_sync(0xffffffff, rs0, 1);
        rs0 += __shfl_xor_sync(0xffffffff, rs0, 2);
        rs1 += __shfl_xor_sync(0xffffffff, rs1, 1);
        rs1 += __shfl_xor_sync(0xffffffff, rs1, 2);

        float scale0 = __expf(m0 - mn0);
        float scale1 = __expf(m1 - mn1);
        l0 = l0 * scale0 + rs0;
        l1 = l1 * scale1 + rs1;
        m0 = mn0; m1 = mn1;
        #pragma unroll
        for (int nt = 0; nt < 8; nt++) {
            ob[nt][0] *= scale0; ob[nt][1] *= scale0;
            ob[nt][2] *= scale1; ob[nt][3] *= scale1;
        }

        __syncwarp();
        #pragma unroll
        for (int nt = 0; nt < 8; nt++) {
            *reinterpret_cast<float2*>(&sm[OFF_P + r0 * PS_STRIDE + nt * 8 + 2 * tg]) =
                make_float2(rtf32(sc[nt][0]), rtf32(sc[nt][1]));
            *reinterpret_cast<float2*>(&sm[OFF_P + (r0 + 8) * PS_STRIDE + nt * 8 + 2 * tg]) =
                make_float2(rtf32(sc[nt][2]), rtf32(sc[nt][3]));
        }
        __syncwarp();

        #pragma unroll
        for (int kc = 0; kc < 8; kc++) {
            uint32_t pa0 = __float_as_uint(sm[OFF_P + r0       * PS_STRIDE + kc * 8 + tg]);
            uint32_t pa1 = __float_as_uint(sm[OFF_P + (r0 + 8) * PS_STRIDE + kc * 8 + tg]);
            uint32_t pa2 = __float_as_uint(sm[OFF_P + r0       * PS_STRIDE + kc * 8 + tg + 4]);
            uint32_t pa3 = __float_as_uint(sm[OFF_P + (r0 + 8) * PS_STRIDE + kc * 8 + tg + 4]);
            #pragma unroll
            for (int nt = 0; nt < 8; nt++) {
                uint32_t vb0 = __float_as_uint(Vs[(kc * 8 + tg)     * VS_STRIDE + nt * 8 + g]);
                uint32_t vb1 = __float_as_uint(Vs[(kc * 8 + tg + 4) * VS_STRIDE + nt * 8 + g]);
                MMA_TF32(ob[nt][0], ob[nt][1], ob[nt][2], ob[nt][3],
                         pa0, pa1, pa2, pa3, vb0, vb1);
            }
        }
        __syncthreads();
    }

    float inv0 = 1.0f / l0;
    float inv1 = 1.0f / l1;
    size_t row0 = ((size_t)b * TT + qt0 + r0) * EE + h * 64;
    size_t row1 = row0 + 8 * EE;
    #pragma unroll
    for (int nt = 0; nt < 8; nt++) {
        int col = nt * 8 + 2 * tg;
        *reinterpret_cast<__half2*>(out + row0 + col) =
            __floats2half2_rn(ob[nt][0] * inv0, ob[nt][1] * inv0);
        *reinterpret_cast<__half2*>(out + row1 + col) =
            __floats2half2_rn(ob[nt][2] * inv1, ob[nt][3] * inv1);
    }
}

// ---------------------------------------------------------------------------
// Launch
// ---------------------------------------------------------------------------
extern "C" void kernel_launch(void* const* d_in, const int* in_sizes, int n_in,
                              void* d_out, int out_size) {
    const float* x        = (const float*)d_in[0];
    const float* c_attn_w = (const float*)d_in[1];
    const float* c_attn_b = (const float*)d_in[2];
    const float* c_proj_w = (const float*)d_in[3];
    const float* c_proj_b = (const float*)d_in[4];
    const float* mlp_w1   = (const float*)d_in[5];
    const float* mlp_b1   = (const float*)d_in[6];
    const float* mlp_w2   = (const float*)d_in[7];
    const float* mlp_b2   = (const float*)d_in[8];
    const float* ln1_g    = (const float*)d_in[9];
    const float* ln1_b    = (const float*)d_in[10];
    const float* ln2_g    = (const float*)d_in[11];
    const float* ln2_b    = (const float*)d_in[12];
    float* out = (float*)d_out;

    float *lnf, *qkv, *attf, *x2, *actf, *wf;
    cudaGetSymbolAddress((void**)&lnf,  g_ln);
    cudaGetSymbolAddress((void**)&qkv,  g_qkv);
    cudaGetSymbolAddress((void**)&attf, g_att);
    cudaGetSymbolAddress((void**)&x2,   g_x2);
    cudaGetSymbolAddress((void**)&actf, g_act);
    cudaGetSymbolAddress((void**)&wf,   g_w);
    __half* ln  = (__half*)lnf;
    __half* att = (__half*)attf;
    __half* act = (__half*)actf;
    __half* w   = (__half*)wf;

    cudaFuncSetAttribute(mma_gemm<false, false, false>,
                         cudaFuncAttributeMaxDynamicSharedMemorySize, GSMEM_BYTES);
    cudaFuncSetAttribute(mma_gemm<false, true, false>,
                         cudaFuncAttributeMaxDynamicSharedMemorySize, GSMEM_BYTES);
    cudaFuncSetAttribute(mma_gemm<true, false, true>,
                         cudaFuncAttributeMaxDynamicSharedMemorySize, GSMEM_BYTES);
    cudaFuncSetAttribute(attn_mma_kernel,
                         cudaFuncAttributeMaxDynamicSharedMemorySize, ATT_SMEM);

    // 0. Transpose + fp16-convert weights: W[K][N] -> Wt[N][K]
    transpose_h_kernel<<<dim3(3*EE/32, EE/32), dim3(32, 8)>>>(c_attn_w, w + WT_ATTN_OFF, EE, 3*EE);
    transpose_h_kernel<<<dim3(EE/32,   EE/32), dim3(32, 8)>>>(c_proj_w, w + WT_PROJ_OFF, EE, EE);
    transpose_h_kernel<<<dim3(FF/32,   EE/32), dim3(32, 8)>>>(mlp_w1,   w + WT_MLP1_OFF, EE, FF);
    transpose_h_kernel<<<dim3(EE/32,   FF/32), dim3(32, 8)>>>(mlp_w2,   w + WT_MLP2_OFF, FF, EE);

    // 1. LN1 (fp16 out)
    ln_kernel<<<MM, 256>>>(x, ln1_g, ln1_b, ln);
    // 2. QKV = ln @ c_attn_w + b           [4096, 3072] fp32 out
    mma_gemm<false, false, false><<<dim3(3*EE/128, MM/128), 256, GSMEM_BYTES>>>(
        ln, w + WT_ATTN_OFF, c_attn_b, nullptr, qkv, MM, 3*EE, EE);
    // 3. Attention (fp16 out)
    attn_mma_kernel<<<dim3(TT/64, HH, BB), 128, ATT_SMEM>>>(qkv, att);
    // 4. x2 = x + att @ c_proj_w + b       [4096, 1024] fp32 out
    mma_gemm<false, true, false><<<dim3(EE/128, MM/128), 256, GSMEM_BYTES>>>(
        att, w + WT_PROJ_OFF, c_proj_b, x, x2, MM, EE, EE);
    // 5. LN2 (fp16 out)
    ln_kernel<<<MM, 256>>>(x2, ln2_g, ln2_b, ln);
    // 6. act = gelu(h @ mlp_w1 + b1)       [4096, 4096] fp16 out
    mma_gemm<true, false, true><<<dim3(FF/128, MM/128), 256, GSMEM_BYTES>>>(
        ln, w + WT_MLP1_OFF, mlp_b1, nullptr, act, MM, FF, EE);
    // 7. out = x2 + act @ mlp_w2 + b2      [4096, 1024] fp32 out
    mma_gemm<false, true, false><<<dim3(EE/128, MM/128), 256, GSMEM_BYTES>>>(
        act, w + WT_MLP2_OFF, mlp_b2, x2, out, MM, EE, FF);
}

// round 8
// speedup vs baseline: 7.7831x; 1.1104x over previous
#include <cuda_runtime.h>
#include <cuda_fp16.h>
#include <math.h>
#include <stdint.h>

// Problem constants
#define BB 2
#define TT 2048
#define EE 1024
#define HH 16
#define DH 64
#define FF 4096
#define MM (BB*TT)   // 4096 rows

// Scratch (device globals: no allocation allowed)
__device__ float g_ln [MM*EE];         // as __half
__device__ float g_qkv[MM*3*EE];       // as __half now
__device__ float g_att[MM*EE];         // as __half
__device__ float g_x2 [MM*EE];         // fp32
__device__ float g_act[(size_t)MM*FF]; // as __half
__device__ float g_w  [6*1024*1024];   // fp16 transposed weights

#define WT_ATTN_OFF 0
#define WT_PROJ_OFF (3*EE*EE)
#define WT_MLP1_OFF (WT_PROJ_OFF + EE*EE)
#define WT_MLP2_OFF (WT_MLP1_OFF + EE*FF)

// ---------------------------------------------------------------------------
// Helpers
// ---------------------------------------------------------------------------
__device__ __forceinline__ void cp16(uint32_t dst, const void* src) {
    asm volatile("cp.async.cg.shared.global [%0], [%1], 16;\n" :: "r"(dst), "l"(src));
}

#define MMA_F16(d0,d1,d2,d3,a0,a1,a2,a3,b0,b1) \
    asm volatile( \
        "mma.sync.aligned.m16n8k16.row.col.f32.f16.f16.f32 " \
        "{%0,%1,%2,%3}, {%4,%5,%6,%7}, {%8,%9}, {%0,%1,%2,%3};" \
        : "+f"(d0), "+f"(d1), "+f"(d2), "+f"(d3) \
        : "r"(a0), "r"(a1), "r"(a2), "r"(a3), "r"(b0), "r"(b1))

#define LDSM_X4(r0,r1,r2,r3,addr) \
    asm volatile("ldmatrix.sync.aligned.m8n8.x4.shared.b16 {%0,%1,%2,%3}, [%4];" \
        : "=r"(r0), "=r"(r1), "=r"(r2), "=r"(r3) : "r"(addr))

#define LDSM_X4_T(r0,r1,r2,r3,addr) \
    asm volatile("ldmatrix.sync.aligned.m8n8.x4.trans.shared.b16 {%0,%1,%2,%3}, [%4];" \
        : "=r"(r0), "=r"(r1), "=r"(r2), "=r"(r3) : "r"(addr))

// ---------------------------------------------------------------------------
// Weight transpose + fp16 convert: in[R][C] fp32 -> out[C][R] fp16
// ---------------------------------------------------------------------------
__global__ void transpose_h_kernel(const float* __restrict__ in,
                                   __half* __restrict__ out, int R, int C) {
    __shared__ float tile[32][33];
    int x = blockIdx.x * 32 + threadIdx.x;
    int y0 = blockIdx.y * 32;
    #pragma unroll
    for (int j = threadIdx.y; j < 32; j += 8)
        tile[j][threadIdx.x] = in[(size_t)(y0 + j) * C + x];
    __syncthreads();
    int ox = y0 + threadIdx.x;
    int oy0 = blockIdx.x * 32;
    #pragma unroll
    for (int j = threadIdx.y; j < 32; j += 8)
        out[(size_t)(oy0 + j) * R + ox] = __float2half_rn(tile[threadIdx.x][j]);
}

// ---------------------------------------------------------------------------
// LayerNorm: one block per row of 1024, 256 threads, fp16 output
// ---------------------------------------------------------------------------
__global__ void ln_kernel(const float* __restrict__ x,
                          const float* __restrict__ g,
                          const float* __restrict__ b,
                          __half* __restrict__ out) {
    int row = blockIdx.x;
    int tid = threadIdx.x;
    const float4* xr = reinterpret_cast<const float4*>(x + (size_t)row * EE);
    float4 v = xr[tid];
    float s  = v.x + v.y + v.z + v.w;
    float sq = v.x*v.x + v.y*v.y + v.z*v.z + v.w*v.w;
    #pragma unroll
    for (int o = 16; o > 0; o >>= 1) {
        s  += __shfl_xor_sync(0xffffffff, s,  o);
        sq += __shfl_xor_sync(0xffffffff, sq, o);
    }
    __shared__ float rs[8], rq[8], mu_s, rstd_s;
    int warp = tid >> 5, lane = tid & 31;
    if (lane == 0) { rs[warp] = s; rq[warp] = sq; }
    __syncthreads();
    if (tid == 0) {
        float ts = 0.f, tq = 0.f;
        #pragma unroll
        for (int i = 0; i < 8; i++) { ts += rs[i]; tq += rq[i]; }
        float mu  = ts * (1.0f / EE);
        float var = tq * (1.0f / EE) - mu * mu;
        mu_s = mu;
        rstd_s = rsqrtf(var + 1e-5f);
    }
    __syncthreads();
    float mu = mu_s, rstd = rstd_s;
    float4 gv = reinterpret_cast<const float4*>(g)[tid];
    float4 bv = reinterpret_cast<const float4*>(b)[tid];
    __half2 h0 = __floats2half2_rn((v.x - mu) * rstd * gv.x + bv.x,
                                   (v.y - mu) * rstd * gv.y + bv.y);
    __half2 h1 = __floats2half2_rn((v.z - mu) * rstd * gv.z + bv.z,
                                   (v.w - mu) * rstd * gv.w + bv.w);
    __half2* op = reinterpret_cast<__half2*>(out + (size_t)row * EE);
    op[tid * 2]     = h0;
    op[tid * 2 + 1] = h1;
}

__device__ __forceinline__ float gelu_f(float x) {
    const float c = 0.7978845608028654f;
    float x3 = x * x * x;
    return 0.5f * x * (1.0f + tanhf(c * (x + 0.044715f * x3)));
}

// ---------------------------------------------------------------------------
// fp16 GEMM, CTA 128x256x64, 8 warps (2x4), warp tile 64x64, fp32 accum.
// Per warp per k16: 8 LDSM.x4 feed 32 MMAs (128 B smem / MMA).
// 3-stage cp.async; one __syncthreads per k-iteration. 1 CTA/SM.
// Smem/stage: A 128x128B (16K) + B 256x128B (32K) = 48K; 3 stages = 144K.
// ---------------------------------------------------------------------------
#define GSTAGE 49152
#define GSMEM_BYTES (3*GSTAGE)    // 147456

template<bool GELU, bool RES, bool OUTH>
__global__ void __launch_bounds__(256, 1)
mma_gemm(const __half* __restrict__ A, const __half* __restrict__ Wt,
         const float* __restrict__ bias, const float* __restrict__ res,
         void* __restrict__ Cv, int M, int N, int K) {
    extern __shared__ char smc[];
    const uint32_t sm_u = (uint32_t)__cvta_generic_to_shared(smc);

    const int tid  = threadIdx.x;
    const int lane = tid & 31;
    const int warp = tid >> 5;
    const int wm = warp >> 2;     // 0..1 -> m offset *64
    const int wn = warp & 3;      // 0..3 -> n offset *64
    const int g  = lane >> 2;
    const int tg = lane & 3;

    const int bm = blockIdx.y, bn = blockIdx.x;
    const __half* Ab = A  + (size_t)bm * 128 * K;
    const __half* Bb = Wt + (size_t)bn * 256 * K;

    // ldmatrix lane addressing
    const int j    = lane & 7;
    const int tile = lane >> 3;
    const uint32_t jm = (uint32_t)(j * 16);
    const uint32_t aRowSel = (uint32_t)((tile & 1) * 8);
    const uint32_t aC16    = (uint32_t)((tile >> 1) * 16);
    const uint32_t bRowSel = (uint32_t)((tile >> 1) * 8);
    const uint32_t bC16    = (uint32_t)((tile & 1) * 16);

    uint32_t aRow[4], bRow[4];
    #pragma unroll
    for (int mi = 0; mi < 4; mi++)
        aRow[mi] = ((uint32_t)(wm * 64 + mi * 16 + j) + aRowSel) * 128;
    #pragma unroll
    for (int bi = 0; bi < 4; bi++)
        bRow[bi] = 16384u + ((uint32_t)(wn * 64 + bi * 16 + j) + bRowSel) * 128;

    const int sch = (tid & 7) << 4;    // byte chunk within 128B row

    float acc[4][8][4];
    #pragma unroll
    for (int i = 0; i < 4; i++)
        #pragma unroll
        for (int jj = 0; jj < 8; jj++)
            #pragma unroll
            for (int c = 0; c < 4; c++) acc[i][jj][c] = 0.f;

    auto issue = [&](int stage, int kt) {
        uint32_t sA = sm_u + (uint32_t)stage * GSTAGE;
        uint32_t sB = sA + 16384u;
        int kc = kt * 64 + (sch >> 1);
        #pragma unroll
        for (int p = 0; p < 4; p++) {
            int r = (tid >> 3) + p * 32;
            uint32_t dst = (uint32_t)(r * 128) + ((uint32_t)sch ^ ((uint32_t)(r & 7) * 16));
            cp16(sA + dst, Ab + (size_t)r * K + kc);
        }
        #pragma unroll
        for (int p = 0; p < 8; p++) {
            int r = (tid >> 3) + p * 32;
            uint32_t dst = (uint32_t)(r * 128) + ((uint32_t)sch ^ ((uint32_t)(r & 7) * 16));
            cp16(sB + dst, Bb + (size_t)r * K + kc);
        }
        asm volatile("cp.async.commit_group;\n");
    };

    const int KT = K >> 6;
    issue(0, 0);
    issue(1, 1);

    int rbuf = 0, ibuf = 2;
    for (int kt = 0; kt < KT; kt++) {
        if (kt + 1 < KT) {
            asm volatile("cp.async.wait_group 1;\n");
        } else {
            asm volatile("cp.async.wait_group 0;\n");
        }
        __syncthreads();
        if (kt + 2 < KT) {
            issue(ibuf, kt + 2);
            if (++ibuf == 3) ibuf = 0;
        }

        const uint32_t stBase = sm_u + (uint32_t)rbuf * GSTAGE;
        if (++rbuf == 3) rbuf = 0;

        #pragma unroll
        for (int ks = 0; ks < 4; ks++) {
            const uint32_t koffA = ((uint32_t)(ks * 32) + aC16) ^ jm;
            const uint32_t koffB = ((uint32_t)(ks * 32) + bC16) ^ jm;

            uint32_t af[4][4];
            #pragma unroll
            for (int mi = 0; mi < 4; mi++)
                LDSM_X4(af[mi][0], af[mi][1], af[mi][2], af[mi][3],
                        stBase + aRow[mi] + koffA);

            uint32_t bf[8][2];
            #pragma unroll
            for (int bi = 0; bi < 4; bi++)
                LDSM_X4(bf[bi*2][0], bf[bi*2][1], bf[bi*2+1][0], bf[bi*2+1][1],
                        stBase + bRow[bi] + koffB);

            #pragma unroll
            for (int mi = 0; mi < 4; mi++)
                #pragma unroll
                for (int ni = 0; ni < 8; ni++)
                    MMA_F16(acc[mi][ni][0], acc[mi][ni][1], acc[mi][ni][2], acc[mi][ni][3],
                            af[mi][0], af[mi][1], af[mi][2], af[mi][3],
                            bf[ni][0], bf[ni][1]);
        }
    }

    const int rowBase = bm * 128 + wm * 64;
    const int colBase = bn * 256 + wn * 64;
    float* Cf = (float*)Cv;
    __half* Ch = (__half*)Cv;
    #pragma unroll
    for (int mi = 0; mi < 4; mi++) {
        #pragma unroll
        for (int ni = 0; ni < 8; ni++) {
            int col = colBase + ni * 8 + 2 * tg;
            float bb0 = bias[col], bb1 = bias[col + 1];
            int r0 = rowBase + mi * 16 + g;
            int r1 = r0 + 8;
            float v0 = acc[mi][ni][0] + bb0;
            float v1 = acc[mi][ni][1] + bb1;
            float v2 = acc[mi][ni][2] + bb0;
            float v3 = acc[mi][ni][3] + bb1;
            if (GELU) { v0 = gelu_f(v0); v1 = gelu_f(v1); v2 = gelu_f(v2); v3 = gelu_f(v3); }
            if (RES) {
                const float2 rr0 = *reinterpret_cast<const float2*>(res + (size_t)r0 * N + col);
                const float2 rr1 = *reinterpret_cast<const float2*>(res + (size_t)r1 * N + col);
                v0 += rr0.x; v1 += rr0.y; v2 += rr1.x; v3 += rr1.y;
            }
            if (OUTH) {
                *reinterpret_cast<__half2*>(Ch + (size_t)r0 * N + col) = __floats2half2_rn(v0, v1);
                *reinterpret_cast<__half2*>(Ch + (size_t)r1 * N + col) = __floats2half2_rn(v2, v3);
            } else {
                *reinterpret_cast<float2*>(Cf + (size_t)r0 * N + col) = make_float2(v0, v1);
                *reinterpret_cast<float2*>(Cf + (size_t)r1 * N + col) = make_float2(v2, v3);
            }
        }
    }
}

// ---------------------------------------------------------------------------
// fp16 tensor-core flash attention (m16n8k16; V^T via ldmatrix.trans).
// CTA: 64 queries x head x batch, 4 warps (16 q rows each).
// Smem (bytes): K 2x8K @0, V 2x8K @16384, Q 8K @32768, P 8K @40960.
// ---------------------------------------------------------------------------
#define AOFF_V 16384u
#define AOFF_Q 32768u
#define AOFF_P 40960u
#define ATT_SMEM 49152

__global__ void __launch_bounds__(128, 2)
attn_mma_kernel(const __half* __restrict__ qkv, __half* __restrict__ out) {
    extern __shared__ char smc[];
    const uint32_t sm_u = (uint32_t)__cvta_generic_to_shared(smc);

    const int qt  = gridDim.x - 1 - blockIdx.x;
    const int qt0 = qt * 64;
    const int h   = blockIdx.y;
    const int b   = blockIdx.z;
    const int tid = threadIdx.x;
    const int lane = tid & 31;
    const int warp = tid >> 5;
    const int g  = lane >> 2;
    const int tg = lane & 3;
    const int r0 = warp * 16 + g;          // first query row (local)

    const int j    = lane & 7;
    const int tile = lane >> 3;
    const uint32_t jm = (uint32_t)(j * 16);
    const uint32_t aRowSel = (uint32_t)((tile & 1) * 8);
    const uint32_t aC16    = (uint32_t)((tile >> 1) * 16);
    const uint32_t bRowSel = (uint32_t)((tile >> 1) * 8);
    const uint32_t bC16    = (uint32_t)((tile & 1) * 16);

    const __half* base = qkv + (size_t)b * TT * (3 * EE);
    const int sch = (tid & 7) << 4;        // byte chunk

    auto issueKV = [&](int buf, int kt) {
        int krow0 = kt * 64;
        uint32_t sK = sm_u + (uint32_t)buf * 8192u;
        uint32_t sV = sm_u + AOFF_V + (uint32_t)buf * 8192u;
        #pragma unroll
        for (int p = 0; p < 4; p++) {
            int r = (tid >> 3) + p * 16;
            uint32_t dst = (uint32_t)(r * 128) + ((uint32_t)sch ^ ((uint32_t)(r & 7) * 16));
            const __half* src = base + (size_t)(krow0 + r) * 3072 + EE + h * 64 + (sch >> 1);
            cp16(sK + dst, src);
            cp16(sV + dst, src + EE);
        }
        asm volatile("cp.async.commit_group;\n");
    };

    issueKV(0, 0);

    // Stage Q (scaled by 1/8 in fp16 — exact) into swizzled smem
    {
        const __half2 sc8 = __float2half2_rn(0.125f);
        #pragma unroll
        for (int p = 0; p < 4; p++) {
            int r = (tid >> 3) + p * 16;
            uint4 q = *reinterpret_cast<const uint4*>(
                base + (size_t)(qt0 + r) * 3072 + h * 64 + (sch >> 1));
            __half2* qh = reinterpret_cast<__half2*>(&q);
            qh[0] = __hmul2(qh[0], sc8);
            qh[1] = __hmul2(qh[1], sc8);
            qh[2] = __hmul2(qh[2], sc8);
            qh[3] = __hmul2(qh[3], sc8);
            uint32_t dst = AOFF_Q + (uint32_t)(r * 128) +
                           ((uint32_t)sch ^ ((uint32_t)(r & 7) * 16));
            *reinterpret_cast<uint4*>(smc + dst) = q;
        }
    }
    __syncthreads();

    // Q fragments (held in registers across all K tiles)
    uint32_t qa[4][4];
    #pragma unroll
    for (int ks = 0; ks < 4; ks++) {
        uint32_t addr = sm_u + AOFF_Q +
            ((uint32_t)(warp * 16 + j) + aRowSel) * 128 +
            (((uint32_t)(ks * 32) + aC16) ^ jm);
        LDSM_X4(qa[ks][0], qa[ks][1], qa[ks][2], qa[ks][3], addr);
    }

    float m0 = -1e30f, m1 = -1e30f, l0 = 0.f, l1 = 0.f;
    float ob[8][4];
    #pragma unroll
    for (int nt = 0; nt < 8; nt++)
        #pragma unroll
        for (int c = 0; c < 4; c++) ob[nt][c] = 0.f;

    const int nkt = qt + 1;
    for (int kt = 0; kt < nkt; kt++) {
        if (kt + 1 < nkt) {
            issueKV((kt + 1) & 1, kt + 1);
            asm volatile("cp.async.wait_group 1;\n");
        } else {
            asm volatile("cp.async.wait_group 0;\n");
        }
        __syncthreads();

        const uint32_t sK = sm_u + (uint32_t)(kt & 1) * 8192u;
        const uint32_t sV = sm_u + AOFF_V + (uint32_t)(kt & 1) * 8192u;

        // S = Q @ K^T   (K rows are [key][d] = [n][k] K-major)
        float sc[8][4];
        #pragma unroll
        for (int nt = 0; nt < 8; nt++)
            #pragma unroll
            for (int c = 0; c < 4; c++) sc[nt][c] = 0.f;

        #pragma unroll
        for (int ks = 0; ks < 4; ks++) {
            const uint32_t koffB = ((uint32_t)(ks * 32) + bC16) ^ jm;
            uint32_t bf[8][2];
            #pragma unroll
            for (int bi = 0; bi < 4; bi++) {
                uint32_t addr = sK + ((uint32_t)(bi * 16 + j) + bRowSel) * 128 + koffB;
                LDSM_X4(bf[bi*2][0], bf[bi*2][1], bf[bi*2+1][0], bf[bi*2+1][1], addr);
            }
            #pragma unroll
            for (int nt = 0; nt < 8; nt++)
                MMA_F16(sc[nt][0], sc[nt][1], sc[nt][2], sc[nt][3],
                        qa[ks][0], qa[ks][1], qa[ks][2], qa[ks][3],
                        bf[nt][0], bf[nt][1]);
        }

        // Causal mask (diagonal tile)
        if (kt == nkt - 1) {
            int qrow0 = qt0 + r0;
            int qrow1 = qrow0 + 8;
            #pragma unroll
            for (int nt = 0; nt < 8; nt++) {
                int kc0 = kt * 64 + nt * 8 + 2 * tg;
                if (kc0     > qrow0) sc[nt][0] = -1e30f;
                if (kc0 + 1 > qrow0) sc[nt][1] = -1e30f;
                if (kc0     > qrow1) sc[nt][2] = -1e30f;
                if (kc0 + 1 > qrow1) sc[nt][3] = -1e30f;
            }
        }

        // Online softmax (rows r0, r0+8)
        float rm0 = -1e30f, rm1 = -1e30f;
        #pragma unroll
        for (int nt = 0; nt < 8; nt++) {
            rm0 = fmaxf(rm0, fmaxf(sc[nt][0], sc[nt][1]));
            rm1 = fmaxf(rm1, fmaxf(sc[nt][2], sc[nt][3]));
        }
        rm0 = fmaxf(rm0, __shfl_xor_sync(0xffffffff, rm0, 1));
        rm0 = fmaxf(rm0, __shfl_xor_sync(0xffffffff, rm0, 2));
        rm1 = fmaxf(rm1, __shfl_xor_sync(0xffffffff, rm1, 1));
        rm1 = fmaxf(rm1, __shfl_xor_sync(0xffffffff, rm1, 2));
        float mn0 = fmaxf(m0, rm0);
        float mn1 = fmaxf(m1, rm1);

        float rs0 = 0.f, rs1 = 0.f;
        #pragma unroll
        for (int nt = 0; nt < 8; nt++) {
            sc[nt][0] = __expf(sc[nt][0] - mn0);
            sc[nt][1] = __expf(sc[nt][1] - mn0);
            sc[nt][2] = __expf(sc[nt][2] - mn1);
            sc[nt][3] = __expf(sc[nt][3] - mn1);
            rs0 += sc[nt][0] + sc[nt][1];
            rs1 += sc[nt][2] + sc[nt][3];
        }
        rs0 += __shfl_xor_sync(0xffffffff, rs0, 1);
        rs0 += __shfl_xor_sync(0xffffffff, rs0, 2);
        rs1 += __shfl_xor_sync(0xffffffff, rs1, 1);
        rs1 += __shfl_xor_sync(0xffffffff, rs1, 2);

        float scale0 = __expf(m0 - mn0);
        float scale1 = __expf(m1 - mn1);
        l0 = l0 * scale0 + rs0;
        l1 = l1 * scale1 + rs1;
        m0 = mn0; m1 = mn1;
        #pragma unroll
        for (int nt = 0; nt < 8; nt++) {
            ob[nt][0] *= scale0; ob[nt][1] *= scale0;
            ob[nt][2] *= scale1; ob[nt][3] *= scale1;
        }

        // Store P (fp16) to warp-private smem rows
        __syncwarp();
        #pragma unroll
        for (int nt = 0; nt < 8; nt++) {
            uint32_t off0 = AOFF_P + (uint32_t)(r0 * 128) +
                (((uint32_t)(nt * 16 + 4 * tg)) ^ ((uint32_t)(r0 & 7) * 16));
            uint32_t off1 = AOFF_P + (uint32_t)((r0 + 8) * 128) +
                (((uint32_t)(nt * 16 + 4 * tg)) ^ ((uint32_t)((r0 + 8) & 7) * 16));
            *reinterpret_cast<__half2*>(smc + off0) = __floats2half2_rn(sc[nt][0], sc[nt][1]);
            *reinterpret_cast<__half2*>(smc + off1) = __floats2half2_rn(sc[nt][2], sc[nt][3]);
        }
        __syncwarp();

        // O += P @ V   (P is A [q][k]; V^T fragments via ldmatrix.trans)
        #pragma unroll
        for (int ks = 0; ks < 4; ks++) {
            uint32_t pa[4];
            {
                uint32_t addr = sm_u + AOFF_P +
                    ((uint32_t)(warp * 16 + j) + aRowSel) * 128 +
                    (((uint32_t)(ks * 32) + aC16) ^ jm);
                LDSM_X4(pa[0], pa[1], pa[2], pa[3], addr);
            }
            uint32_t vf[8][2];
            #pragma unroll
            for (int li = 0; li < 4; li++) {
                // tiles: kh = tile&1 (k +0/+8), nb = tile>>1 (n +0/+8)
                uint32_t addr = sV +
                    (uint32_t)((ks * 16 + (tile & 1) * 8 + j) * 128) +
                    (((uint32_t)(li * 32 + (tile >> 1) * 16)) ^ jm);
                LDSM_X4_T(vf[li*2][0], vf[li*2][1], vf[li*2+1][0], vf[li*2+1][1], addr);
            }
            #pragma unroll
            for (int nt = 0; nt < 8; nt++)
                MMA_F16(ob[nt][0], ob[nt][1], ob[nt][2], ob[nt][3],
                        pa[0], pa[1], pa[2], pa[3], vf[nt][0], vf[nt][1]);
        }
        __syncthreads();   // protect K/V buffers before next issue
    }

    // Epilogue
    float inv0 = 1.0f / l0;
    float inv1 = 1.0f / l1;
    size_t row0 = ((size_t)b * TT + qt0 + r0) * EE + h * 64;
    size_t row1 = row0 + 8 * EE;
    #pragma unroll
    for (int nt = 0; nt < 8; nt++) {
        int col = nt * 8 + 2 * tg;
        *reinterpret_cast<__half2*>(out + row0 + col) =
            __floats2half2_rn(ob[nt][0] * inv0, ob[nt][1] * inv0);
        *reinterpret_cast<__half2*>(out + row1 + col) =
            __floats2half2_rn(ob[nt][2] * inv1, ob[nt][3] * inv1);
    }
}

// ---------------------------------------------------------------------------
// Launch
// ---------------------------------------------------------------------------
extern "C" void kernel_launch(void* const* d_in, const int* in_sizes, int n_in,
                              void* d_out, int out_size) {
    const float* x        = (const float*)d_in[0];
    const float* c_attn_w = (const float*)d_in[1];
    const float* c_attn_b = (const float*)d_in[2];
    const float* c_proj_w = (const float*)d_in[3];
    const float* c_proj_b = (const float*)d_in[4];
    const float* mlp_w1   = (const float*)d_in[5];
    const float* mlp_b1   = (const float*)d_in[6];
    const float* mlp_w2   = (const float*)d_in[7];
    const float* mlp_b2   = (const float*)d_in[8];
    const float* ln1_g    = (const float*)d_in[9];
    const float* ln1_b    = (const float*)d_in[10];
    const float* ln2_g    = (const float*)d_in[11];
    const float* ln2_b    = (const float*)d_in[12];
    float* out = (float*)d_out;

    float *lnf, *qkvf, *attf, *x2, *actf, *wf;
    cudaGetSymbolAddress((void**)&lnf,  g_ln);
    cudaGetSymbolAddress((void**)&qkvf, g_qkv);
    cudaGetSymbolAddress((void**)&attf, g_att);
    cudaGetSymbolAddress((void**)&x2,   g_x2);
    cudaGetSymbolAddress((void**)&actf, g_act);
    cudaGetSymbolAddress((void**)&wf,   g_w);
    __half* ln  = (__half*)lnf;
    __half* qkv = (__half*)qkvf;
    __half* att = (__half*)attf;
    __half* act = (__half*)actf;
    __half* w   = (__half*)wf;

    cudaFuncSetAttribute(mma_gemm<false, false, true>,
                         cudaFuncAttributeMaxDynamicSharedMemorySize, GSMEM_BYTES);
    cudaFuncSetAttribute(mma_gemm<false, true, false>,
                         cudaFuncAttributeMaxDynamicSharedMemorySize, GSMEM_BYTES);
    cudaFuncSetAttribute(mma_gemm<true, false, true>,
                         cudaFuncAttributeMaxDynamicSharedMemorySize, GSMEM_BYTES);
    cudaFuncSetAttribute(attn_mma_kernel,
                         cudaFuncAttributeMaxDynamicSharedMemorySize, ATT_SMEM);

    // 0. Transpose + fp16-convert weights: W[K][N] -> Wt[N][K]
    transpose_h_kernel<<<dim3(3*EE/32, EE/32), dim3(32, 8)>>>(c_attn_w, w + WT_ATTN_OFF, EE, 3*EE);
    transpose_h_kernel<<<dim3(EE/32,   EE/32), dim3(32, 8)>>>(c_proj_w, w + WT_PROJ_OFF, EE, EE);
    transpose_h_kernel<<<dim3(FF/32,   EE/32), dim3(32, 8)>>>(mlp_w1,   w + WT_MLP1_OFF, EE, FF);
    transpose_h_kernel<<<dim3(EE/32,   FF/32), dim3(32, 8)>>>(mlp_w2,   w + WT_MLP2_OFF, FF, EE);

    // 1. LN1 (fp16 out)
    ln_kernel<<<MM, 256>>>(x, ln1_g, ln1_b, ln);
    // 2. QKV = ln @ c_attn_w + b           [4096, 3072] fp16 out
    mma_gemm<false, false, true><<<dim3(3*EE/256, MM/128), 256, GSMEM_BYTES>>>(
        ln, w + WT_ATTN_OFF, c_attn_b, nullptr, qkv, MM, 3*EE, EE);
    // 3. Attention (full fp16)
    attn_mma_kernel<<<dim3(TT/64, HH, BB), 128, ATT_SMEM>>>(qkv, att);
    // 4. x2 = x + att @ c_proj_w + b       [4096, 1024] fp32 out
    mma_gemm<false, true, false><<<dim3(EE/256, MM/128), 256, GSMEM_BYTES>>>(
        att, w + WT_PROJ_OFF, c_proj_b, x, x2, MM, EE, EE);
    // 5. LN2 (fp16 out)
    ln_kernel<<<MM, 256>>>(x2, ln2_g, ln2_b, ln);
    // 6. act = gelu(h @ mlp_w1 + b1)       [4096, 4096] fp16 out
    mma_gemm<true, false, true><<<dim3(FF/256, MM/128), 256, GSMEM_BYTES>>>(
        ln, w + WT_MLP1_OFF, mlp_b1, nullptr, act, MM, FF, EE);
    // 7. out = x2 + act @ mlp_w2 + b2      [4096, 1024] fp32 out
    mma_gemm<false, true, false><<<dim3(EE/256, MM/128), 256, GSMEM_BYTES>>>(
        act, w + WT_MLP2_OFF, mlp_b2, x2, out, MM, EE, FF);
}

// round 9
// speedup vs baseline: 7.8986x; 1.0149x over previous
#include <cuda_runtime.h>
#include <cuda_fp16.h>
#include <math.h>
#include <stdint.h>

// Problem constants
#define BB 2
#define TT 2048
#define EE 1024
#define HH 16
#define DH 64
#define FF 4096
#define MM (BB*TT)   // 4096 rows

// Scratch (device globals: no allocation allowed)
__device__ float g_ln [MM*EE];         // as __half
__device__ float g_qkv[MM*3*EE];       // as __half
__device__ float g_att[MM*EE];         // as __half
__device__ float g_x2 [MM*EE];         // fp32
__device__ float g_act[(size_t)MM*FF]; // as __half
__device__ float g_w  [6*1024*1024];   // fp16 weights, NATURAL [K][N] layout

// offsets in halves
#define WH_ATTN 0
#define WH_PROJ (3*EE*EE)
#define WH_MLP1 (WH_PROJ + EE*EE)
#define WH_MLP2 (WH_MLP1 + EE*FF)

// ---------------------------------------------------------------------------
// Helpers
// ---------------------------------------------------------------------------
__device__ __forceinline__ void cp16(uint32_t dst, const void* src) {
    asm volatile("cp.async.cg.shared.global [%0], [%1], 16;\n" :: "r"(dst), "l"(src));
}

#define MMA_F16(d0,d1,d2,d3,a0,a1,a2,a3,b0,b1) \
    asm volatile( \
        "mma.sync.aligned.m16n8k16.row.col.f32.f16.f16.f32 " \
        "{%0,%1,%2,%3}, {%4,%5,%6,%7}, {%8,%9}, {%0,%1,%2,%3};" \
        : "+f"(d0), "+f"(d1), "+f"(d2), "+f"(d3) \
        : "r"(a0), "r"(a1), "r"(a2), "r"(a3), "r"(b0), "r"(b1))

#define LDSM_X4(r0,r1,r2,r3,addr) \
    asm volatile("ldmatrix.sync.aligned.m8n8.x4.shared.b16 {%0,%1,%2,%3}, [%4];" \
        : "=r"(r0), "=r"(r1), "=r"(r2), "=r"(r3) : "r"(addr))

#define LDSM_X4_T(r0,r1,r2,r3,addr) \
    asm volatile("ldmatrix.sync.aligned.m8n8.x4.trans.shared.b16 {%0,%1,%2,%3}, [%4];" \
        : "=r"(r0), "=r"(r1), "=r"(r2), "=r"(r3) : "r"(addr))

// ---------------------------------------------------------------------------
// fp32 -> fp16 convert (same layout), coalesced float4 grid-stride
// ---------------------------------------------------------------------------
__global__ void convert_h_kernel(const float4* __restrict__ in,
                                 uint2* __restrict__ out, int n4) {
    int i = blockIdx.x * blockDim.x + threadIdx.x;
    int stride = gridDim.x * blockDim.x;
    for (; i < n4; i += stride) {
        float4 v = in[i];
        __half2 a = __floats2half2_rn(v.x, v.y);
        __half2 b = __floats2half2_rn(v.z, v.w);
        uint2 o;
        o.x = *reinterpret_cast<uint32_t*>(&a);
        o.y = *reinterpret_cast<uint32_t*>(&b);
        out[i] = o;
    }
}

// ---------------------------------------------------------------------------
// LayerNorm: one block per row of 1024, 256 threads, fp16 output
// ---------------------------------------------------------------------------
__global__ void ln_kernel(const float* __restrict__ x,
                          const float* __restrict__ g,
                          const float* __restrict__ b,
                          __half* __restrict__ out) {
    int row = blockIdx.x;
    int tid = threadIdx.x;
    const float4* xr = reinterpret_cast<const float4*>(x + (size_t)row * EE);
    float4 v = xr[tid];
    float s  = v.x + v.y + v.z + v.w;
    float sq = v.x*v.x + v.y*v.y + v.z*v.z + v.w*v.w;
    #pragma unroll
    for (int o = 16; o > 0; o >>= 1) {
        s  += __shfl_xor_sync(0xffffffff, s,  o);
        sq += __shfl_xor_sync(0xffffffff, sq, o);
    }
    __shared__ float rs[8], rq[8], mu_s, rstd_s;
    int warp = tid >> 5, lane = tid & 31;
    if (lane == 0) { rs[warp] = s; rq[warp] = sq; }
    __syncthreads();
    if (tid == 0) {
        float ts = 0.f, tq = 0.f;
        #pragma unroll
        for (int i = 0; i < 8; i++) { ts += rs[i]; tq += rq[i]; }
        float mu  = ts * (1.0f / EE);
        float var = tq * (1.0f / EE) - mu * mu;
        mu_s = mu;
        rstd_s = rsqrtf(var + 1e-5f);
    }
    __syncthreads();
    float mu = mu_s, rstd = rstd_s;
    float4 gv = reinterpret_cast<const float4*>(g)[tid];
    float4 bv = reinterpret_cast<const float4*>(b)[tid];
    __half2 h0 = __floats2half2_rn((v.x - mu) * rstd * gv.x + bv.x,
                                   (v.y - mu) * rstd * gv.y + bv.y);
    __half2 h1 = __floats2half2_rn((v.z - mu) * rstd * gv.z + bv.z,
                                   (v.w - mu) * rstd * gv.w + bv.w);
    __half2* op = reinterpret_cast<__half2*>(out + (size_t)row * EE);
    op[tid * 2]     = h0;
    op[tid * 2 + 1] = h1;
}

__device__ __forceinline__ float gelu_f(float x) {
    const float c = 0.7978845608028654f;
    float x3 = x * x * x;
    return 0.5f * x * (1.0f + tanhf(c * (x + 0.044715f * x3)));
}

// ---------------------------------------------------------------------------
// fp16 GEMM, CTA 128x256x64, 8 warps (2x4), warp tile 64x64, fp32 accum.
// A: [M][K] fp16, staged as [m][k] 128B rows (SW by m&7), LDSM_X4.
// B: W [K][N] fp16 NATURAL, staged as [k][n] 512B rows (SW by k&7 within
//    128B blocks), fragments via LDSM_X4_T (verified pattern from attn V).
// Fragments double-buffered across k16 steps. 3-stage cp.async, one
// __syncthreads per k64 iteration.
// ---------------------------------------------------------------------------
#define GSTAGE 49152
#define GSMEM_BYTES (3*GSTAGE)    // 147456

template<bool GELU, bool RES, bool OUTH>
__global__ void __launch_bounds__(256, 1)
mma_gemm(const __half* __restrict__ A, const __half* __restrict__ W,
         const float* __restrict__ bias, const float* __restrict__ res,
         void* __restrict__ Cv, int M, int N, int K) {
    extern __shared__ char smc[];
    const uint32_t sm_u = (uint32_t)__cvta_generic_to_shared(smc);

    const int tid  = threadIdx.x;
    const int lane = tid & 31;
    const int warp = tid >> 5;
    const int wm = warp >> 2;     // 0..1 -> m offset *64
    const int wn = warp & 3;      // 0..3 -> n offset *64
    const int g  = lane >> 2;
    const int tg = lane & 3;

    const int bm = blockIdx.y, bn = blockIdx.x;
    const __half* Ab = A + (size_t)bm * 128 * K;
    const __half* Bb = W + (size_t)bn * 256;      // column offset in [K][N]

    // ldmatrix lane addressing
    const int j    = lane & 7;
    const int tile = lane >> 3;
    const uint32_t jm = (uint32_t)(j * 16);
    const uint32_t aRowSel = (uint32_t)((tile & 1) * 8);
    const uint32_t aC16    = (uint32_t)((tile >> 1) * 16);
    // B (trans): kh = tile&1 -> k +0/+8 ; nb = tile>>1 -> n +0/+8
    const uint32_t nbOff   = (uint32_t)((tile >> 1) * 16);   // bytes

    uint32_t aRow[4];
    #pragma unroll
    for (int mi = 0; mi < 4; mi++)
        aRow[mi] = ((uint32_t)(wm * 64 + mi * 16 + j) + aRowSel) * 128;
    // B base: smem B at +16384; row = k (512B); this lane's row j + kh*8
    const uint32_t bBase = 16384u + (uint32_t)wn * 128u +
                           (uint32_t)(tile & 1) * 4096u + (uint32_t)j * 512u;

    float acc[4][8][4];
    #pragma unroll
    for (int i = 0; i < 4; i++)
        #pragma unroll
        for (int jj = 0; jj < 8; jj++)
            #pragma unroll
            for (int c = 0; c < 4; c++) acc[i][jj][c] = 0.f;

    auto issue = [&](int stage, int kt) {
        uint32_t sA = sm_u + (uint32_t)stage * GSTAGE;
        uint32_t sB = sA + 16384u;
        // A: 128 rows x 8 chunks(16B); 1024 chunks / 256 thr = 4
        {
            int c = tid & 7;                 // chunk
            int kc = kt * 64 + c * 8;        // half index
            #pragma unroll
            for (int p = 0; p < 4; p++) {
                int r = (tid >> 3) + p * 32;
                uint32_t dst = (uint32_t)(r * 128) +
                               (((uint32_t)(c * 16)) ^ ((uint32_t)(r & 7) * 16));
                cp16(sA + dst, Ab + (size_t)r * K + kc);
            }
        }
        // B: 64 k-rows x 32 chunks(16B) of N; 2048 chunks / 256 thr = 8
        #pragma unroll
        for (int p = 0; p < 8; p++) {
            int idx = tid + p * 256;
            int r = idx >> 5;                // k row 0..63
            int c = idx & 31;                // 16B chunk 0..31
            uint32_t dst = (uint32_t)(r * 512) + (uint32_t)((c >> 3) * 128) +
                           (((uint32_t)((c & 7) * 16)) ^ ((uint32_t)(r & 7) * 16));
            cp16(sB + dst, Bb + (size_t)(kt * 64 + r) * N + c * 8);
        }
        asm volatile("cp.async.commit_group;\n");
    };

    const int KT = K >> 6;
    issue(0, 0);
    issue(1, 1);

    uint32_t af[2][4][4];
    uint32_t bf[2][8][2];

    int rbuf = 0, ibuf = 2;
    for (int kt = 0; kt < KT; kt++) {
        if (kt + 1 < KT) {
            asm volatile("cp.async.wait_group 1;\n");
        } else {
            asm volatile("cp.async.wait_group 0;\n");
        }
        __syncthreads();
        if (kt + 2 < KT) {
            issue(ibuf, kt + 2);
            if (++ibuf == 3) ibuf = 0;
        }

        const uint32_t stBase = sm_u + (uint32_t)rbuf * GSTAGE;
        if (++rbuf == 3) rbuf = 0;

        // fragment loader for k16 step ks into buffer fb
        #define LOAD_FRAG(fb, ks) do {                                          \
            const uint32_t koffA = ((uint32_t)((ks) * 32) + aC16) ^ jm;         \
            _Pragma("unroll")                                                   \
            for (int mi = 0; mi < 4; mi++)                                      \
                LDSM_X4(af[fb][mi][0], af[fb][mi][1], af[fb][mi][2],            \
                        af[fb][mi][3], stBase + aRow[mi] + koffA);              \
            const uint32_t bk = stBase + bBase + (uint32_t)(ks) * 8192u;        \
            _Pragma("unroll")                                                   \
            for (int li = 0; li < 4; li++) {                                    \
                uint32_t addr = bk + (((uint32_t)(li * 32) + nbOff) ^ jm);      \
                LDSM_X4_T(bf[fb][li*2][0], bf[fb][li*2][1],                     \
                          bf[fb][li*2+1][0], bf[fb][li*2+1][1], addr);          \
            }                                                                   \
        } while (0)

        LOAD_FRAG(0, 0);
        #pragma unroll
        for (int ks = 0; ks < 4; ks++) {
            if (ks < 3) {
                if ((ks & 1) == 0) LOAD_FRAG(1, ks + 1);
                else               LOAD_FRAG(0, ks + 1);
            }
            const int fb = ks & 1;
            #pragma unroll
            for (int mi = 0; mi < 4; mi++)
                #pragma unroll
                for (int ni = 0; ni < 8; ni++)
                    MMA_F16(acc[mi][ni][0], acc[mi][ni][1], acc[mi][ni][2], acc[mi][ni][3],
                            af[fb][mi][0], af[fb][mi][1], af[fb][mi][2], af[fb][mi][3],
                            bf[fb][ni][0], bf[fb][ni][1]);
        }
        #undef LOAD_FRAG
    }

    const int rowBase = bm * 128 + wm * 64;
    const int colBase = bn * 256 + wn * 64;
    float* Cf = (float*)Cv;
    __half* Ch = (__half*)Cv;
    #pragma unroll
    for (int mi = 0; mi < 4; mi++) {
        #pragma unroll
        for (int ni = 0; ni < 8; ni++) {
            int col = colBase + ni * 8 + 2 * tg;
            float bb0 = bias[col], bb1 = bias[col + 1];
            int r0 = rowBase + mi * 16 + g;
            int r1 = r0 + 8;
            float v0 = acc[mi][ni][0] + bb0;
            float v1 = acc[mi][ni][1] + bb1;
            float v2 = acc[mi][ni][2] + bb0;
            float v3 = acc[mi][ni][3] + bb1;
            if (GELU) { v0 = gelu_f(v0); v1 = gelu_f(v1); v2 = gelu_f(v2); v3 = gelu_f(v3); }
            if (RES) {
                const float2 rr0 = *reinterpret_cast<const float2*>(res + (size_t)r0 * N + col);
                const float2 rr1 = *reinterpret_cast<const float2*>(res + (size_t)r1 * N + col);
                v0 += rr0.x; v1 += rr0.y; v2 += rr1.x; v3 += rr1.y;
            }
            if (OUTH) {
                *reinterpret_cast<__half2*>(Ch + (size_t)r0 * N + col) = __floats2half2_rn(v0, v1);
                *reinterpret_cast<__half2*>(Ch + (size_t)r1 * N + col) = __floats2half2_rn(v2, v3);
            } else {
                *reinterpret_cast<float2*>(Cf + (size_t)r0 * N + col) = make_float2(v0, v1);
                *reinterpret_cast<float2*>(Cf + (size_t)r1 * N + col) = make_float2(v2, v3);
            }
        }
    }
}

// ---------------------------------------------------------------------------
// fp16 tensor-core flash attention (unchanged from R8 — verified).
// ---------------------------------------------------------------------------
#define AOFF_V 16384u
#define AOFF_Q 32768u
#define AOFF_P 40960u
#define ATT_SMEM 49152

__global__ void __launch_bounds__(128, 2)
attn_mma_kernel(const __half* __restrict__ qkv, __half* __restrict__ out) {
    extern __shared__ char smc[];
    const uint32_t sm_u = (uint32_t)__cvta_generic_to_shared(smc);

    const int qt  = gridDim.x - 1 - blockIdx.x;
    const int qt0 = qt * 64;
    const int h   = blockIdx.y;
    const int b   = blockIdx.z;
    const int tid = threadIdx.x;
    const int lane = tid & 31;
    const int warp = tid >> 5;
    const int g  = lane >> 2;
    const int tg = lane & 3;
    const int r0 = warp * 16 + g;

    const int j    = lane & 7;
    const int tile = lane >> 3;
    const uint32_t jm = (uint32_t)(j * 16);
    const uint32_t aRowSel = (uint32_t)((tile & 1) * 8);
    const uint32_t aC16    = (uint32_t)((tile >> 1) * 16);
    const uint32_t bRowSel = (uint32_t)((tile >> 1) * 8);
    const uint32_t bC16    = (uint32_t)((tile & 1) * 16);

    const __half* base = qkv + (size_t)b * TT * (3 * EE);
    const int sch = (tid & 7) << 4;

    auto issueKV = [&](int buf, int kt) {
        int krow0 = kt * 64;
        uint32_t sK = sm_u + (uint32_t)buf * 8192u;
        uint32_t sV = sm_u + AOFF_V + (uint32_t)buf * 8192u;
        #pragma unroll
        for (int p = 0; p < 4; p++) {
            int r = (tid >> 3) + p * 16;
            uint32_t dst = (uint32_t)(r * 128) + ((uint32_t)sch ^ ((uint32_t)(r & 7) * 16));
            const __half* src = base + (size_t)(krow0 + r) * 3072 + EE + h * 64 + (sch >> 1);
            cp16(sK + dst, src);
            cp16(sV + dst, src + EE);
        }
        asm volatile("cp.async.commit_group;\n");
    };

    issueKV(0, 0);

    {
        const __half2 sc8 = __float2half2_rn(0.125f);
        #pragma unroll
        for (int p = 0; p < 4; p++) {
            int r = (tid >> 3) + p * 16;
            uint4 q = *reinterpret_cast<const uint4*>(
                base + (size_t)(qt0 + r) * 3072 + h * 64 + (sch >> 1));
            __half2* qh = reinterpret_cast<__half2*>(&q);
            qh[0] = __hmul2(qh[0], sc8);
            qh[1] = __hmul2(qh[1], sc8);
            qh[2] = __hmul2(qh[2], sc8);
            qh[3] = __hmul2(qh[3], sc8);
            uint32_t dst = AOFF_Q + (uint32_t)(r * 128) +
                           ((uint32_t)sch ^ ((uint32_t)(r & 7) * 16));
            *reinterpret_cast<uint4*>(smc + dst) = q;
        }
    }
    __syncthreads();

    uint32_t qa[4][4];
    #pragma unroll
    for (int ks = 0; ks < 4; ks++) {
        uint32_t addr = sm_u + AOFF_Q +
            ((uint32_t)(warp * 16 + j) + aRowSel) * 128 +
            (((uint32_t)(ks * 32) + aC16) ^ jm);
        LDSM_X4(qa[ks][0], qa[ks][1], qa[ks][2], qa[ks][3], addr);
    }

    float m0 = -1e30f, m1 = -1e30f, l0 = 0.f, l1 = 0.f;
    float ob[8][4];
    #pragma unroll
    for (int nt = 0; nt < 8; nt++)
        #pragma unroll
        for (int c = 0; c < 4; c++) ob[nt][c] = 0.f;

    const int nkt = qt + 1;
    for (int kt = 0; kt < nkt; kt++) {
        if (kt + 1 < nkt) {
            issueKV((kt + 1) & 1, kt + 1);
            asm volatile("cp.async.wait_group 1;\n");
        } else {
            asm volatile("cp.async.wait_group 0;\n");
        }
        __syncthreads();

        const uint32_t sK = sm_u + (uint32_t)(kt & 1) * 8192u;
        const uint32_t sV = sm_u + AOFF_V + (uint32_t)(kt & 1) * 8192u;

        float sc[8][4];
        #pragma unroll
        for (int nt = 0; nt < 8; nt++)
            #pragma unroll
            for (int c = 0; c < 4; c++) sc[nt][c] = 0.f;

        #pragma unroll
        for (int ks = 0; ks < 4; ks++) {
            const uint32_t koffB = ((uint32_t)(ks * 32) + bC16) ^ jm;
            uint32_t bfr[8][2];
            #pragma unroll
            for (int bi = 0; bi < 4; bi++) {
                uint32_t addr = sK + ((uint32_t)(bi * 16 + j) + bRowSel) * 128 + koffB;
                LDSM_X4(bfr[bi*2][0], bfr[bi*2][1], bfr[bi*2+1][0], bfr[bi*2+1][1], addr);
            }
            #pragma unroll
            for (int nt = 0; nt < 8; nt++)
                MMA_F16(sc[nt][0], sc[nt][1], sc[nt][2], sc[nt][3],
                        qa[ks][0], qa[ks][1], qa[ks][2], qa[ks][3],
                        bfr[nt][0], bfr[nt][1]);
        }

        if (kt == nkt - 1) {
            int qrow0 = qt0 + r0;
            int qrow1 = qrow0 + 8;
            #pragma unroll
            for (int nt = 0; nt < 8; nt++) {
                int kc0 = kt * 64 + nt * 8 + 2 * tg;
                if (kc0     > qrow0) sc[nt][0] = -1e30f;
                if (kc0 + 1 > qrow0) sc[nt][1] = -1e30f;
                if (kc0     > qrow1) sc[nt][2] = -1e30f;
                if (kc0 + 1 > qrow1) sc[nt][3] = -1e30f;
            }
        }

        float rm0 = -1e30f, rm1 = -1e30f;
        #pragma unroll
        for (int nt = 0; nt < 8; nt++) {
            rm0 = fmaxf(rm0, fmaxf(sc[nt][0], sc[nt][1]));
            rm1 = fmaxf(rm1, fmaxf(sc[nt][2], sc[nt][3]));
        }
        rm0 = fmaxf(rm0, __shfl_xor_sync(0xffffffff, rm0, 1));
        rm0 = fmaxf(rm0, __shfl_xor_sync(0xffffffff, rm0, 2));
        rm1 = fmaxf(rm1, __shfl_xor_sync(0xffffffff, rm1, 1));
        rm1 = fmaxf(rm1, __shfl_xor_sync(0xffffffff, rm1, 2));
        float mn0 = fmaxf(m0, rm0);
        float mn1 = fmaxf(m1, rm1);

        float rs0 = 0.f, rs1 = 0.f;
        #pragma unroll
        for (int nt = 0; nt < 8; nt++) {
            sc[nt][0] = __expf(sc[nt][0] - mn0);
            sc[nt][1] = __expf(sc[nt][1] - mn0);
            sc[nt][2] = __expf(sc[nt][2] - mn1);
            sc[nt][3] = __expf(sc[nt][3] - mn1);
            rs0 += sc[nt][0] + sc[nt][1];
            rs1 += sc[nt][2] + sc[nt][3];
        }
        rs0 += __shfl_xor_sync(0xffffffff, rs0, 1);
        rs0 += __shfl_xor_sync(0xffffffff, rs0, 2);
        rs1 += __shfl_xor_sync(0xffffffff, rs1, 1);
        rs1 += __shfl_xor_sync(0xffffffff, rs1, 2);

        float scale0 = __expf(m0 - mn0);
        float scale1 = __expf(m1 - mn1);
        l0 = l0 * scale0 + rs0;
        l1 = l1 * scale1 + rs1;
        m0 = mn0; m1 = mn1;
        #pragma unroll
        for (int nt = 0; nt < 8; nt++) {
            ob[nt][0] *= scale0; ob[nt][1] *= scale0;
            ob[nt][2] *= scale1; ob[nt][3] *= scale1;
        }

        __syncwarp();
        #pragma unroll
        for (int nt = 0; nt < 8; nt++) {
            uint32_t off0 = AOFF_P + (uint32_t)(r0 * 128) +
                (((uint32_t)(nt * 16 + 4 * tg)) ^ ((uint32_t)(r0 & 7) * 16));
            uint32_t off1 = AOFF_P + (uint32_t)((r0 + 8) * 128) +
                (((uint32_t)(nt * 16 + 4 * tg)) ^ ((uint32_t)((r0 + 8) & 7) * 16));
            *reinterpret_cast<__half2*>(smc + off0) = __floats2half2_rn(sc[nt][0], sc[nt][1]);
            *reinterpret_cast<__half2*>(smc + off1) = __floats2half2_rn(sc[nt][2], sc[nt][3]);
        }
        __syncwarp();

        #pragma unroll
        for (int ks = 0; ks < 4; ks++) {
            uint32_t pa[4];
            {
                uint32_t addr = sm_u + AOFF_P +
                    ((uint32_t)(warp * 16 + j) + aRowSel) * 128 +
                    (((uint32_t)(ks * 32) + aC16) ^ jm);
                LDSM_X4(pa[0], pa[1], pa[2], pa[3], addr);
            }
            uint32_t vf[8][2];
            #pragma unroll
            for (int li = 0; li < 4; li++) {
                uint32_t addr = sV +
                    (uint32_t)((ks * 16 + (tile & 1) * 8 + j) * 128) +
                    (((uint32_t)(li * 32 + (tile >> 1) * 16)) ^ jm);
                LDSM_X4_T(vf[li*2][0], vf[li*2][1], vf[li*2+1][0], vf[li*2+1][1], addr);
            }
            #pragma unroll
            for (int nt = 0; nt < 8; nt++)
                MMA_F16(ob[nt][0], ob[nt][1], ob[nt][2], ob[nt][3],
                        pa[0], pa[1], pa[2], pa[3], vf[nt][0], vf[nt][1]);
        }
        __syncthreads();
    }

    float inv0 = 1.0f / l0;
    float inv1 = 1.0f / l1;
    size_t row0 = ((size_t)b * TT + qt0 + r0) * EE + h * 64;
    size_t row1 = row0 + 8 * EE;
    #pragma unroll
    for (int nt = 0; nt < 8; nt++) {
        int col = nt * 8 + 2 * tg;
        *reinterpret_cast<__half2*>(out + row0 + col) =
            __floats2half2_rn(ob[nt][0] * inv0, ob[nt][1] * inv0);
        *reinterpret_cast<__half2*>(out + row1 + col) =
            __floats2half2_rn(ob[nt][2] * inv1, ob[nt][3] * inv1);
    }
}

// ---------------------------------------------------------------------------
// Launch
// ---------------------------------------------------------------------------
extern "C" void kernel_launch(void* const* d_in, const int* in_sizes, int n_in,
                              void* d_out, int out_size) {
    const float* x        = (const float*)d_in[0];
    const float* c_attn_w = (const float*)d_in[1];
    const float* c_attn_b = (const float*)d_in[2];
    const float* c_proj_w = (const float*)d_in[3];
    const float* c_proj_b = (const float*)d_in[4];
    const float* mlp_w1   = (const float*)d_in[5];
    const float* mlp_b1   = (const float*)d_in[6];
    const float* mlp_w2   = (const float*)d_in[7];
    const float* mlp_b2   = (const float*)d_in[8];
    const float* ln1_g    = (const float*)d_in[9];
    const float* ln1_b    = (const float*)d_in[10];
    const float* ln2_g    = (const float*)d_in[11];
    const float* ln2_b    = (const float*)d_in[12];
    float* out = (float*)d_out;

    float *lnf, *qkvf, *attf, *x2, *actf, *wf;
    cudaGetSymbolAddress((void**)&lnf,  g_ln);
    cudaGetSymbolAddress((void**)&qkvf, g_qkv);
    cudaGetSymbolAddress((void**)&attf, g_att);
    cudaGetSymbolAddress((void**)&x2,   g_x2);
    cudaGetSymbolAddress((void**)&actf, g_act);
    cudaGetSymbolAddress((void**)&wf,   g_w);
    __half* ln  = (__half*)lnf;
    __half* qkv = (__half*)qkvf;
    __half* att = (__half*)attf;
    __half* act = (__half*)actf;
    __half* w   = (__half*)wf;

    cudaFuncSetAttribute(mma_gemm<false, false, true>,
                         cudaFuncAttributeMaxDynamicSharedMemorySize, GSMEM_BYTES);
    cudaFuncSetAttribute(mma_gemm<false, true, false>,
                         cudaFuncAttributeMaxDynamicSharedMemorySize, GSMEM_BYTES);
    cudaFuncSetAttribute(mma_gemm<true, false, true>,
                         cudaFuncAttributeMaxDynamicSharedMemorySize, GSMEM_BYTES);
    cudaFuncSetAttribute(attn_mma_kernel,
                         cudaFuncAttributeMaxDynamicSharedMemorySize, ATT_SMEM);

    // 0. Convert weights fp32 -> fp16 (same [K][N] layout, no transpose)
    convert_h_kernel<<<1184, 256>>>((const float4*)c_attn_w, (uint2*)(w + WH_ATTN), 3*EE*EE/4);
    convert_h_kernel<<<1184, 256>>>((const float4*)c_proj_w, (uint2*)(w + WH_PROJ), EE*EE/4);
    convert_h_kernel<<<1184, 256>>>((const float4*)mlp_w1,   (uint2*)(w + WH_MLP1), EE*FF/4);
    convert_h_kernel<<<1184, 256>>>((const float4*)mlp_w2,   (uint2*)(w + WH_MLP2), FF*EE/4);

    // 1. LN1 (fp16 out)
    ln_kernel<<<MM, 256>>>(x, ln1_g, ln1_b, ln);
    // 2. QKV = ln @ c_attn_w + b           [4096, 3072] fp16 out
    mma_gemm<false, false, true><<<dim3(3*EE/256, MM/128), 256, GSMEM_BYTES>>>(
        ln, w + WH_ATTN, c_attn_b, nullptr, qkv, MM, 3*EE, EE);
    // 3. Attention (full fp16)
    attn_mma_kernel<<<dim3(TT/64, HH, BB), 128, ATT_SMEM>>>(qkv, att);
    // 4. x2 = x + att @ c_proj_w + b       [4096, 1024] fp32 out
    mma_gemm<false, true, false><<<dim3(EE/256, MM/128), 256, GSMEM_BYTES>>>(
        att, w + WH_PROJ, c_proj_b, x, x2, MM, EE, EE);
    // 5. LN2 (fp16 out)
    ln_kernel<<<MM, 256>>>(x2, ln2_g, ln2_b, ln);
    // 6. act = gelu(h @ mlp_w1 + b1)       [4096, 4096] fp16 out
    mma_gemm<true, false, true><<<dim3(FF/256, MM/128), 256, GSMEM_BYTES>>>(
        ln, w + WH_MLP1, mlp_b1, nullptr, act, MM, FF, EE);
    // 7. out = x2 + act @ mlp_w2 + b2      [4096, 1024] fp32 out
    mma_gemm<false, true, false><<<dim3(EE/256, MM/128), 256, GSMEM_BYTES>>>(
        act, w + WH_MLP2, mlp_b2, x2, out, MM, EE, FF);
}

// round 10
// speedup vs baseline: 8.0268x; 1.0162x over previous
#include <cuda_runtime.h>
#include <cuda_fp16.h>
#include <math.h>
#include <stdint.h>

// Problem constants
#define BB 2
#define TT 2048
#define EE 1024
#define HH 16
#define DH 64
#define FF 4096
#define MM (BB*TT)   // 4096 rows

// Scratch (device globals: no allocation allowed)
__device__ float g_ln [MM*EE];         // as __half
__device__ float g_qkv[MM*3*EE];       // as __half
__device__ float g_att[MM*EE];         // as __half
__device__ float g_x2 [MM*EE];         // fp32
__device__ float g_act[(size_t)MM*FF]; // as __half
__device__ float g_w  [6*1024*1024];   // fp16 weights, NATURAL [K][N] layout

// offsets in halves
#define WH_ATTN 0
#define WH_PROJ (3*EE*EE)
#define WH_MLP1 (WH_PROJ + EE*EE)
#define WH_MLP2 (WH_MLP1 + EE*FF)

// ---------------------------------------------------------------------------
// Helpers
// ---------------------------------------------------------------------------
__device__ __forceinline__ void cp16(uint32_t dst, const void* src) {
    asm volatile("cp.async.cg.shared.global [%0], [%1], 16;\n" :: "r"(dst), "l"(src));
}

#define MMA_F16(d0,d1,d2,d3,a0,a1,a2,a3,b0,b1) \
    asm volatile( \
        "mma.sync.aligned.m16n8k16.row.col.f32.f16.f16.f32 " \
        "{%0,%1,%2,%3}, {%4,%5,%6,%7}, {%8,%9}, {%0,%1,%2,%3};" \
        : "+f"(d0), "+f"(d1), "+f"(d2), "+f"(d3) \
        : "r"(a0), "r"(a1), "r"(a2), "r"(a3), "r"(b0), "r"(b1))

#define LDSM_X4(r0,r1,r2,r3,addr) \
    asm volatile("ldmatrix.sync.aligned.m8n8.x4.shared.b16 {%0,%1,%2,%3}, [%4];" \
        : "=r"(r0), "=r"(r1), "=r"(r2), "=r"(r3) : "r"(addr))

#define LDSM_X4_T(r0,r1,r2,r3,addr) \
    asm volatile("ldmatrix.sync.aligned.m8n8.x4.trans.shared.b16 {%0,%1,%2,%3}, [%4];" \
        : "=r"(r0), "=r"(r1), "=r"(r2), "=r"(r3) : "r"(addr))

// ---------------------------------------------------------------------------
// Fused fp32->fp16 convert for all four weights (dsts contiguous in g_w)
// ---------------------------------------------------------------------------
#define CV_S0 786432    // 3*EE*EE/4
#define CV_S1 1048576   // + EE*EE/4
#define CV_S2 2097152   // + EE*FF/4
#define CV_N  3145728   // + FF*EE/4
__global__ void convert_all_kernel(const float4* __restrict__ wa,
                                   const float4* __restrict__ wp,
                                   const float4* __restrict__ w1,
                                   const float4* __restrict__ w2,
                                   uint2* __restrict__ out) {
    int i = blockIdx.x * blockDim.x + threadIdx.x;
    int stride = gridDim.x * blockDim.x;
    for (; i < CV_N; i += stride) {
        float4 v;
        if (i < CV_S0)      v = wa[i];
        else if (i < CV_S1) v = wp[i - CV_S0];
        else if (i < CV_S2) v = w1[i - CV_S1];
        else                v = w2[i - CV_S2];
        __half2 a = __floats2half2_rn(v.x, v.y);
        __half2 b = __floats2half2_rn(v.z, v.w);
        uint2 o;
        o.x = *reinterpret_cast<uint32_t*>(&a);
        o.y = *reinterpret_cast<uint32_t*>(&b);
        out[i] = o;
    }
}

// ---------------------------------------------------------------------------
// LayerNorm: warp per row (no smem, no block barriers). 8 warps/block.
// ---------------------------------------------------------------------------
__global__ void ln_kernel(const float* __restrict__ x,
                          const float* __restrict__ g,
                          const float* __restrict__ b,
                          __half* __restrict__ out) {
    int row  = blockIdx.x * 8 + (threadIdx.x >> 5);
    int lane = threadIdx.x & 31;
    const float4* xr = reinterpret_cast<const float4*>(x + (size_t)row * EE);
    float4 v[8];
    float s = 0.f, sq = 0.f;
    #pragma unroll
    for (int i = 0; i < 8; i++) {
        v[i] = xr[i * 32 + lane];
        s  += v[i].x + v[i].y + v[i].z + v[i].w;
        sq += v[i].x*v[i].x + v[i].y*v[i].y + v[i].z*v[i].z + v[i].w*v[i].w;
    }
    #pragma unroll
    for (int o = 16; o > 0; o >>= 1) {
        s  += __shfl_xor_sync(0xffffffff, s,  o);
        sq += __shfl_xor_sync(0xffffffff, sq, o);
    }
    float mu   = s * (1.0f / EE);
    float rstd = rsqrtf(sq * (1.0f / EE) - mu * mu + 1e-5f);
    uint2* op = reinterpret_cast<uint2*>(out + (size_t)row * EE);
    const float4* gr = reinterpret_cast<const float4*>(g);
    const float4* br = reinterpret_cast<const float4*>(b);
    #pragma unroll
    for (int i = 0; i < 8; i++) {
        float4 gv = gr[i * 32 + lane];
        float4 bv = br[i * 32 + lane];
        __half2 h0 = __floats2half2_rn((v[i].x - mu) * rstd * gv.x + bv.x,
                                       (v[i].y - mu) * rstd * gv.y + bv.y);
        __half2 h1 = __floats2half2_rn((v[i].z - mu) * rstd * gv.z + bv.z,
                                       (v[i].w - mu) * rstd * gv.w + bv.w);
        uint2 o;
        o.x = *reinterpret_cast<uint32_t*>(&h0);
        o.y = *reinterpret_cast<uint32_t*>(&h1);
        op[i * 32 + lane] = o;
    }
}

__device__ __forceinline__ float gelu_f(float x) {
    const float c = 0.7978845608028654f;
    float x3 = x * x * x;
    return 0.5f * x * (1.0f + tanhf(c * (x + 0.044715f * x3)));
}

// ---------------------------------------------------------------------------
// fp16 GEMM, CTA 128x256x64, 8 warps (2x4), warp tile 64x64, fp32 accum.
// A: [M][K] staged as [m][k] 128B rows (SW by m&7), LDSM_X4.
// B: W [K][N] NATURAL, staged as [k][n] 512B rows (SW by k&7 per 128B block),
//    fragments via LDSM_X4_T. Inline per-ks fragment loads (R8 style).
// 3-stage cp.async, one __syncthreads per k64 iteration. 1 CTA/SM.
// ---------------------------------------------------------------------------
#define GSTAGE 49152
#define GSMEM_BYTES (3*GSTAGE)    // 147456

template<bool GELU, bool RES, bool OUTH>
__global__ void __launch_bounds__(256, 1)
mma_gemm(const __half* __restrict__ A, const __half* __restrict__ W,
         const float* __restrict__ bias, const float* __restrict__ res,
         void* __restrict__ Cv, int M, int N, int K) {
    extern __shared__ char smc[];
    const uint32_t sm_u = (uint32_t)__cvta_generic_to_shared(smc);

    const int tid  = threadIdx.x;
    const int lane = tid & 31;
    const int warp = tid >> 5;
    const int wm = warp >> 2;     // 0..1 -> m offset *64
    const int wn = warp & 3;      // 0..3 -> n offset *64
    const int g  = lane >> 2;
    const int tg = lane & 3;

    const int bm = blockIdx.y, bn = blockIdx.x;
    const __half* Ab = A + (size_t)bm * 128 * K;
    const __half* Bb = W + (size_t)bn * 256;      // column offset in [K][N]

    const int j    = lane & 7;
    const int tile = lane >> 3;
    const uint32_t jm = (uint32_t)(j * 16);
    const uint32_t aRowSel = (uint32_t)((tile & 1) * 8);
    const uint32_t aC16    = (uint32_t)((tile >> 1) * 16);
    const uint32_t nbOff   = (uint32_t)((tile >> 1) * 16);   // bytes

    uint32_t aRow[4];
    #pragma unroll
    for (int mi = 0; mi < 4; mi++)
        aRow[mi] = ((uint32_t)(wm * 64 + mi * 16 + j) + aRowSel) * 128;
    const uint32_t bBase = 16384u + (uint32_t)wn * 128u +
                           (uint32_t)(tile & 1) * 4096u + (uint32_t)j * 512u;

    float acc[4][8][4];
    #pragma unroll
    for (int i = 0; i < 4; i++)
        #pragma unroll
        for (int jj = 0; jj < 8; jj++)
            #pragma unroll
            for (int c = 0; c < 4; c++) acc[i][jj][c] = 0.f;

    auto issue = [&](int stage, int kt) {
        uint32_t sA = sm_u + (uint32_t)stage * GSTAGE;
        uint32_t sB = sA + 16384u;
        {
            int c = tid & 7;
            int kc = kt * 64 + c * 8;
            #pragma unroll
            for (int p = 0; p < 4; p++) {
                int r = (tid >> 3) + p * 32;
                uint32_t dst = (uint32_t)(r * 128) +
                               (((uint32_t)(c * 16)) ^ ((uint32_t)(r & 7) * 16));
                cp16(sA + dst, Ab + (size_t)r * K + kc);
            }
        }
        #pragma unroll
        for (int p = 0; p < 8; p++) {
            int idx = tid + p * 256;
            int r = idx >> 5;                // k row 0..63
            int c = idx & 31;                // 16B chunk 0..31
            uint32_t dst = (uint32_t)(r * 512) + (uint32_t)((c >> 3) * 128) +
                           (((uint32_t)((c & 7) * 16)) ^ ((uint32_t)(r & 7) * 16));
            cp16(sB + dst, Bb + (size_t)(kt * 64 + r) * N + c * 8);
        }
        asm volatile("cp.async.commit_group;\n");
    };

    const int KT = K >> 6;
    issue(0, 0);
    issue(1, 1);

    int rbuf = 0, ibuf = 2;
    for (int kt = 0; kt < KT; kt++) {
        if (kt + 1 < KT) {
            asm volatile("cp.async.wait_group 1;\n");
        } else {
            asm volatile("cp.async.wait_group 0;\n");
        }
        __syncthreads();
        if (kt + 2 < KT) {
            issue(ibuf, kt + 2);
            if (++ibuf == 3) ibuf = 0;
        }

        const uint32_t stBase = sm_u + (uint32_t)rbuf * GSTAGE;
        if (++rbuf == 3) rbuf = 0;

        #pragma unroll
        for (int ks = 0; ks < 4; ks++) {
            const uint32_t koffA = ((uint32_t)(ks * 32) + aC16) ^ jm;

            uint32_t af[4][4];
            #pragma unroll
            for (int mi = 0; mi < 4; mi++)
                LDSM_X4(af[mi][0], af[mi][1], af[mi][2], af[mi][3],
                        stBase + aRow[mi] + koffA);

            uint32_t bf[8][2];
            const uint32_t bk = stBase + bBase + (uint32_t)ks * 8192u;
            #pragma unroll
            for (int li = 0; li < 4; li++) {
                uint32_t addr = bk + (((uint32_t)(li * 32) + nbOff) ^ jm);
                LDSM_X4_T(bf[li*2][0], bf[li*2][1], bf[li*2+1][0], bf[li*2+1][1], addr);
            }

            #pragma unroll
            for (int mi = 0; mi < 4; mi++)
                #pragma unroll
                for (int ni = 0; ni < 8; ni++)
                    MMA_F16(acc[mi][ni][0], acc[mi][ni][1], acc[mi][ni][2], acc[mi][ni][3],
                            af[mi][0], af[mi][1], af[mi][2], af[mi][3],
                            bf[ni][0], bf[ni][1]);
        }
    }

    const int rowBase = bm * 128 + wm * 64;
    const int colBase = bn * 256 + wn * 64;
    float* Cf = (float*)Cv;
    __half* Ch = (__half*)Cv;
    #pragma unroll
    for (int mi = 0; mi < 4; mi++) {
        #pragma unroll
        for (int ni = 0; ni < 8; ni++) {
            int col = colBase + ni * 8 + 2 * tg;
            float bb0 = bias[col], bb1 = bias[col + 1];
            int r0 = rowBase + mi * 16 + g;
            int r1 = r0 + 8;
            float v0 = acc[mi][ni][0] + bb0;
            float v1 = acc[mi][ni][1] + bb1;
            float v2 = acc[mi][ni][2] + bb0;
            float v3 = acc[mi][ni][3] + bb1;
            if (GELU) { v0 = gelu_f(v0); v1 = gelu_f(v1); v2 = gelu_f(v2); v3 = gelu_f(v3); }
            if (RES) {
                const float2 rr0 = *reinterpret_cast<const float2*>(res + (size_t)r0 * N + col);
                const float2 rr1 = *reinterpret_cast<const float2*>(res + (size_t)r1 * N + col);
                v0 += rr0.x; v1 += rr0.y; v2 += rr1.x; v3 += rr1.y;
            }
            if (OUTH) {
                *reinterpret_cast<__half2*>(Ch + (size_t)r0 * N + col) = __floats2half2_rn(v0, v1);
                *reinterpret_cast<__half2*>(Ch + (size_t)r1 * N + col) = __floats2half2_rn(v2, v3);
            } else {
                *reinterpret_cast<float2*>(Cf + (size_t)r0 * N + col) = make_float2(v0, v1);
                *reinterpret_cast<float2*>(Cf + (size_t)r1 * N + col) = make_float2(v2, v3);
            }
        }
    }
}

// ---------------------------------------------------------------------------
// fp16 tensor-core flash attention (unchanged — verified).
// ---------------------------------------------------------------------------
#define AOFF_V 16384u
#define AOFF_Q 32768u
#define AOFF_P 40960u
#define ATT_SMEM 49152

__global__ void __launch_bounds__(128, 2)
attn_mma_kernel(const __half* __restrict__ qkv, __half* __restrict__ out) {
    extern __shared__ char smc[];
    const uint32_t sm_u = (uint32_t)__cvta_generic_to_shared(smc);

    const int qt  = gridDim.x - 1 - blockIdx.x;
    const int qt0 = qt * 64;
    const int h   = blockIdx.y;
    const int b   = blockIdx.z;
    const int tid = threadIdx.x;
    const int lane = tid & 31;
    const int warp = tid >> 5;
    const int g  = lane >> 2;
    const int tg = lane & 3;
    const int r0 = warp * 16 + g;

    const int j    = lane & 7;
    const int tile = lane >> 3;
    const uint32_t jm = (uint32_t)(j * 16);
    const uint32_t aRowSel = (uint32_t)((tile & 1) * 8);
    const uint32_t aC16    = (uint32_t)((tile >> 1) * 16);
    const uint32_t bRowSel = (uint32_t)((tile >> 1) * 8);
    const uint32_t bC16    = (uint32_t)((tile & 1) * 16);

    const __half* base = qkv + (size_t)b * TT * (3 * EE);
    const int sch = (tid & 7) << 4;

    auto issueKV = [&](int buf, int kt) {
        int krow0 = kt * 64;
        uint32_t sK = sm_u + (uint32_t)buf * 8192u;
        uint32_t sV = sm_u + AOFF_V + (uint32_t)buf * 8192u;
        #pragma unroll
        for (int p = 0; p < 4; p++) {
            int r = (tid >> 3) + p * 16;
            uint32_t dst = (uint32_t)(r * 128) + ((uint32_t)sch ^ ((uint32_t)(r & 7) * 16));
            const __half* src = base + (size_t)(krow0 + r) * 3072 + EE + h * 64 + (sch >> 1);
            cp16(sK + dst, src);
            cp16(sV + dst, src + EE);
        }
        asm volatile("cp.async.commit_group;\n");
    };

    issueKV(0, 0);

    {
        const __half2 sc8 = __float2half2_rn(0.125f);
        #pragma unroll
        for (int p = 0; p < 4; p++) {
            int r = (tid >> 3) + p * 16;
            uint4 q = *reinterpret_cast<const uint4*>(
                base + (size_t)(qt0 + r) * 3072 + h * 64 + (sch >> 1));
            __half2* qh = reinterpret_cast<__half2*>(&q);
            qh[0] = __hmul2(qh[0], sc8);
            qh[1] = __hmul2(qh[1], sc8);
            qh[2] = __hmul2(qh[2], sc8);
            qh[3] = __hmul2(qh[3], sc8);
            uint32_t dst = AOFF_Q + (uint32_t)(r * 128) +
                           ((uint32_t)sch ^ ((uint32_t)(r & 7) * 16));
            *reinterpret_cast<uint4*>(smc + dst) = q;
        }
    }
    __syncthreads();

    uint32_t qa[4][4];
    #pragma unroll
    for (int ks = 0; ks < 4; ks++) {
        uint32_t addr = sm_u + AOFF_Q +
            ((uint32_t)(warp * 16 + j) + aRowSel) * 128 +
            (((uint32_t)(ks * 32) + aC16) ^ jm);
        LDSM_X4(qa[ks][0], qa[ks][1], qa[ks][2], qa[ks][3], addr);
    }

    float m0 = -1e30f, m1 = -1e30f, l0 = 0.f, l1 = 0.f;
    float ob[8][4];
    #pragma unroll
    for (int nt = 0; nt < 8; nt++)
        #pragma unroll
        for (int c = 0; c < 4; c++) ob[nt][c] = 0.f;

    const int nkt = qt + 1;
    for (int kt = 0; kt < nkt; kt++) {
        if (kt + 1 < nkt) {
            issueKV((kt + 1) & 1, kt + 1);
            asm volatile("cp.async.wait_group 1;\n");
        } else {
            asm volatile("cp.async.wait_group 0;\n");
        }
        __syncthreads();

        const uint32_t sK = sm_u + (uint32_t)(kt & 1) * 8192u;
        const uint32_t sV = sm_u + AOFF_V + (uint32_t)(kt & 1) * 8192u;

        float sc[8][4];
        #pragma unroll
        for (int nt = 0; nt < 8; nt++)
            #pragma unroll
            for (int c = 0; c < 4; c++) sc[nt][c] = 0.f;

        #pragma unroll
        for (int ks = 0; ks < 4; ks++) {
            const uint32_t koffB = ((uint32_t)(ks * 32) + bC16) ^ jm;
            uint32_t bfr[8][2];
            #pragma unroll
            for (int bi = 0; bi < 4; bi++) {
                uint32_t addr = sK + ((uint32_t)(bi * 16 + j) + bRowSel) * 128 + koffB;
                LDSM_X4(bfr[bi*2][0], bfr[bi*2][1], bfr[bi*2+1][0], bfr[bi*2+1][1], addr);
            }
            #pragma unroll
            for (int nt = 0; nt < 8; nt++)
                MMA_F16(sc[nt][0], sc[nt][1], sc[nt][2], sc[nt][3],
                        qa[ks][0], qa[ks][1], qa[ks][2], qa[ks][3],
                        bfr[nt][0], bfr[nt][1]);
        }

        if (kt == nkt - 1) {
            int qrow0 = qt0 + r0;
            int qrow1 = qrow0 + 8;
            #pragma unroll
            for (int nt = 0; nt < 8; nt++) {
                int kc0 = kt * 64 + nt * 8 + 2 * tg;
                if (kc0     > qrow0) sc[nt][0] = -1e30f;
                if (kc0 + 1 > qrow0) sc[nt][1] = -1e30f;
                if (kc0     > qrow1) sc[nt][2] = -1e30f;
                if (kc0 + 1 > qrow1) sc[nt][3] = -1e30f;
            }
        }

        float rm0 = -1e30f, rm1 = -1e30f;
        #pragma unroll
        for (int nt = 0; nt < 8; nt++) {
            rm0 = fmaxf(rm0, fmaxf(sc[nt][0], sc[nt][1]));
            rm1 = fmaxf(rm1, fmaxf(sc[nt][2], sc[nt][3]));
        }
        rm0 = fmaxf(rm0, __shfl_xor_sync(0xffffffff, rm0, 1));
        rm0 = fmaxf(rm0, __shfl_xor_sync(0xffffffff, rm0, 2));
        rm1 = fmaxf(rm1, __shfl_xor_sync(0xffffffff, rm1, 1));
        rm1 = fmaxf(rm1, __shfl_xor_sync(0xffffffff, rm1, 2));
        float mn0 = fmaxf(m0, rm0);
        float mn1 = fmaxf(m1, rm1);

        float rs0 = 0.f, rs1 = 0.f;
        #pragma unroll
        for (int nt = 0; nt < 8; nt++) {
            sc[nt][0] = __expf(sc[nt][0] - mn0);
            sc[nt][1] = __expf(sc[nt][1] - mn0);
            sc[nt][2] = __expf(sc[nt][2] - mn1);
            sc[nt][3] = __expf(sc[nt][3] - mn1);
            rs0 += sc[nt][0] + sc[nt][1];
            rs1 += sc[nt][2] + sc[nt][3];
        }
        rs0 += __shfl_xor_sync(0xffffffff, rs0, 1);
        rs0 += __shfl_xor_sync(0xffffffff, rs0, 2);
        rs1 += __shfl_xor_sync(0xffffffff, rs1, 1);
        rs1 += __shfl_xor_sync(0xffffffff, rs1, 2);

        float scale0 = __expf(m0 - mn0);
        float scale1 = __expf(m1 - mn1);
        l0 = l0 * scale0 + rs0;
        l1 = l1 * scale1 + rs1;
        m0 = mn0; m1 = mn1;
        #pragma unroll
        for (int nt = 0; nt < 8; nt++) {
            ob[nt][0] *= scale0; ob[nt][1] *= scale0;
            ob[nt][2] *= scale1; ob[nt][3] *= scale1;
        }

        __syncwarp();
        #pragma unroll
        for (int nt = 0; nt < 8; nt++) {
            uint32_t off0 = AOFF_P + (uint32_t)(r0 * 128) +
                (((uint32_t)(nt * 16 + 4 * tg)) ^ ((uint32_t)(r0 & 7) * 16));
            uint32_t off1 = AOFF_P + (uint32_t)((r0 + 8) * 128) +
                (((uint32_t)(nt * 16 + 4 * tg)) ^ ((uint32_t)((r0 + 8) & 7) * 16));
            *reinterpret_cast<__half2*>(smc + off0) = __floats2half2_rn(sc[nt][0], sc[nt][1]);
            *reinterpret_cast<__half2*>(smc + off1) = __floats2half2_rn(sc[nt][2], sc[nt][3]);
        }
        __syncwarp();

        #pragma unroll
        for (int ks = 0; ks < 4; ks++) {
            uint32_t pa[4];
            {
                uint32_t addr = sm_u + AOFF_P +
                    ((uint32_t)(warp * 16 + j) + aRowSel) * 128 +
                    (((uint32_t)(ks * 32) + aC16) ^ jm);
                LDSM_X4(pa[0], pa[1], pa[2], pa[3], addr);
            }
            uint32_t vf[8][2];
            #pragma unroll
            for (int li = 0; li < 4; li++) {
                uint32_t addr = sV +
                    (uint32_t)((ks * 16 + (tile & 1) * 8 + j) * 128) +
                    (((uint32_t)(li * 32 + (tile >> 1) * 16)) ^ jm);
                LDSM_X4_T(vf[li*2][0], vf[li*2][1], vf[li*2+1][0], vf[li*2+1][1], addr);
            }
            #pragma unroll
            for (int nt = 0; nt < 8; nt++)
                MMA_F16(ob[nt][0], ob[nt][1], ob[nt][2], ob[nt][3],
                        pa[0], pa[1], pa[2], pa[3], vf[nt][0], vf[nt][1]);
        }
        __syncthreads();
    }

    float inv0 = 1.0f / l0;
    float inv1 = 1.0f / l1;
    size_t row0 = ((size_t)b * TT + qt0 + r0) * EE + h * 64;
    size_t row1 = row0 + 8 * EE;
    #pragma unroll
    for (int nt = 0; nt < 8; nt++) {
        int col = nt * 8 + 2 * tg;
        *reinterpret_cast<__half2*>(out + row0 + col) =
            __floats2half2_rn(ob[nt][0] * inv0, ob[nt][1] * inv0);
        *reinterpret_cast<__half2*>(out + row1 + col) =
            __floats2half2_rn(ob[nt][2] * inv1, ob[nt][3] * inv1);
    }
}

// ---------------------------------------------------------------------------
// Launch
// ---------------------------------------------------------------------------
extern "C" void kernel_launch(void* const* d_in, const int* in_sizes, int n_in,
                              void* d_out, int out_size) {
    const float* x        = (const float*)d_in[0];
    const float* c_attn_w = (const float*)d_in[1];
    const float* c_attn_b = (const float*)d_in[2];
    const float* c_proj_w = (const float*)d_in[3];
    const float* c_proj_b = (const float*)d_in[4];
    const float* mlp_w1   = (const float*)d_in[5];
    const float* mlp_b1   = (const float*)d_in[6];
    const float* mlp_w2   = (const float*)d_in[7];
    const float* mlp_b2   = (const float*)d_in[8];
    const float* ln1_g    = (const float*)d_in[9];
    const float* ln1_b    = (const float*)d_in[10];
    const float* ln2_g    = (const float*)d_in[11];
    const float* ln2_b    = (const float*)d_in[12];
    float* out = (float*)d_out;

    float *lnf, *qkvf, *attf, *x2, *actf, *wf;
    cudaGetSymbolAddress((void**)&lnf,  g_ln);
    cudaGetSymbolAddress((void**)&qkvf, g_qkv);
    cudaGetSymbolAddress((void**)&attf, g_att);
    cudaGetSymbolAddress((void**)&x2,   g_x2);
    cudaGetSymbolAddress((void**)&actf, g_act);
    cudaGetSymbolAddress((void**)&wf,   g_w);
    __half* ln  = (__half*)lnf;
    __half* qkv = (__half*)qkvf;
    __half* att = (__half*)attf;
    __half* act = (__half*)actf;
    __half* w   = (__half*)wf;

    cudaFuncSetAttribute(mma_gemm<false, false, true>,
                         cudaFuncAttributeMaxDynamicSharedMemorySize, GSMEM_BYTES);
    cudaFuncSetAttribute(mma_gemm<false, true, false>,
                         cudaFuncAttributeMaxDynamicSharedMemorySize, GSMEM_BYTES);
    cudaFuncSetAttribute(mma_gemm<true, false, true>,
                         cudaFuncAttributeMaxDynamicSharedMemorySize, GSMEM_BYTES);
    cudaFuncSetAttribute(attn_mma_kernel,
                         cudaFuncAttributeMaxDynamicSharedMemorySize, ATT_SMEM);

    // 0. Convert all weights fp32 -> fp16 in one launch (same [K][N] layout)
    convert_all_kernel<<<4096, 256>>>((const float4*)c_attn_w, (const float4*)c_proj_w,
                                      (const float4*)mlp_w1, (const float4*)mlp_w2,
                                      (uint2*)w);

    // 1. LN1 (fp16 out)
    ln_kernel<<<MM/8, 256>>>(x, ln1_g, ln1_b, ln);
    // 2. QKV = ln @ c_attn_w + b           [4096, 3072] fp16 out
    mma_gemm<false, false, true><<<dim3(3*EE/256, MM/128), 256, GSMEM_BYTES>>>(
        ln, w + WH_ATTN, c_attn_b, nullptr, qkv, MM, 3*EE, EE);
    // 3. Attention (full fp16)
    attn_mma_kernel<<<dim3(TT/64, HH, BB), 128, ATT_SMEM>>>(qkv, att);
    // 4. x2 = x + att @ c_proj_w + b       [4096, 1024] fp32 out
    mma_gemm<false, true, false><<<dim3(EE/256, MM/128), 256, GSMEM_BYTES>>>(
        att, w + WH_PROJ, c_proj_b, x, x2, MM, EE, EE);
    // 5. LN2 (fp16 out)
    ln_kernel<<<MM/8, 256>>>(x2, ln2_g, ln2_b, ln);
    // 6. act = gelu(h @ mlp_w1 + b1)       [4096, 4096] fp16 out
    mma_gemm<true, false, true><<<dim3(FF/256, MM/128), 256, GSMEM_BYTES>>>(
        ln, w + WH_MLP1, mlp_b1, nullptr, act, MM, FF, EE);
    // 7. out = x2 + act @ mlp_w2 + b2      [4096, 1024] fp32 out
    mma_gemm<false, true, false><<<dim3(EE/256, MM/128), 256, GSMEM_BYTES>>>(
        act, w + WH_MLP2, mlp_b2, x2, out, MM, EE, FF);
}

// round 11
// speedup vs baseline: 8.0659x; 1.0049x over previous
#include <cuda_runtime.h>
#include <cuda_fp16.h>
#include <math.h>
#include <stdint.h>

// Problem constants
#define BB 2
#define TT 2048
#define EE 1024
#define HH 16
#define DH 64
#define FF 4096
#define MM (BB*TT)   // 4096 rows

// Scratch (device globals: no allocation allowed)
__device__ float g_ln [MM*EE];         // as __half
__device__ float g_qkv[MM*3*EE];       // as __half
__device__ float g_att[MM*EE];         // as __half
__device__ float g_x2 [MM*EE];         // fp32
__device__ float g_act[(size_t)MM*FF]; // as __half
__device__ float g_w  [6*1024*1024];   // fp16 weights, NATURAL [K][N] layout

// offsets in halves
#define WH_ATTN 0
#define WH_PROJ (3*EE*EE)
#define WH_MLP1 (WH_PROJ + EE*EE)
#define WH_MLP2 (WH_MLP1 + EE*FF)

// ---------------------------------------------------------------------------
// Helpers
// ---------------------------------------------------------------------------
__device__ __forceinline__ void cp16(uint32_t dst, const void* src) {
    asm volatile("cp.async.cg.shared.global [%0], [%1], 16;\n" :: "r"(dst), "l"(src));
}

#define MMA_F16(d0,d1,d2,d3,a0,a1,a2,a3,b0,b1) \
    asm volatile( \
        "mma.sync.aligned.m16n8k16.row.col.f32.f16.f16.f32 " \
        "{%0,%1,%2,%3}, {%4,%5,%6,%7}, {%8,%9}, {%0,%1,%2,%3};" \
        : "+f"(d0), "+f"(d1), "+f"(d2), "+f"(d3) \
        : "r"(a0), "r"(a1), "r"(a2), "r"(a3), "r"(b0), "r"(b1))

#define LDSM_X4(r0,r1,r2,r3,addr) \
    asm volatile("ldmatrix.sync.aligned.m8n8.x4.shared.b16 {%0,%1,%2,%3}, [%4];" \
        : "=r"(r0), "=r"(r1), "=r"(r2), "=r"(r3) : "r"(addr))

#define LDSM_X4_T(r0,r1,r2,r3,addr) \
    asm volatile("ldmatrix.sync.aligned.m8n8.x4.trans.shared.b16 {%0,%1,%2,%3}, [%4];" \
        : "=r"(r0), "=r"(r1), "=r"(r2), "=r"(r3) : "r"(addr))

// ---------------------------------------------------------------------------
// Fused fp32->fp16 convert for all four weights (dsts contiguous in g_w)
// ---------------------------------------------------------------------------
#define CV_S0 786432    // 3*EE*EE/4
#define CV_S1 1048576   // + EE*EE/4
#define CV_S2 2097152   // + EE*FF/4
#define CV_N  3145728   // + FF*EE/4
__global__ void convert_all_kernel(const float4* __restrict__ wa,
                                   const float4* __restrict__ wp,
                                   const float4* __restrict__ w1,
                                   const float4* __restrict__ w2,
                                   uint2* __restrict__ out) {
    int i = blockIdx.x * blockDim.x + threadIdx.x;
    int stride = gridDim.x * blockDim.x;
    for (; i < CV_N; i += stride) {
        float4 v;
        if (i < CV_S0)      v = wa[i];
        else if (i < CV_S1) v = wp[i - CV_S0];
        else if (i < CV_S2) v = w1[i - CV_S1];
        else                v = w2[i - CV_S2];
        __half2 a = __floats2half2_rn(v.x, v.y);
        __half2 b = __floats2half2_rn(v.z, v.w);
        uint2 o;
        o.x = *reinterpret_cast<uint32_t*>(&a);
        o.y = *reinterpret_cast<uint32_t*>(&b);
        out[i] = o;
    }
}

// ---------------------------------------------------------------------------
// LayerNorm: warp per row (no smem, no block barriers). 8 warps/block.
// ---------------------------------------------------------------------------
__global__ void ln_kernel(const float* __restrict__ x,
                          const float* __restrict__ g,
                          const float* __restrict__ b,
                          __half* __restrict__ out) {
    int row  = blockIdx.x * 8 + (threadIdx.x >> 5);
    int lane = threadIdx.x & 31;
    const float4* xr = reinterpret_cast<const float4*>(x + (size_t)row * EE);
    float4 v[8];
    float s = 0.f, sq = 0.f;
    #pragma unroll
    for (int i = 0; i < 8; i++) {
        v[i] = xr[i * 32 + lane];
        s  += v[i].x + v[i].y + v[i].z + v[i].w;
        sq += v[i].x*v[i].x + v[i].y*v[i].y + v[i].z*v[i].z + v[i].w*v[i].w;
    }
    #pragma unroll
    for (int o = 16; o > 0; o >>= 1) {
        s  += __shfl_xor_sync(0xffffffff, s,  o);
        sq += __shfl_xor_sync(0xffffffff, sq, o);
    }
    float mu   = s * (1.0f / EE);
    float rstd = rsqrtf(sq * (1.0f / EE) - mu * mu + 1e-5f);
    uint2* op = reinterpret_cast<uint2*>(out + (size_t)row * EE);
    const float4* gr = reinterpret_cast<const float4*>(g);
    const float4* br = reinterpret_cast<const float4*>(b);
    #pragma unroll
    for (int i = 0; i < 8; i++) {
        float4 gv = gr[i * 32 + lane];
        float4 bv = br[i * 32 + lane];
        __half2 h0 = __floats2half2_rn((v[i].x - mu) * rstd * gv.x + bv.x,
                                       (v[i].y - mu) * rstd * gv.y + bv.y);
        __half2 h1 = __floats2half2_rn((v[i].z - mu) * rstd * gv.z + bv.z,
                                       (v[i].w - mu) * rstd * gv.w + bv.w);
        uint2 o;
        o.x = *reinterpret_cast<uint32_t*>(&h0);
        o.y = *reinterpret_cast<uint32_t*>(&h1);
        op[i * 32 + lane] = o;
    }
}

__device__ __forceinline__ float gelu_f(float x) {
    const float c = 0.7978845608028654f;
    float x3 = x * x * x;
    return 0.5f * x * (1.0f + tanhf(c * (x + 0.044715f * x3)));
}

// ---------------------------------------------------------------------------
// fp16 GEMM, CTA 128x256x64, 8 warps (2x4), warp tile 64x64, fp32 accum.
// (unchanged from R10 — at HMMA path rate)
// ---------------------------------------------------------------------------
#define GSTAGE 49152
#define GSMEM_BYTES (3*GSTAGE)    // 147456

template<bool GELU, bool RES, bool OUTH>
__global__ void __launch_bounds__(256, 1)
mma_gemm(const __half* __restrict__ A, const __half* __restrict__ W,
         const float* __restrict__ bias, const float* __restrict__ res,
         void* __restrict__ Cv, int M, int N, int K) {
    extern __shared__ char smc[];
    const uint32_t sm_u = (uint32_t)__cvta_generic_to_shared(smc);

    const int tid  = threadIdx.x;
    const int lane = tid & 31;
    const int warp = tid >> 5;
    const int wm = warp >> 2;
    const int wn = warp & 3;
    const int g  = lane >> 2;
    const int tg = lane & 3;

    const int bm = blockIdx.y, bn = blockIdx.x;
    const __half* Ab = A + (size_t)bm * 128 * K;
    const __half* Bb = W + (size_t)bn * 256;

    const int j    = lane & 7;
    const int tile = lane >> 3;
    const uint32_t jm = (uint32_t)(j * 16);
    const uint32_t aRowSel = (uint32_t)((tile & 1) * 8);
    const uint32_t aC16    = (uint32_t)((tile >> 1) * 16);
    const uint32_t nbOff   = (uint32_t)((tile >> 1) * 16);

    uint32_t aRow[4];
    #pragma unroll
    for (int mi = 0; mi < 4; mi++)
        aRow[mi] = ((uint32_t)(wm * 64 + mi * 16 + j) + aRowSel) * 128;
    const uint32_t bBase = 16384u + (uint32_t)wn * 128u +
                           (uint32_t)(tile & 1) * 4096u + (uint32_t)j * 512u;

    float acc[4][8][4];
    #pragma unroll
    for (int i = 0; i < 4; i++)
        #pragma unroll
        for (int jj = 0; jj < 8; jj++)
            #pragma unroll
            for (int c = 0; c < 4; c++) acc[i][jj][c] = 0.f;

    auto issue = [&](int stage, int kt) {
        uint32_t sA = sm_u + (uint32_t)stage * GSTAGE;
        uint32_t sB = sA + 16384u;
        {
            int c = tid & 7;
            int kc = kt * 64 + c * 8;
            #pragma unroll
            for (int p = 0; p < 4; p++) {
                int r = (tid >> 3) + p * 32;
                uint32_t dst = (uint32_t)(r * 128) +
                               (((uint32_t)(c * 16)) ^ ((uint32_t)(r & 7) * 16));
                cp16(sA + dst, Ab + (size_t)r * K + kc);
            }
        }
        #pragma unroll
        for (int p = 0; p < 8; p++) {
            int idx = tid + p * 256;
            int r = idx >> 5;
            int c = idx & 31;
            uint32_t dst = (uint32_t)(r * 512) + (uint32_t)((c >> 3) * 128) +
                           (((uint32_t)((c & 7) * 16)) ^ ((uint32_t)(r & 7) * 16));
            cp16(sB + dst, Bb + (size_t)(kt * 64 + r) * N + c * 8);
        }
        asm volatile("cp.async.commit_group;\n");
    };

    const int KT = K >> 6;
    issue(0, 0);
    issue(1, 1);

    int rbuf = 0, ibuf = 2;
    for (int kt = 0; kt < KT; kt++) {
        if (kt + 1 < KT) {
            asm volatile("cp.async.wait_group 1;\n");
        } else {
            asm volatile("cp.async.wait_group 0;\n");
        }
        __syncthreads();
        if (kt + 2 < KT) {
            issue(ibuf, kt + 2);
            if (++ibuf == 3) ibuf = 0;
        }

        const uint32_t stBase = sm_u + (uint32_t)rbuf * GSTAGE;
        if (++rbuf == 3) rbuf = 0;

        #pragma unroll
        for (int ks = 0; ks < 4; ks++) {
            const uint32_t koffA = ((uint32_t)(ks * 32) + aC16) ^ jm;

            uint32_t af[4][4];
            #pragma unroll
            for (int mi = 0; mi < 4; mi++)
                LDSM_X4(af[mi][0], af[mi][1], af[mi][2], af[mi][3],
                        stBase + aRow[mi] + koffA);

            uint32_t bf[8][2];
            const uint32_t bk = stBase + bBase + (uint32_t)ks * 8192u;
            #pragma unroll
            for (int li = 0; li < 4; li++) {
                uint32_t addr = bk + (((uint32_t)(li * 32) + nbOff) ^ jm);
                LDSM_X4_T(bf[li*2][0], bf[li*2][1], bf[li*2+1][0], bf[li*2+1][1], addr);
            }

            #pragma unroll
            for (int mi = 0; mi < 4; mi++)
                #pragma unroll
                for (int ni = 0; ni < 8; ni++)
                    MMA_F16(acc[mi][ni][0], acc[mi][ni][1], acc[mi][ni][2], acc[mi][ni][3],
                            af[mi][0], af[mi][1], af[mi][2], af[mi][3],
                            bf[ni][0], bf[ni][1]);
        }
    }

    const int rowBase = bm * 128 + wm * 64;
    const int colBase = bn * 256 + wn * 64;
    float* Cf = (float*)Cv;
    __half* Ch = (__half*)Cv;
    #pragma unroll
    for (int mi = 0; mi < 4; mi++) {
        #pragma unroll
        for (int ni = 0; ni < 8; ni++) {
            int col = colBase + ni * 8 + 2 * tg;
            float bb0 = bias[col], bb1 = bias[col + 1];
            int r0 = rowBase + mi * 16 + g;
            int r1 = r0 + 8;
            float v0 = acc[mi][ni][0] + bb0;
            float v1 = acc[mi][ni][1] + bb1;
            float v2 = acc[mi][ni][2] + bb0;
            float v3 = acc[mi][ni][3] + bb1;
            if (GELU) { v0 = gelu_f(v0); v1 = gelu_f(v1); v2 = gelu_f(v2); v3 = gelu_f(v3); }
            if (RES) {
                const float2 rr0 = *reinterpret_cast<const float2*>(res + (size_t)r0 * N + col);
                const float2 rr1 = *reinterpret_cast<const float2*>(res + (size_t)r1 * N + col);
                v0 += rr0.x; v1 += rr0.y; v2 += rr1.x; v3 += rr1.y;
            }
            if (OUTH) {
                *reinterpret_cast<__half2*>(Ch + (size_t)r0 * N + col) = __floats2half2_rn(v0, v1);
                *reinterpret_cast<__half2*>(Ch + (size_t)r1 * N + col) = __floats2half2_rn(v2, v3);
            } else {
                *reinterpret_cast<float2*>(Cf + (size_t)r0 * N + col) = make_float2(v0, v1);
                *reinterpret_cast<float2*>(Cf + (size_t)r1 * N + col) = make_float2(v2, v3);
            }
        }
    }
}

// ---------------------------------------------------------------------------
// fp16 tensor-core flash attention. Changes vs R10:
//   - __launch_bounds__(128, 3): 3 CTAs/SM (regs capped 170, smem 144KB)
//   - exp2-domain softmax: Q pre-scaled by 0.125*log2(e); exp2f instead of
//     __expf (drops the ex2-prep multiply on every score element)
// ---------------------------------------------------------------------------
#define AOFF_V 16384u
#define AOFF_Q 32768u
#define AOFF_P 40960u
#define ATT_SMEM 49152

__global__ void __launch_bounds__(128, 3)
attn_mma_kernel(const __half* __restrict__ qkv, __half* __restrict__ out) {
    extern __shared__ char smc[];
    const uint32_t sm_u = (uint32_t)__cvta_generic_to_shared(smc);

    const int qt  = gridDim.x - 1 - blockIdx.x;
    const int qt0 = qt * 64;
    const int h   = blockIdx.y;
    const int b   = blockIdx.z;
    const int tid = threadIdx.x;
    const int lane = tid & 31;
    const int warp = tid >> 5;
    const int g  = lane >> 2;
    const int tg = lane & 3;
    const int r0 = warp * 16 + g;

    const int j    = lane & 7;
    const int tile = lane >> 3;
    const uint32_t jm = (uint32_t)(j * 16);
    const uint32_t aRowSel = (uint32_t)((tile & 1) * 8);
    const uint32_t aC16    = (uint32_t)((tile >> 1) * 16);
    const uint32_t bRowSel = (uint32_t)((tile >> 1) * 8);
    const uint32_t bC16    = (uint32_t)((tile & 1) * 16);

    const __half* base = qkv + (size_t)b * TT * (3 * EE);
    const int sch = (tid & 7) << 4;

    auto issueKV = [&](int buf, int kt) {
        int krow0 = kt * 64;
        uint32_t sK = sm_u + (uint32_t)buf * 8192u;
        uint32_t sV = sm_u + AOFF_V + (uint32_t)buf * 8192u;
        #pragma unroll
        for (int p = 0; p < 4; p++) {
            int r = (tid >> 3) + p * 16;
            uint32_t dst = (uint32_t)(r * 128) + ((uint32_t)sch ^ ((uint32_t)(r & 7) * 16));
            const __half* src = base + (size_t)(krow0 + r) * 3072 + EE + h * 64 + (sch >> 1);
            cp16(sK + dst, src);
            cp16(sV + dst, src + EE);
        }
        asm volatile("cp.async.commit_group;\n");
    };

    issueKV(0, 0);

    {
        // Q pre-scale: 1/8 * log2(e) -> softmax computed in base-2 domain
        const __half2 sc8 = __float2half2_rn(0.18033688f);
        #pragma unroll
        for (int p = 0; p < 4; p++) {
            int r = (tid >> 3) + p * 16;
            uint4 q = *reinterpret_cast<const uint4*>(
                base + (size_t)(qt0 + r) * 3072 + h * 64 + (sch >> 1));
            __half2* qh = reinterpret_cast<__half2*>(&q);
            qh[0] = __hmul2(qh[0], sc8);
            qh[1] = __hmul2(qh[1], sc8);
            qh[2] = __hmul2(qh[2], sc8);
            qh[3] = __hmul2(qh[3], sc8);
            uint32_t dst = AOFF_Q + (uint32_t)(r * 128) +
                           ((uint32_t)sch ^ ((uint32_t)(r & 7) * 16));
            *reinterpret_cast<uint4*>(smc + dst) = q;
        }
    }
    __syncthreads();

    uint32_t qa[4][4];
    #pragma unroll
    for (int ks = 0; ks < 4; ks++) {
        uint32_t addr = sm_u + AOFF_Q +
            ((uint32_t)(warp * 16 + j) + aRowSel) * 128 +
            (((uint32_t)(ks * 32) + aC16) ^ jm);
        LDSM_X4(qa[ks][0], qa[ks][1], qa[ks][2], qa[ks][3], addr);
    }

    float m0 = -1e30f, m1 = -1e30f, l0 = 0.f, l1 = 0.f;
    float ob[8][4];
    #pragma unroll
    for (int nt = 0; nt < 8; nt++)
        #pragma unroll
        for (int c = 0; c < 4; c++) ob[nt][c] = 0.f;

    const int nkt = qt + 1;
    for (int kt = 0; kt < nkt; kt++) {
        if (kt + 1 < nkt) {
            issueKV((kt + 1) & 1, kt + 1);
            asm volatile("cp.async.wait_group 1;\n");
        } else {
            asm volatile("cp.async.wait_group 0;\n");
        }
        __syncthreads();

        const uint32_t sK = sm_u + (uint32_t)(kt & 1) * 8192u;
        const uint32_t sV = sm_u + AOFF_V + (uint32_t)(kt & 1) * 8192u;

        float sc[8][4];
        #pragma unroll
        for (int nt = 0; nt < 8; nt++)
            #pragma unroll
            for (int c = 0; c < 4; c++) sc[nt][c] = 0.f;

        #pragma unroll
        for (int ks = 0; ks < 4; ks++) {
            const uint32_t koffB = ((uint32_t)(ks * 32) + bC16) ^ jm;
            uint32_t bfr[8][2];
            #pragma unroll
            for (int bi = 0; bi < 4; bi++) {
                uint32_t addr = sK + ((uint32_t)(bi * 16 + j) + bRowSel) * 128 + koffB;
                LDSM_X4(bfr[bi*2][0], bfr[bi*2][1], bfr[bi*2+1][0], bfr[bi*2+1][1], addr);
            }
            #pragma unroll
            for (int nt = 0; nt < 8; nt++)
                MMA_F16(sc[nt][0], sc[nt][1], sc[nt][2], sc[nt][3],
                        qa[ks][0], qa[ks][1], qa[ks][2], qa[ks][3],
                        bfr[nt][0], bfr[nt][1]);
        }

        if (kt == nkt - 1) {
            int qrow0 = qt0 + r0;
            int qrow1 = qrow0 + 8;
            #pragma unroll
            for (int nt = 0; nt < 8; nt++) {
                int kc0 = kt * 64 + nt * 8 + 2 * tg;
                if (kc0     > qrow0) sc[nt][0] = -1e30f;
                if (kc0 + 1 > qrow0) sc[nt][1] = -1e30f;
                if (kc0     > qrow1) sc[nt][2] = -1e30f;
                if (kc0 + 1 > qrow1) sc[nt][3] = -1e30f;
            }
        }

        float rm0 = -1e30f, rm1 = -1e30f;
        #pragma unroll
        for (int nt = 0; nt < 8; nt++) {
            rm0 = fmaxf(rm0, fmaxf(sc[nt][0], sc[nt][1]));
            rm1 = fmaxf(rm1, fmaxf(sc[nt][2], sc[nt][3]));
        }
        rm0 = fmaxf(rm0, __shfl_xor_sync(0xffffffff, rm0, 1));
        rm0 = fmaxf(rm0, __shfl_xor_sync(0xffffffff, rm0, 2));
        rm1 = fmaxf(rm1, __shfl_xor_sync(0xffffffff, rm1, 1));
        rm1 = fmaxf(rm1, __shfl_xor_sync(0xffffffff, rm1, 2));
        float mn0 = fmaxf(m0, rm0);
        float mn1 = fmaxf(m1, rm1);

        float rs0 = 0.f, rs1 = 0.f;
        #pragma unroll
        for (int nt = 0; nt < 8; nt++) {
            sc[nt][0] = exp2f(sc[nt][0] - mn0);
            sc[nt][1] = exp2f(sc[nt][1] - mn0);
            sc[nt][2] = exp2f(sc[nt][2] - mn1);
            sc[nt][3] = exp2f(sc[nt][3] - mn1);
            rs0 += sc[nt][0] + sc[nt][1];
            rs1 += sc[nt][2] + sc[nt][3];
        }
        rs0 += __shfl_xor_sync(0xffffffff, rs0, 1);
        rs0 += __shfl_xor_sync(0xffffffff, rs0, 2);
        rs1 += __shfl_xor_sync(0xffffffff, rs1, 1);
        rs1 += __shfl_xor_sync(0xffffffff, rs1, 2);

        float scale0 = exp2f(m0 - mn0);
        float scale1 = exp2f(m1 - mn1);
        l0 = l0 * scale0 + rs0;
        l1 = l1 * scale1 + rs1;
        m0 = mn0; m1 = mn1;
        #pragma unroll
        for (int nt = 0; nt < 8; nt++) {
            ob[nt][0] *= scale0; ob[nt][1] *= scale0;
            ob[nt][2] *= scale1; ob[nt][3] *= scale1;
        }

        __syncwarp();
        #pragma unroll
        for (int nt = 0; nt < 8; nt++) {
            uint32_t off0 = AOFF_P + (uint32_t)(r0 * 128) +
                (((uint32_t)(nt * 16 + 4 * tg)) ^ ((uint32_t)(r0 & 7) * 16));
            uint32_t off1 = AOFF_P + (uint32_t)((r0 + 8) * 128) +
                (((uint32_t)(nt * 16 + 4 * tg)) ^ ((uint32_t)((r0 + 8) & 7) * 16));
            *reinterpret_cast<__half2*>(smc + off0) = __floats2half2_rn(sc[nt][0], sc[nt][1]);
            *reinterpret_cast<__half2*>(smc + off1) = __floats2half2_rn(sc[nt][2], sc[nt][3]);
        }
        __syncwarp();

        #pragma unroll
        for (int ks = 0; ks < 4; ks++) {
            uint32_t pa[4];
            {
                uint32_t addr = sm_u + AOFF_P +
                    ((uint32_t)(warp * 16 + j) + aRowSel) * 128 +
                    (((uint32_t)(ks * 32) + aC16) ^ jm);
                LDSM_X4(pa[0], pa[1], pa[2], pa[3], addr);
            }
            uint32_t vf[8][2];
            #pragma unroll
            for (int li = 0; li < 4; li++) {
                uint32_t addr = sV +
                    (uint32_t)((ks * 16 + (tile & 1) * 8 + j) * 128) +
                    (((uint32_t)(li * 32 + (tile >> 1) * 16)) ^ jm);
                LDSM_X4_T(vf[li*2][0], vf[li*2][1], vf[li*2+1][0], vf[li*2+1][1], addr);
            }
            #pragma unroll
            for (int nt = 0; nt < 8; nt++)
                MMA_F16(ob[nt][0], ob[nt][1], ob[nt][2], ob[nt][3],
                        pa[0], pa[1], pa[2], pa[3], vf[nt][0], vf[nt][1]);
        }
        __syncthreads();
    }

    float inv0 = 1.0f / l0;
    float inv1 = 1.0f / l1;
    size_t row0 = ((size_t)b * TT + qt0 + r0) * EE + h * 64;
    size_t row1 = row0 + 8 * EE;
    #pragma unroll
    for (int nt = 0; nt < 8; nt++) {
        int col = nt * 8 + 2 * tg;
        *reinterpret_cast<__half2*>(out + row0 + col) =
            __floats2half2_rn(ob[nt][0] * inv0, ob[nt][1] * inv0);
        *reinterpret_cast<__half2*>(out + row1 + col) =
            __floats2half2_rn(ob[nt][2] * inv1, ob[nt][3] * inv1);
    }
}

// ---------------------------------------------------------------------------
// Launch
// ---------------------------------------------------------------------------
extern "C" void kernel_launch(void* const* d_in, const int* in_sizes, int n_in,
                              void* d_out, int out_size) {
    const float* x        = (const float*)d_in[0];
    const float* c_attn_w = (const float*)d_in[1];
    const float* c_attn_b = (const float*)d_in[2];
    const float* c_proj_w = (const float*)d_in[3];
    const float* c_proj_b = (const float*)d_in[4];
    const float* mlp_w1   = (const float*)d_in[5];
    const float* mlp_b1   = (const float*)d_in[6];
    const float* mlp_w2   = (const float*)d_in[7];
    const float* mlp_b2   = (const float*)d_in[8];
    const float* ln1_g    = (const float*)d_in[9];
    const float* ln1_b    = (const float*)d_in[10];
    const float* ln2_g    = (const float*)d_in[11];
    const float* ln2_b    = (const float*)d_in[12];
    float* out = (float*)d_out;

    float *lnf, *qkvf, *attf, *x2, *actf, *wf;
    cudaGetSymbolAddress((void**)&lnf,  g_ln);
    cudaGetSymbolAddress((void**)&qkvf, g_qkv);
    cudaGetSymbolAddress((void**)&attf, g_att);
    cudaGetSymbolAddress((void**)&x2,   g_x2);
    cudaGetSymbolAddress((void**)&actf, g_act);
    cudaGetSymbolAddress((void**)&wf,   g_w);
    __half* ln  = (__half*)lnf;
    __half* qkv = (__half*)qkvf;
    __half* att = (__half*)attf;
    __half* act = (__half*)actf;
    __half* w   = (__half*)wf;

    cudaFuncSetAttribute(mma_gemm<false, false, true>,
                         cudaFuncAttributeMaxDynamicSharedMemorySize, GSMEM_BYTES);
    cudaFuncSetAttribute(mma_gemm<false, true, false>,
                         cudaFuncAttributeMaxDynamicSharedMemorySize, GSMEM_BYTES);
    cudaFuncSetAttribute(mma_gemm<true, false, true>,
                         cudaFuncAttributeMaxDynamicSharedMemorySize, GSMEM_BYTES);
    cudaFuncSetAttribute(attn_mma_kernel,
                         cudaFuncAttributeMaxDynamicSharedMemorySize, ATT_SMEM);

    // 0. Convert all weights fp32 -> fp16 in one launch (same [K][N] layout)
    convert_all_kernel<<<4096, 256>>>((const float4*)c_attn_w, (const float4*)c_proj_w,
                                      (const float4*)mlp_w1, (const float4*)mlp_w2,
                                      (uint2*)w);

    // 1. LN1 (fp16 out)
    ln_kernel<<<MM/8, 256>>>(x, ln1_g, ln1_b, ln);
    // 2. QKV = ln @ c_attn_w + b           [4096, 3072] fp16 out
    mma_gemm<false, false, true><<<dim3(3*EE/256, MM/128), 256, GSMEM_BYTES>>>(
        ln, w + WH_ATTN, c_attn_b, nullptr, qkv, MM, 3*EE, EE);
    // 3. Attention (full fp16, exp2 softmax, 3 CTAs/SM)
    attn_mma_kernel<<<dim3(TT/64, HH, BB), 128, ATT_SMEM>>>(qkv, att);
    // 4. x2 = x + att @ c_proj_w + b       [4096, 1024] fp32 out
    mma_gemm<false, true, false><<<dim3(EE/256, MM/128), 256, GSMEM_BYTES>>>(
        att, w + WH_PROJ, c_proj_b, x, x2, MM, EE, EE);
    // 5. LN2 (fp16 out)
    ln_kernel<<<MM/8, 256>>>(x2, ln2_g, ln2_b, ln);
    // 6. act = gelu(h @ mlp_w1 + b1)       [4096, 4096] fp16 out
    mma_gemm<true, false, true><<<dim3(FF/256, MM/128), 256, GSMEM_BYTES>>>(
        ln, w + WH_MLP1, mlp_b1, nullptr, act, MM, FF, EE);
    // 7. out = x2 + act @ mlp_w2 + b2      [4096, 1024] fp32 out
    mma_gemm<false, true, false><<<dim3(EE/256, MM/128), 256, GSMEM_BYTES>>>(
        act, w + WH_MLP2, mlp_b2, x2, out, MM, EE, FF);
}

// round 12
// speedup vs baseline: 8.2319x; 1.0206x over previous
#include <cuda_runtime.h>
#include <cuda_fp16.h>
#include <math.h>
#include <stdint.h>

// Problem constants
#define BB 2
#define TT 2048
#define EE 1024
#define HH 16
#define DH 64
#define FF 4096
#define MM (BB*TT)   // 4096 rows

// Scratch (device globals: no allocation allowed)
__device__ float g_ln [MM*EE];         // as __half
__device__ float g_qkv[MM*3*EE];       // as __half
__device__ float g_att[MM*EE];         // as __half
__device__ float g_x2 [MM*EE];         // fp32
__device__ float g_act[(size_t)MM*FF]; // as __half
__device__ float g_w  [6*1024*1024];   // fp16 weights, NATURAL [K][N] layout

// offsets in halves
#define WH_ATTN 0
#define WH_PROJ (3*EE*EE)
#define WH_MLP1 (WH_PROJ + EE*EE)
#define WH_MLP2 (WH_MLP1 + EE*FF)

// ---------------------------------------------------------------------------
// Helpers
// ---------------------------------------------------------------------------
__device__ __forceinline__ void cp16(uint32_t dst, const void* src) {
    asm volatile("cp.async.cg.shared.global [%0], [%1], 16;\n" :: "r"(dst), "l"(src));
}

__device__ __forceinline__ uint32_t packh2(float a, float b) {
    __half2 h = __floats2half2_rn(a, b);
    return *reinterpret_cast<uint32_t*>(&h);
}

#define MMA_F16(d0,d1,d2,d3,a0,a1,a2,a3,b0,b1) \
    asm volatile( \
        "mma.sync.aligned.m16n8k16.row.col.f32.f16.f16.f32 " \
        "{%0,%1,%2,%3}, {%4,%5,%6,%7}, {%8,%9}, {%0,%1,%2,%3};" \
        : "+f"(d0), "+f"(d1), "+f"(d2), "+f"(d3) \
        : "r"(a0), "r"(a1), "r"(a2), "r"(a3), "r"(b0), "r"(b1))

#define LDSM_X4(r0,r1,r2,r3,addr) \
    asm volatile("ldmatrix.sync.aligned.m8n8.x4.shared.b16 {%0,%1,%2,%3}, [%4];" \
        : "=r"(r0), "=r"(r1), "=r"(r2), "=r"(r3) : "r"(addr))

#define LDSM_X4_T(r0,r1,r2,r3,addr) \
    asm volatile("ldmatrix.sync.aligned.m8n8.x4.trans.shared.b16 {%0,%1,%2,%3}, [%4];" \
        : "=r"(r0), "=r"(r1), "=r"(r2), "=r"(r3) : "r"(addr))

// ---------------------------------------------------------------------------
// Fused fp32->fp16 convert for all four weights (dsts contiguous in g_w)
// ---------------------------------------------------------------------------
#define CV_S0 786432
#define CV_S1 1048576
#define CV_S2 2097152
#define CV_N  3145728
__global__ void convert_all_kernel(const float4* __restrict__ wa,
                                   const float4* __restrict__ wp,
                                   const float4* __restrict__ w1,
                                   const float4* __restrict__ w2,
                                   uint2* __restrict__ out) {
    int i = blockIdx.x * blockDim.x + threadIdx.x;
    int stride = gridDim.x * blockDim.x;
    for (; i < CV_N; i += stride) {
        float4 v;
        if (i < CV_S0)      v = wa[i];
        else if (i < CV_S1) v = wp[i - CV_S0];
        else if (i < CV_S2) v = w1[i - CV_S1];
        else                v = w2[i - CV_S2];
        uint2 o;
        o.x = packh2(v.x, v.y);
        o.y = packh2(v.z, v.w);
        out[i] = o;
    }
}

// ---------------------------------------------------------------------------
// LayerNorm: warp per row. 8 warps/block.
// ---------------------------------------------------------------------------
__global__ void ln_kernel(const float* __restrict__ x,
                          const float* __restrict__ g,
                          const float* __restrict__ b,
                          __half* __restrict__ out) {
    int row  = blockIdx.x * 8 + (threadIdx.x >> 5);
    int lane = threadIdx.x & 31;
    const float4* xr = reinterpret_cast<const float4*>(x + (size_t)row * EE);
    float4 v[8];
    float s = 0.f, sq = 0.f;
    #pragma unroll
    for (int i = 0; i < 8; i++) {
        v[i] = xr[i * 32 + lane];
        s  += v[i].x + v[i].y + v[i].z + v[i].w;
        sq += v[i].x*v[i].x + v[i].y*v[i].y + v[i].z*v[i].z + v[i].w*v[i].w;
    }
    #pragma unroll
    for (int o = 16; o > 0; o >>= 1) {
        s  += __shfl_xor_sync(0xffffffff, s,  o);
        sq += __shfl_xor_sync(0xffffffff, sq, o);
    }
    float mu   = s * (1.0f / EE);
    float rstd = rsqrtf(sq * (1.0f / EE) - mu * mu + 1e-5f);
    uint2* op = reinterpret_cast<uint2*>(out + (size_t)row * EE);
    const float4* gr = reinterpret_cast<const float4*>(g);
    const float4* br = reinterpret_cast<const float4*>(b);
    #pragma unroll
    for (int i = 0; i < 8; i++) {
        float4 gv = gr[i * 32 + lane];
        float4 bv = br[i * 32 + lane];
        uint2 o;
        o.x = packh2((v[i].x - mu) * rstd * gv.x + bv.x,
                     (v[i].y - mu) * rstd * gv.y + bv.y);
        o.y = packh2((v[i].z - mu) * rstd * gv.z + bv.z,
                     (v[i].w - mu) * rstd * gv.w + bv.w);
        op[i * 32 + lane] = o;
    }
}

__device__ __forceinline__ float gelu_f(float x) {
    const float c = 0.7978845608028654f;
    float x3 = x * x * x;
    return 0.5f * x * (1.0f + tanhf(c * (x + 0.044715f * x3)));
}

// ---------------------------------------------------------------------------
// fp16 GEMM, CTA 128x256x64 (unchanged — at HMMA path rate)
// ---------------------------------------------------------------------------
#define GSTAGE 49152
#define GSMEM_BYTES (3*GSTAGE)

template<bool GELU, bool RES, bool OUTH>
__global__ void __launch_bounds__(256, 1)
mma_gemm(const __half* __restrict__ A, const __half* __restrict__ W,
         const float* __restrict__ bias, const float* __restrict__ res,
         void* __restrict__ Cv, int M, int N, int K) {
    extern __shared__ char smc[];
    const uint32_t sm_u = (uint32_t)__cvta_generic_to_shared(smc);

    const int tid  = threadIdx.x;
    const int lane = tid & 31;
    const int warp = tid >> 5;
    const int wm = warp >> 2;
    const int wn = warp & 3;
    const int g  = lane >> 2;
    const int tg = lane & 3;

    const int bm = blockIdx.y, bn = blockIdx.x;
    const __half* Ab = A + (size_t)bm * 128 * K;
    const __half* Bb = W + (size_t)bn * 256;

    const int j    = lane & 7;
    const int tile = lane >> 3;
    const uint32_t jm = (uint32_t)(j * 16);
    const uint32_t aRowSel = (uint32_t)((tile & 1) * 8);
    const uint32_t aC16    = (uint32_t)((tile >> 1) * 16);
    const uint32_t nbOff   = (uint32_t)((tile >> 1) * 16);

    uint32_t aRow[4];
    #pragma unroll
    for (int mi = 0; mi < 4; mi++)
        aRow[mi] = ((uint32_t)(wm * 64 + mi * 16 + j) + aRowSel) * 128;
    const uint32_t bBase = 16384u + (uint32_t)wn * 128u +
                           (uint32_t)(tile & 1) * 4096u + (uint32_t)j * 512u;

    float acc[4][8][4];
    #pragma unroll
    for (int i = 0; i < 4; i++)
        #pragma unroll
        for (int jj = 0; jj < 8; jj++)
            #pragma unroll
            for (int c = 0; c < 4; c++) acc[i][jj][c] = 0.f;

    auto issue = [&](int stage, int kt) {
        uint32_t sA = sm_u + (uint32_t)stage * GSTAGE;
        uint32_t sB = sA + 16384u;
        {
            int c = tid & 7;
            int kc = kt * 64 + c * 8;
            #pragma unroll
            for (int p = 0; p < 4; p++) {
                int r = (tid >> 3) + p * 32;
                uint32_t dst = (uint32_t)(r * 128) +
                               (((uint32_t)(c * 16)) ^ ((uint32_t)(r & 7) * 16));
                cp16(sA + dst, Ab + (size_t)r * K + kc);
            }
        }
        #pragma unroll
        for (int p = 0; p < 8; p++) {
            int idx = tid + p * 256;
            int r = idx >> 5;
            int c = idx & 31;
            uint32_t dst = (uint32_t)(r * 512) + (uint32_t)((c >> 3) * 128) +
                           (((uint32_t)((c & 7) * 16)) ^ ((uint32_t)(r & 7) * 16));
            cp16(sB + dst, Bb + (size_t)(kt * 64 + r) * N + c * 8);
        }
        asm volatile("cp.async.commit_group;\n");
    };

    const int KT = K >> 6;
    issue(0, 0);
    issue(1, 1);

    int rbuf = 0, ibuf = 2;
    for (int kt = 0; kt < KT; kt++) {
        if (kt + 1 < KT) {
            asm volatile("cp.async.wait_group 1;\n");
        } else {
            asm volatile("cp.async.wait_group 0;\n");
        }
        __syncthreads();
        if (kt + 2 < KT) {
            issue(ibuf, kt + 2);
            if (++ibuf == 3) ibuf = 0;
        }

        const uint32_t stBase = sm_u + (uint32_t)rbuf * GSTAGE;
        if (++rbuf == 3) rbuf = 0;

        #pragma unroll
        for (int ks = 0; ks < 4; ks++) {
            const uint32_t koffA = ((uint32_t)(ks * 32) + aC16) ^ jm;

            uint32_t af[4][4];
            #pragma unroll
            for (int mi = 0; mi < 4; mi++)
                LDSM_X4(af[mi][0], af[mi][1], af[mi][2], af[mi][3],
                        stBase + aRow[mi] + koffA);

            uint32_t bf[8][2];
            const uint32_t bk = stBase + bBase + (uint32_t)ks * 8192u;
            #pragma unroll
            for (int li = 0; li < 4; li++) {
                uint32_t addr = bk + (((uint32_t)(li * 32) + nbOff) ^ jm);
                LDSM_X4_T(bf[li*2][0], bf[li*2][1], bf[li*2+1][0], bf[li*2+1][1], addr);
            }

            #pragma unroll
            for (int mi = 0; mi < 4; mi++)
                #pragma unroll
                for (int ni = 0; ni < 8; ni++)
                    MMA_F16(acc[mi][ni][0], acc[mi][ni][1], acc[mi][ni][2], acc[mi][ni][3],
                            af[mi][0], af[mi][1], af[mi][2], af[mi][3],
                            bf[ni][0], bf[ni][1]);
        }
    }

    const int rowBase = bm * 128 + wm * 64;
    const int colBase = bn * 256 + wn * 64;
    float* Cf = (float*)Cv;
    __half* Ch = (__half*)Cv;
    #pragma unroll
    for (int mi = 0; mi < 4; mi++) {
        #pragma unroll
        for (int ni = 0; ni < 8; ni++) {
            int col = colBase + ni * 8 + 2 * tg;
            float bb0 = bias[col], bb1 = bias[col + 1];
            int r0 = rowBase + mi * 16 + g;
            int r1 = r0 + 8;
            float v0 = acc[mi][ni][0] + bb0;
            float v1 = acc[mi][ni][1] + bb1;
            float v2 = acc[mi][ni][2] + bb0;
            float v3 = acc[mi][ni][3] + bb1;
            if (GELU) { v0 = gelu_f(v0); v1 = gelu_f(v1); v2 = gelu_f(v2); v3 = gelu_f(v3); }
            if (RES) {
                const float2 rr0 = *reinterpret_cast<const float2*>(res + (size_t)r0 * N + col);
                const float2 rr1 = *reinterpret_cast<const float2*>(res + (size_t)r1 * N + col);
                v0 += rr0.x; v1 += rr0.y; v2 += rr1.x; v3 += rr1.y;
            }
            if (OUTH) {
                *reinterpret_cast<__half2*>(Ch + (size_t)r0 * N + col) = __floats2half2_rn(v0, v1);
                *reinterpret_cast<__half2*>(Ch + (size_t)r1 * N + col) = __floats2half2_rn(v2, v3);
            } else {
                *reinterpret_cast<float2*>(Cf + (size_t)r0 * N + col) = make_float2(v0, v1);
                *reinterpret_cast<float2*>(Cf + (size_t)r1 * N + col) = make_float2(v2, v3);
            }
        }
    }
}

// ---------------------------------------------------------------------------
// fp16 flash attention. Changes vs R11:
//   - P kept register-resident: S-accumulator fragments are repacked
//     directly into A-operand fragments for P@V (no smem P buffer, no
//     extra LDSM, no __syncwarp pair).
//   - 3-stage KV ring, ONE __syncthreads per k-tile (GEMM-style proof:
//     barrier at iter kt is after compute(kt-1) in all warps' program
//     order, so issuing into stage (kt+2)%3 == (kt-1)%3 is safe).
// Smem: K 3x8K @0, V 3x8K @24576, Q 8K @49152 -> 57344 B; 3 CTAs/SM.
// ---------------------------------------------------------------------------
#define AOFF_V 24576u
#define AOFF_Q 49152u
#define ATT_SMEM 57344

__global__ void __launch_bounds__(128, 3)
attn_mma_kernel(const __half* __restrict__ qkv, __half* __restrict__ out) {
    extern __shared__ char smc[];
    const uint32_t sm_u = (uint32_t)__cvta_generic_to_shared(smc);

    const int qt  = gridDim.x - 1 - blockIdx.x;
    const int qt0 = qt * 64;
    const int h   = blockIdx.y;
    const int b   = blockIdx.z;
    const int tid = threadIdx.x;
    const int lane = tid & 31;
    const int warp = tid >> 5;
    const int g  = lane >> 2;
    const int tg = lane & 3;
    const int r0 = warp * 16 + g;

    const int j    = lane & 7;
    const int tile = lane >> 3;
    const uint32_t jm = (uint32_t)(j * 16);
    const uint32_t aRowSel = (uint32_t)((tile & 1) * 8);
    const uint32_t aC16    = (uint32_t)((tile >> 1) * 16);
    const uint32_t bRowSel = (uint32_t)((tile >> 1) * 8);
    const uint32_t bC16    = (uint32_t)((tile & 1) * 16);

    const __half* base = qkv + (size_t)b * TT * (3 * EE);
    const int sch = (tid & 7) << 4;

    auto issueKV = [&](int stage, int kt) {
        int krow0 = kt * 64;
        uint32_t sK = sm_u + (uint32_t)stage * 8192u;
        uint32_t sV = sm_u + AOFF_V + (uint32_t)stage * 8192u;
        #pragma unroll
        for (int p = 0; p < 4; p++) {
            int r = (tid >> 3) + p * 16;
            uint32_t dst = (uint32_t)(r * 128) + ((uint32_t)sch ^ ((uint32_t)(r & 7) * 16));
            const __half* src = base + (size_t)(krow0 + r) * 3072 + EE + h * 64 + (sch >> 1);
            cp16(sK + dst, src);
            cp16(sV + dst, src + EE);
        }
        asm volatile("cp.async.commit_group;\n");
    };

    const int nkt = qt + 1;
    issueKV(0, 0);
    if (nkt > 1) issueKV(1, 1);

    {
        // Q pre-scale: 1/8 * log2(e) -> softmax in base-2 domain
        const __half2 sc8 = __float2half2_rn(0.18033688f);
        #pragma unroll
        for (int p = 0; p < 4; p++) {
            int r = (tid >> 3) + p * 16;
            uint4 q = *reinterpret_cast<const uint4*>(
                base + (size_t)(qt0 + r) * 3072 + h * 64 + (sch >> 1));
            __half2* qh = reinterpret_cast<__half2*>(&q);
            qh[0] = __hmul2(qh[0], sc8);
            qh[1] = __hmul2(qh[1], sc8);
            qh[2] = __hmul2(qh[2], sc8);
            qh[3] = __hmul2(qh[3], sc8);
            uint32_t dst = AOFF_Q + (uint32_t)(r * 128) +
                           ((uint32_t)sch ^ ((uint32_t)(r & 7) * 16));
            *reinterpret_cast<uint4*>(smc + dst) = q;
        }
    }
    __syncthreads();

    uint32_t qa[4][4];
    #pragma unroll
    for (int ks = 0; ks < 4; ks++) {
        uint32_t addr = sm_u + AOFF_Q +
            ((uint32_t)(warp * 16 + j) + aRowSel) * 128 +
            (((uint32_t)(ks * 32) + aC16) ^ jm);
        LDSM_X4(qa[ks][0], qa[ks][1], qa[ks][2], qa[ks][3], addr);
    }

    float m0 = -1e30f, m1 = -1e30f, l0 = 0.f, l1 = 0.f;
    float ob[8][4];
    #pragma unroll
    for (int nt = 0; nt < 8; nt++)
        #pragma unroll
        for (int c = 0; c < 4; c++) ob[nt][c] = 0.f;

    int rstage = 0, istage = 2;
    for (int kt = 0; kt < nkt; kt++) {
        if (kt + 1 < nkt) {
            asm volatile("cp.async.wait_group 1;\n");
        } else {
            asm volatile("cp.async.wait_group 0;\n");
        }
        __syncthreads();
        if (kt + 2 < nkt) {
            issueKV(istage, kt + 2);
            if (++istage == 3) istage = 0;
        }

        const uint32_t sK = sm_u + (uint32_t)rstage * 8192u;
        const uint32_t sV = sm_u + AOFF_V + (uint32_t)rstage * 8192u;
        if (++rstage == 3) rstage = 0;

        // S = Q @ K^T
        float sc[8][4];
        #pragma unroll
        for (int nt = 0; nt < 8; nt++)
            #pragma unroll
            for (int c = 0; c < 4; c++) sc[nt][c] = 0.f;

        #pragma unroll
        for (int ks = 0; ks < 4; ks++) {
            const uint32_t koffB = ((uint32_t)(ks * 32) + bC16) ^ jm;
            uint32_t bfr[8][2];
            #pragma unroll
            for (int bi = 0; bi < 4; bi++) {
                uint32_t addr = sK + ((uint32_t)(bi * 16 + j) + bRowSel) * 128 + koffB;
                LDSM_X4(bfr[bi*2][0], bfr[bi*2][1], bfr[bi*2+1][0], bfr[bi*2+1][1], addr);
            }
            #pragma unroll
            for (int nt = 0; nt < 8; nt++)
                MMA_F16(sc[nt][0], sc[nt][1], sc[nt][2], sc[nt][3],
                        qa[ks][0], qa[ks][1], qa[ks][2], qa[ks][3],
                        bfr[nt][0], bfr[nt][1]);
        }

        // Causal mask (diagonal tile)
        if (kt == nkt - 1) {
            int qrow0 = qt0 + r0;
            int qrow1 = qrow0 + 8;
            #pragma unroll
            for (int nt = 0; nt < 8; nt++) {
                int kc0 = kt * 64 + nt * 8 + 2 * tg;
                if (kc0     > qrow0) sc[nt][0] = -1e30f;
                if (kc0 + 1 > qrow0) sc[nt][1] = -1e30f;
                if (kc0     > qrow1) sc[nt][2] = -1e30f;
                if (kc0 + 1 > qrow1) sc[nt][3] = -1e30f;
            }
        }

        // Online softmax (base-2)
        float rm0 = -1e30f, rm1 = -1e30f;
        #pragma unroll
        for (int nt = 0; nt < 8; nt++) {
            rm0 = fmaxf(rm0, fmaxf(sc[nt][0], sc[nt][1]));
            rm1 = fmaxf(rm1, fmaxf(sc[nt][2], sc[nt][3]));
        }
        rm0 = fmaxf(rm0, __shfl_xor_sync(0xffffffff, rm0, 1));
        rm0 = fmaxf(rm0, __shfl_xor_sync(0xffffffff, rm0, 2));
        rm1 = fmaxf(rm1, __shfl_xor_sync(0xffffffff, rm1, 1));
        rm1 = fmaxf(rm1, __shfl_xor_sync(0xffffffff, rm1, 2));
        float mn0 = fmaxf(m0, rm0);
        float mn1 = fmaxf(m1, rm1);

        float rs0 = 0.f, rs1 = 0.f;
        #pragma unroll
        for (int nt = 0; nt < 8; nt++) {
            sc[nt][0] = exp2f(sc[nt][0] - mn0);
            sc[nt][1] = exp2f(sc[nt][1] - mn0);
            sc[nt][2] = exp2f(sc[nt][2] - mn1);
            sc[nt][3] = exp2f(sc[nt][3] - mn1);
            rs0 += sc[nt][0] + sc[nt][1];
            rs1 += sc[nt][2] + sc[nt][3];
        }
        rs0 += __shfl_xor_sync(0xffffffff, rs0, 1);
        rs0 += __shfl_xor_sync(0xffffffff, rs0, 2);
        rs1 += __shfl_xor_sync(0xffffffff, rs1, 1);
        rs1 += __shfl_xor_sync(0xffffffff, rs1, 2);

        float scale0 = exp2f(m0 - mn0);
        float scale1 = exp2f(m1 - mn1);
        l0 = l0 * scale0 + rs0;
        l1 = l1 * scale1 + rs1;
        m0 = mn0; m1 = mn1;
        #pragma unroll
        for (int nt = 0; nt < 8; nt++) {
            ob[nt][0] *= scale0; ob[nt][1] *= scale0;
            ob[nt][2] *= scale1; ob[nt][3] *= scale1;
        }

        // O += P @ V — P fragments packed directly from sc registers.
        // A-frag for keys [16ks,16ks+16): a0=(g, 16ks+2tg pair)=sc[2ks][0..1],
        // a1=(g+8,..)=sc[2ks][2..3], a2=(g, +8 cols)=sc[2ks+1][0..1],
        // a3=(g+8, +8 cols)=sc[2ks+1][2..3].
        #pragma unroll
        for (int ks = 0; ks < 4; ks++) {
            uint32_t pa0 = packh2(sc[2*ks][0],   sc[2*ks][1]);
            uint32_t pa1 = packh2(sc[2*ks][2],   sc[2*ks][3]);
            uint32_t pa2 = packh2(sc[2*ks+1][0], sc[2*ks+1][1]);
            uint32_t pa3 = packh2(sc[2*ks+1][2], sc[2*ks+1][3]);
            uint32_t vf[8][2];
            #pragma unroll
            for (int li = 0; li < 4; li++) {
                uint32_t addr = sV +
                    (uint32_t)((ks * 16 + (tile & 1) * 8 + j) * 128) +
                    (((uint32_t)(li * 32 + (tile >> 1) * 16)) ^ jm);
                LDSM_X4_T(vf[li*2][0], vf[li*2][1], vf[li*2+1][0], vf[li*2+1][1], addr);
            }
            #pragma unroll
            for (int nt = 0; nt < 8; nt++)
                MMA_F16(ob[nt][0], ob[nt][1], ob[nt][2], ob[nt][3],
                        pa0, pa1, pa2, pa3, vf[nt][0], vf[nt][1]);
        }
    }

    float inv0 = 1.0f / l0;
    float inv1 = 1.0f / l1;
    size_t row0 = ((size_t)b * TT + qt0 + r0) * EE + h * 64;
    size_t row1 = row0 + 8 * EE;
    #pragma unroll
    for (int nt = 0; nt < 8; nt++) {
        int col = nt * 8 + 2 * tg;
        *reinterpret_cast<__half2*>(out + row0 + col) =
            __floats2half2_rn(ob[nt][0] * inv0, ob[nt][1] * inv0);
        *reinterpret_cast<__half2*>(out + row1 + col) =
            __floats2half2_rn(ob[nt][2] * inv1, ob[nt][3] * inv1);
    }
}

// ---------------------------------------------------------------------------
// Launch
// ---------------------------------------------------------------------------
extern "C" void kernel_launch(void* const* d_in, const int* in_sizes, int n_in,
                              void* d_out, int out_size) {
    const float* x        = (const float*)d_in[0];
    const float* c_attn_w = (const float*)d_in[1];
    const float* c_attn_b = (const float*)d_in[2];
    const float* c_proj_w = (const float*)d_in[3];
    const float* c_proj_b = (const float*)d_in[4];
    const float* mlp_w1   = (const float*)d_in[5];
    const float* mlp_b1   = (const float*)d_in[6];
    const float* mlp_w2   = (const float*)d_in[7];
    const float* mlp_b2   = (const float*)d_in[8];
    const float* ln1_g    = (const float*)d_in[9];
    const float* ln1_b    = (const float*)d_in[10];
    const float* ln2_g    = (const float*)d_in[11];
    const float* ln2_b    = (const float*)d_in[12];
    float* out = (float*)d_out;

    float *lnf, *qkvf, *attf, *x2, *actf, *wf;
    cudaGetSymbolAddress((void**)&lnf,  g_ln);
    cudaGetSymbolAddress((void**)&qkvf, g_qkv);
    cudaGetSymbolAddress((void**)&attf, g_att);
    cudaGetSymbolAddress((void**)&x2,   g_x2);
    cudaGetSymbolAddress((void**)&actf, g_act);
    cudaGetSymbolAddress((void**)&wf,   g_w);
    __half* ln  = (__half*)lnf;
    __half* qkv = (__half*)qkvf;
    __half* att = (__half*)attf;
    __half* act = (__half*)actf;
    __half* w   = (__half*)wf;

    cudaFuncSetAttribute(mma_gemm<false, false, true>,
                         cudaFuncAttributeMaxDynamicSharedMemorySize, GSMEM_BYTES);
    cudaFuncSetAttribute(mma_gemm<false, true, false>,
                         cudaFuncAttributeMaxDynamicSharedMemorySize, GSMEM_BYTES);
    cudaFuncSetAttribute(mma_gemm<true, false, true>,
                         cudaFuncAttributeMaxDynamicSharedMemorySize, GSMEM_BYTES);
    cudaFuncSetAttribute(attn_mma_kernel,
                         cudaFuncAttributeMaxDynamicSharedMemorySize, ATT_SMEM);

    // 0. Convert all weights fp32 -> fp16 in one launch (natural layout)
    convert_all_kernel<<<4096, 256>>>((const float4*)c_attn_w, (const float4*)c_proj_w,
                                      (const float4*)mlp_w1, (const float4*)mlp_w2,
                                      (uint2*)w);

    // 1. LN1 (fp16 out)
    ln_kernel<<<MM/8, 256>>>(x, ln1_g, ln1_b, ln);
    // 2. QKV = ln @ c_attn_w + b           [4096, 3072] fp16 out
    mma_gemm<false, false, true><<<dim3(3*EE/256, MM/128), 256, GSMEM_BYTES>>>(
        ln, w + WH_ATTN, c_attn_b, nullptr, qkv, MM, 3*EE, EE);
    // 3. Attention (register-resident P, 3-stage KV)
    attn_mma_kernel<<<dim3(TT/64, HH, BB), 128, ATT_SMEM>>>(qkv, att);
    // 4. x2 = x + att @ c_proj_w + b       [4096, 1024] fp32 out
    mma_gemm<false, true, false><<<dim3(EE/256, MM/128), 256, GSMEM_BYTES>>>(
        att, w + WH_PROJ, c_proj_b, x, x2, MM, EE, EE);
    // 5. LN2 (fp16 out)
    ln_kernel<<<MM/8, 256>>>(x2, ln2_g, ln2_b, ln);
    // 6. act = gelu(h @ mlp_w1 + b1)       [4096, 4096] fp16 out
    mma_gemm<true, false, true><<<dim3(FF/256, MM/128), 256, GSMEM_BYTES>>>(
        ln, w + WH_MLP1, mlp_b1, nullptr, act, MM, FF, EE);
    // 7. out = x2 + act @ mlp_w2 + b2      [4096, 1024] fp32 out
    mma_gemm<false, true, false><<<dim3(EE/256, MM/128), 256, GSMEM_BYTES>>>(
        act, w + WH_MLP2, mlp_b2, x2, out, MM, EE, FF);
}